// round 3
// baseline (speedup 1.0000x reference)
#include <cuda_runtime.h>
#include <cuda_bf16.h>
#include <math.h>

// Problem constants
#define BATCH 4
#define SEQ   2048
#define DM    1024
#define NH    16
#define DK    64
#define DFF   4096
#define MROWS (BATCH * SEQ)   // 8192
#define LN_EPS 1e-5f

// ---------------- scratch (device globals; no allocation allowed) ----------------
__device__ float g_q[MROWS * DM];
__device__ float g_k[MROWS * DM];
__device__ float g_v[MROWS * DM];
__device__ float g_ctx[MROWS * DM];
__device__ float g_attn[MROWS * DM];
__device__ float g_h[MROWS * DM];
__device__ float g_ff1[(size_t)MROWS * DFF];
__device__ float g_ff2[MROWS * DM];

// ---------------- SGEMM: C = A[M,K] @ W[K,N] + bias, optional ReLU -------------
// 128x128 block, BK=8, 8x8 per thread, 256 threads.
#define BM 128
#define BN 128
#define BK 8
#define TM 8
#define TN 8

__global__ __launch_bounds__(256) void sgemm_bias(
    const float* __restrict__ A, const float* __restrict__ W,
    const float* __restrict__ bias, float* __restrict__ C,
    int M, int N, int K, int relu)
{
    __shared__ float As[BK][BM];
    __shared__ float Bs[BK][BN];

    const int tid = threadIdx.x;
    const int bx = blockIdx.x, by = blockIdx.y;

    const float* Ablk = A + (size_t)by * BM * K;
    const float* Bblk = W + (size_t)bx * BN;

    const int aRow = tid >> 1;            // 0..127
    const int aCol = (tid & 1) * 4;       // 0 or 4
    const int bRow = tid >> 5;            // 0..7
    const int bCol = (tid & 31) * 4;      // 0..124

    const int tx = tid & 15;              // 0..15
    const int ty = tid >> 4;              // 0..15

    float acc[TM][TN];
#pragma unroll
    for (int i = 0; i < TM; i++)
#pragma unroll
        for (int j = 0; j < TN; j++) acc[i][j] = 0.f;

    for (int k0 = 0; k0 < K; k0 += BK) {
        float4 av = *(const float4*)(Ablk + (size_t)aRow * K + k0 + aCol);
        As[aCol + 0][aRow] = av.x;
        As[aCol + 1][aRow] = av.y;
        As[aCol + 2][aRow] = av.z;
        As[aCol + 3][aRow] = av.w;
        float4 bv = *(const float4*)(Bblk + (size_t)(k0 + bRow) * N + bCol);
        *(float4*)&Bs[bRow][bCol] = bv;
        __syncthreads();

#pragma unroll
        for (int kk = 0; kk < BK; kk++) {
            float a[TM], b[TN];
            float4 a0 = *(const float4*)&As[kk][ty * TM];
            float4 a1 = *(const float4*)&As[kk][ty * TM + 4];
            a[0]=a0.x; a[1]=a0.y; a[2]=a0.z; a[3]=a0.w;
            a[4]=a1.x; a[5]=a1.y; a[6]=a1.z; a[7]=a1.w;
            float4 b0 = *(const float4*)&Bs[kk][tx * TN];
            float4 b1 = *(const float4*)&Bs[kk][tx * TN + 4];
            b[0]=b0.x; b[1]=b0.y; b[2]=b0.z; b[3]=b0.w;
            b[4]=b1.x; b[5]=b1.y; b[6]=b1.z; b[7]=b1.w;
#pragma unroll
            for (int i = 0; i < TM; i++)
#pragma unroll
                for (int j = 0; j < TN; j++)
                    acc[i][j] += a[i] * b[j];
        }
        __syncthreads();
    }

    // epilogue: bias (+ relu), float4 stores
    float bvals[TN];
#pragma unroll
    for (int j = 0; j < TN; j++) bvals[j] = bias[bx * BN + tx * TN + j];

#pragma unroll
    for (int i = 0; i < TM; i++) {
        int row = by * BM + ty * TM + i;
        float* crow = C + (size_t)row * N + bx * BN + tx * TN;
#pragma unroll
        for (int j = 0; j < TN; j += 4) {
            float4 v;
            v.x = acc[i][j + 0] + bvals[j + 0];
            v.y = acc[i][j + 1] + bvals[j + 1];
            v.z = acc[i][j + 2] + bvals[j + 2];
            v.w = acc[i][j + 3] + bvals[j + 3];
            if (relu) {
                v.x = fmaxf(v.x, 0.f); v.y = fmaxf(v.y, 0.f);
                v.z = fmaxf(v.z, 0.f); v.w = fmaxf(v.w, 0.f);
            }
            *(float4*)(crow + j) = v;
        }
    }
}

// ---------------- Attention (flash-style, fp32) -----------------------------------
// grid: (SEQ/64, BATCH*NH), block: 256 threads (8 warps, 8 query rows per warp)
// Q,K,V layout: [B,S,H,DK] == [8192,1024] with head h at cols h*64..h*64+63.
// Output ctx written in the same layout == "merged" in the reference.
#define QPAD 64
#define KPAD 65
#define VPAD 66

__global__ __launch_bounds__(256) void attn_kernel(
    const float* __restrict__ Qg, const float* __restrict__ Kg,
    const float* __restrict__ Vg, const int* __restrict__ maskg,
    float* __restrict__ Og)
{
    extern __shared__ float sm[];
    float* Qs = sm;                      // [64][QPAD]
    float* Ks = Qs + 64 * QPAD;          // [64][KPAD]
    float* Vs = Ks + 64 * KPAD;          // [64][VPAD]
    float* Ps = Vs + 64 * VPAD;          // [64][64]

    const int bh = blockIdx.y;
    const int b = bh >> 4;
    const int h = bh & 15;
    const int qb = blockIdx.x;
    const int tid = threadIdx.x;
    const int warp = tid >> 5;
    const int lane = tid & 31;

    const float* Qbase = Qg + ((size_t)(b * SEQ + qb * 64)) * DM + h * DK;
    const int* maskp = maskg + b * SEQ;

    // load Q tile: 64 rows x 64 cols = 1024 float4
    for (int idx = tid; idx < 1024; idx += 256) {
        int r = idx >> 4;
        int c = (idx & 15) * 4;
        float4 v = *(const float4*)(Qbase + (size_t)r * DM + c);
        Qs[r * QPAD + c + 0] = v.x;
        Qs[r * QPAD + c + 1] = v.y;
        Qs[r * QPAD + c + 2] = v.z;
        Qs[r * QPAD + c + 3] = v.w;
    }

    float m_r[8], l_r[8], o0[8], o1[8];
#pragma unroll
    for (int r = 0; r < 8; r++) { m_r[r] = -1e30f; l_r[r] = 0.f; o0[r] = 0.f; o1[r] = 0.f; }

    for (int kb = 0; kb < SEQ / 64; kb++) {
        __syncthreads();
        const float* Kbase = Kg + ((size_t)(b * SEQ + kb * 64)) * DM + h * DK;
        const float* Vbase = Vg + ((size_t)(b * SEQ + kb * 64)) * DM + h * DK;
        for (int idx = tid; idx < 1024; idx += 256) {
            int r = idx >> 4;
            int c = (idx & 15) * 4;
            float4 kv = *(const float4*)(Kbase + (size_t)r * DM + c);
            Ks[r * KPAD + c + 0] = kv.x;
            Ks[r * KPAD + c + 1] = kv.y;
            Ks[r * KPAD + c + 2] = kv.z;
            Ks[r * KPAD + c + 3] = kv.w;
            float4 vv = *(const float4*)(Vbase + (size_t)r * DM + c);
            Vs[r * VPAD + c + 0] = vv.x;
            Vs[r * VPAD + c + 1] = vv.y;
            Vs[r * VPAD + c + 2] = vv.z;
            Vs[r * VPAD + c + 3] = vv.w;
        }
        __syncthreads();

        const int mk0 = maskp[kb * 64 + lane];
        const int mk1 = maskp[kb * 64 + lane + 32];

#pragma unroll 2
        for (int r = 0; r < 8; r++) {
            const int row = warp * 8 + r;
            const float* qrow = Qs + row * QPAD;
            const float* k0p = Ks + lane * KPAD;
            const float* k1p = Ks + (lane + 32) * KPAD;
            float s0 = 0.f, s1 = 0.f;
#pragma unroll 16
            for (int d = 0; d < DK; d++) {
                float q = qrow[d];
                s0 += q * k0p[d];
                s1 += q * k1p[d];
            }
            s0 *= 0.125f;   // 1/sqrt(64)
            s1 *= 0.125f;
            if (mk0 == 0) s0 = -1e30f;
            if (mk1 == 0) s1 = -1e30f;

            float smax = fmaxf(s0, s1);
#pragma unroll
            for (int off = 16; off > 0; off >>= 1)
                smax = fmaxf(smax, __shfl_xor_sync(0xffffffffu, smax, off));

            float mnew = fmaxf(m_r[r], smax);
            float corr = __expf(m_r[r] - mnew);
            float p0 = __expf(s0 - mnew);
            float p1 = __expf(s1 - mnew);
            float psum = p0 + p1;
#pragma unroll
            for (int off = 16; off > 0; off >>= 1)
                psum += __shfl_xor_sync(0xffffffffu, psum, off);

            l_r[r] = l_r[r] * corr + psum;
            m_r[r] = mnew;
            o0[r] *= corr;
            o1[r] *= corr;
            Ps[row * 64 + lane] = p0;
            Ps[row * 64 + lane + 32] = p1;
        }
        __syncwarp();

#pragma unroll 2
        for (int r = 0; r < 8; r++) {
            const int row = warp * 8 + r;
            const float* prow = Ps + row * 64;
            float a0 = o0[r], a1 = o1[r];
#pragma unroll 8
            for (int k = 0; k < 64; k++) {
                float p = prow[k];
                float2 v = *(const float2*)(Vs + k * VPAD + 2 * lane);
                a0 += p * v.x;
                a1 += p * v.y;
            }
            o0[r] = a0;
            o1[r] = a1;
        }
        __syncwarp();
    }

#pragma unroll
    for (int r = 0; r < 8; r++) {
        const int row = warp * 8 + r;
        float inv = 1.f / l_r[r];
        size_t off = ((size_t)(b * SEQ + qb * 64 + row)) * DM + h * DK + 2 * lane;
        Og[off + 0] = o0[r] * inv;
        Og[off + 1] = o1[r] * inv;
    }
}

// ---------------- fused residual + LayerNorm ------------------------------------
// out = LN(X + R) * gamma + beta ; one CTA per row of 1024, 256 threads
__global__ __launch_bounds__(256) void ln_residual(
    const float* __restrict__ X, const float* __restrict__ R,
    const float* __restrict__ gamma, const float* __restrict__ beta,
    float* __restrict__ out)
{
    const int row = blockIdx.x;
    const int tid = threadIdx.x;
    const float* x = X + (size_t)row * DM;
    const float* r = R + (size_t)row * DM;

    float vals[4];
    float sum = 0.f, sumsq = 0.f;
#pragma unroll
    for (int i = 0; i < 4; i++) {
        float v = x[tid + i * 256] + r[tid + i * 256];
        vals[i] = v;
        sum += v;
        sumsq += v * v;
    }

    __shared__ float2 wred[8];
    __shared__ float2 fin;
    float2 agg = make_float2(sum, sumsq);
#pragma unroll
    for (int off = 16; off > 0; off >>= 1) {
        agg.x += __shfl_xor_sync(0xffffffffu, agg.x, off);
        agg.y += __shfl_xor_sync(0xffffffffu, agg.y, off);
    }
    const int warp = tid >> 5, lane = tid & 31;
    if (lane == 0) wred[warp] = agg;
    __syncthreads();
    if (warp == 0) {
        float2 a = (lane < 8) ? wred[lane] : make_float2(0.f, 0.f);
#pragma unroll
        for (int off = 4; off > 0; off >>= 1) {
            a.x += __shfl_xor_sync(0xffffffffu, a.x, off);
            a.y += __shfl_xor_sync(0xffffffffu, a.y, off);
        }
        if (lane == 0) fin = a;
    }
    __syncthreads();

    float mu = fin.x * (1.f / DM);
    float var = fin.y * (1.f / DM) - mu * mu;
    float rstd = rsqrtf(var + LN_EPS);

    float* o = out + (size_t)row * DM;
#pragma unroll
    for (int i = 0; i < 4; i++) {
        int c = tid + i * 256;
        o[c] = (vals[i] - mu) * rstd * gamma[c] + beta[c];
    }
}

// ---------------- launch ----------------------------------------------------------
extern "C" void kernel_launch(void* const* d_in, const int* in_sizes, int n_in,
                              void* d_out, int out_size)
{
    const float* x    = (const float*)d_in[0];
    const int*   mask = (const int*)  d_in[1];
    const float* w_q  = (const float*)d_in[2];
    const float* b_q  = (const float*)d_in[3];
    const float* w_k  = (const float*)d_in[4];
    const float* b_k  = (const float*)d_in[5];
    const float* w_v  = (const float*)d_in[6];
    const float* b_v  = (const float*)d_in[7];
    const float* w_o  = (const float*)d_in[8];
    const float* b_o  = (const float*)d_in[9];
    const float* w1   = (const float*)d_in[10];
    const float* b1   = (const float*)d_in[11];
    const float* w2   = (const float*)d_in[12];
    const float* b2   = (const float*)d_in[13];
    const float* g1   = (const float*)d_in[14];
    const float* be1  = (const float*)d_in[15];
    const float* g2   = (const float*)d_in[16];
    const float* be2  = (const float*)d_in[17];
    float* out = (float*)d_out;

    float *pq, *pk, *pv, *pctx, *pattn, *ph, *pff1, *pff2;
    cudaGetSymbolAddress((void**)&pq,    g_q);
    cudaGetSymbolAddress((void**)&pk,    g_k);
    cudaGetSymbolAddress((void**)&pv,    g_v);
    cudaGetSymbolAddress((void**)&pctx,  g_ctx);
    cudaGetSymbolAddress((void**)&pattn, g_attn);
    cudaGetSymbolAddress((void**)&ph,    g_h);
    cudaGetSymbolAddress((void**)&pff1,  g_ff1);
    cudaGetSymbolAddress((void**)&pff2,  g_ff2);

    dim3 gD(DM / BN, MROWS / BM);     // (8, 64)
    dim3 gF1(DFF / BN, MROWS / BM);   // (32, 64)

    // QKV projections
    sgemm_bias<<<gD, 256>>>(x, w_q, b_q, pq, MROWS, DM, DM, 0);
    sgemm_bias<<<gD, 256>>>(x, w_k, b_k, pk, MROWS, DM, DM, 0);
    sgemm_bias<<<gD, 256>>>(x, w_v, b_v, pv, MROWS, DM, DM, 0);

    // attention
    const int attn_smem = (64 * QPAD + 64 * KPAD + 64 * VPAD + 64 * 64) * (int)sizeof(float);
    cudaFuncSetAttribute(attn_kernel, cudaFuncAttributeMaxDynamicSharedMemorySize, attn_smem);
    attn_kernel<<<dim3(SEQ / 64, BATCH * NH), 256, attn_smem>>>(pq, pk, pv, mask, pctx);

    // output projection
    sgemm_bias<<<gD, 256>>>(pctx, w_o, b_o, pattn, MROWS, DM, DM, 0);

    // LN1: h = LN(x + attn_out)
    ln_residual<<<MROWS, 256>>>(x, pattn, g1, be1, ph);

    // FFN
    sgemm_bias<<<gF1, 256>>>(ph, w1, b1, pff1, MROWS, DFF, DM, 1);
    sgemm_bias<<<gD, 256>>>(pff1, w2, b2, pff2, MROWS, DM, DFF, 0);

    // LN2: out = LN(h + ff)
    ln_residual<<<MROWS, 256>>>(ph, pff2, g2, be2, out);
}

// round 6
// speedup vs baseline: 1.3527x; 1.3527x over previous
#include <cuda_runtime.h>
#include <cuda_bf16.h>
#include <math.h>
#include <stdint.h>

// Problem constants
#define BATCH 4
#define SEQ   2048
#define DM    1024
#define NH    16
#define DK    64
#define DFF   4096
#define MROWS (BATCH * SEQ)   // 8192
#define LN_EPS 1e-5f

// ---------------- scratch (device globals; no allocation allowed) ----------------
__device__ float g_q[MROWS * DM];
__device__ float g_k[MROWS * DM];
__device__ float g_v[MROWS * DM];
__device__ float g_ctx[MROWS * DM];
__device__ float g_attn[MROWS * DM];
__device__ float g_h[MROWS * DM];
__device__ float g_hr[MROWS * DM];        // tf32-rounded copy of h
__device__ float g_xr[MROWS * DM];        // tf32-rounded copy of x
__device__ float g_ff1[(size_t)MROWS * DFF];
__device__ float g_ff2[MROWS * DM];
// transposed (+tf32-rounded) weights: [N,K] layout
__device__ float g_wtq[DM * DM];
__device__ float g_wtk[DM * DM];
__device__ float g_wtv[DM * DM];
__device__ float g_wto[DM * DM];
__device__ float g_wt1[(size_t)DFF * DM];
__device__ float g_wt2[(size_t)DM * DFF];

// ---------------- small helpers ---------------------------------------------------
__device__ __forceinline__ float rna_tf32(float v) {
    uint32_t u;
    asm("cvt.rna.tf32.f32 %0, %1;" : "=r"(u) : "f"(v));
    return __uint_as_float(u);
}

__device__ __forceinline__ uint32_t smem_u32(const void* p) {
    uint32_t a;
    asm("{ .reg .u64 t; cvta.to.shared.u64 t, %1; cvt.u32.u64 %0, t; }" : "=r"(a) : "l"(p));
    return a;
}

__device__ __forceinline__ void cp16(uint32_t dst, const void* src) {
    asm volatile("cp.async.cg.shared.global [%0], [%1], 16;" :: "r"(dst), "l"(src) : "memory");
}

__device__ __forceinline__ void cp_commit() {
    asm volatile("cp.async.commit_group;" ::: "memory");
}

__device__ __forceinline__ void cp_wait(int pend) {
    switch (pend) {
        case 0: asm volatile("cp.async.wait_group 0;" ::: "memory"); break;
        case 1: asm volatile("cp.async.wait_group 1;" ::: "memory"); break;
        case 2: asm volatile("cp.async.wait_group 2;" ::: "memory"); break;
        default: asm volatile("cp.async.wait_group 3;" ::: "memory"); break;
    }
}

__device__ __forceinline__ void mma_tf32(float* c, uint32_t a0, uint32_t a1,
                                         uint32_t a2, uint32_t a3,
                                         uint32_t b0, uint32_t b1) {
    asm volatile(
        "mma.sync.aligned.m16n8k8.row.col.f32.tf32.tf32.f32 "
        "{%0,%1,%2,%3}, {%4,%5,%6,%7}, {%8,%9}, {%0,%1,%2,%3};"
        : "+f"(c[0]), "+f"(c[1]), "+f"(c[2]), "+f"(c[3])
        : "r"(a0), "r"(a1), "r"(a2), "r"(a3), "r"(b0), "r"(b1));
}

// ---------------- tf32 mma.sync GEMM ----------------------------------------------
// C[M,N] = A[M,K] @ B[N,K]^T + bias, optional relu, optional tf32-rounded output.
// A, B must be K-major with tf32-rounded values.
// Tile 128x128, BK=32, 8 warps (4 warpM x 2 warpN), each warp 32x64.
// smem tiles stored [row][STRIDE] floats, STRIDE=36 (144B, 16B-aligned, conflict-free).
#define BK 32
#define GSTRIDE 36
#define TILE_FLOATS (128 * GSTRIDE)          // per-tile floats
#define STAGE_FLOATS (2 * TILE_FLOATS)       // A + B
#define NSTAGE 4
#define GEMM_SMEM (NSTAGE * STAGE_FLOATS * 4)  // 147456 bytes

__device__ __forceinline__ void g_load_stage(float* smem, const float* Ablk,
                                             const float* Bblk, int K, int s, int tid) {
    float* As = smem + (s & (NSTAGE - 1)) * STAGE_FLOATS;
    float* Bs = As + TILE_FLOATS;
    const int k0 = s * BK;
    const int row = tid >> 1;             // 0..127
    const int cc = (tid & 1) * 4;         // chunk pair: each thread does 4 chunks of 16B
    // each row has 8 chunks of 16B (32 floats); 256 threads -> each thread 4 A + 4 B chunks
#pragma unroll
    for (int i = 0; i < 4; i++) {
        int c = cc + (i & 1) + (i >> 1) * 2;   // cc, cc+1, cc+2, cc+3
        uint32_t soff = (uint32_t)(row * GSTRIDE + c * 4) * 4u;
        cp16(smem_u32(As) + soff, Ablk + (size_t)row * K + k0 + c * 4);
        cp16(smem_u32(Bs) + soff, Bblk + (size_t)row * K + k0 + c * 4);
    }
    cp_commit();
}

__global__ __launch_bounds__(256) void gemm_tf32(
    const float* __restrict__ A, const float* __restrict__ B,
    const float* __restrict__ bias, float* __restrict__ C,
    int M, int N, int K, int relu, int round_out)
{
    extern __shared__ float smem[];

    const int tid = threadIdx.x;
    const int wid = tid >> 5;
    const int lane = tid & 31;
    const int g = lane >> 2;          // group row 0..7
    const int tig = lane & 3;         // thread in group 0..3

    const int wm = wid & 3;           // warpM 0..3 -> rows wm*32
    const int wn = wid >> 2;          // warpN 0..1 -> cols wn*64
    const int rowBase = wm * 32;
    const int colBase = wn * 64;

    const int bx = blockIdx.x, by = blockIdx.y;
    const float* Ablk = A + (size_t)by * 128 * K;
    const float* Bblk = B + (size_t)bx * 128 * K;
    const int nstages = K / BK;

    float acc[2][8][4];
#pragma unroll
    for (int i = 0; i < 2; i++)
#pragma unroll
        for (int j = 0; j < 8; j++)
#pragma unroll
            for (int q = 0; q < 4; q++) acc[i][j][q] = 0.f;

    // prologue: stages 0..2
    g_load_stage(smem, Ablk, Bblk, K, 0, tid);
    g_load_stage(smem, Ablk, Bblk, K, 1, tid);
    g_load_stage(smem, Ablk, Bblk, K, 2, tid);

    for (int s = 0; s < nstages; s++) {
        if (s + 3 < nstages) g_load_stage(smem, Ablk, Bblk, K, s + 3, tid);
        int pend = nstages - 1 - s;
        if (pend > 3) pend = 3;
        cp_wait(pend);
        __syncthreads();

        const float* As = smem + (s & (NSTAGE - 1)) * STAGE_FLOATS;
        const float* Bs = As + TILE_FLOATS;
        const uint32_t* Au = (const uint32_t*)As;
        const uint32_t* Bu = (const uint32_t*)Bs;

#pragma unroll
        for (int ks = 0; ks < 4; ks++) {
            const int k0 = ks * 8;
            uint32_t af[2][4];
#pragma unroll
            for (int ma = 0; ma < 2; ma++) {
                int r0 = rowBase + ma * 16 + g;
                af[ma][0] = Au[r0 * GSTRIDE + k0 + tig];
                af[ma][1] = Au[(r0 + 8) * GSTRIDE + k0 + tig];
                af[ma][2] = Au[r0 * GSTRIDE + k0 + tig + 4];
                af[ma][3] = Au[(r0 + 8) * GSTRIDE + k0 + tig + 4];
            }
            uint32_t bf[8][2];
#pragma unroll
            for (int nb = 0; nb < 8; nb++) {
                int c0 = colBase + nb * 8 + g;
                bf[nb][0] = Bu[c0 * GSTRIDE + k0 + tig];
                bf[nb][1] = Bu[c0 * GSTRIDE + k0 + tig + 4];
            }
#pragma unroll
            for (int ma = 0; ma < 2; ma++)
#pragma unroll
                for (int nb = 0; nb < 8; nb++)
                    mma_tf32(acc[ma][nb], af[ma][0], af[ma][1], af[ma][2], af[ma][3],
                             bf[nb][0], bf[nb][1]);
        }
        __syncthreads();
    }

    // epilogue: write from registers with bias / relu / round
#pragma unroll
    for (int ma = 0; ma < 2; ma++) {
        int r0 = by * 128 + rowBase + ma * 16 + g;
        int r1 = r0 + 8;
#pragma unroll
        for (int nb = 0; nb < 8; nb++) {
            int col = bx * 128 + colBase + nb * 8 + 2 * tig;
            float b0 = bias[col], b1 = bias[col + 1];
            float2 v0, v1;
            v0.x = acc[ma][nb][0] + b0;
            v0.y = acc[ma][nb][1] + b1;
            v1.x = acc[ma][nb][2] + b0;
            v1.y = acc[ma][nb][3] + b1;
            if (relu) {
                v0.x = fmaxf(v0.x, 0.f); v0.y = fmaxf(v0.y, 0.f);
                v1.x = fmaxf(v1.x, 0.f); v1.y = fmaxf(v1.y, 0.f);
            }
            if (round_out) {
                v0.x = rna_tf32(v0.x); v0.y = rna_tf32(v0.y);
                v1.x = rna_tf32(v1.x); v1.y = rna_tf32(v1.y);
            }
            *(float2*)(C + (size_t)r0 * N + col) = v0;
            *(float2*)(C + (size_t)r1 * N + col) = v1;
        }
    }
}

// ---------------- transpose + tf32-round weights: in[K,N] -> out[N,K] -------------
__global__ __launch_bounds__(256) void transpose_rna(
    const float* __restrict__ in, float* __restrict__ out, int K, int N)
{
    __shared__ float t[32][33];
    int x = blockIdx.x * 32 + threadIdx.x;   // N index
    int y0 = blockIdx.y * 32;                // K base
#pragma unroll
    for (int j = 0; j < 32; j += 8)
        t[threadIdx.y + j][threadIdx.x] = rna_tf32(in[(size_t)(y0 + threadIdx.y + j) * N + x]);
    __syncthreads();
    int xo = blockIdx.y * 32 + threadIdx.x;  // K index
    int yo = blockIdx.x * 32;                // N base
#pragma unroll
    for (int j = 0; j < 32; j += 8)
        out[(size_t)(yo + threadIdx.y + j) * K + xo] = t[threadIdx.x][threadIdx.y + j];
}

// ---------------- elementwise tf32 rounding copy ----------------------------------
__global__ __launch_bounds__(256) void round_copy(
    const float* __restrict__ in, float* __restrict__ out, int n4)
{
    int i = blockIdx.x * blockDim.x + threadIdx.x;
    if (i < n4) {
        float4 v = ((const float4*)in)[i];
        v.x = rna_tf32(v.x); v.y = rna_tf32(v.y);
        v.z = rna_tf32(v.z); v.w = rna_tf32(v.w);
        ((float4*)out)[i] = v;
    }
}

// ---------------- Attention (flash-style, fp32; output tf32-rounded) ---------------
#define QPAD 64
#define KPAD 65
#define VPAD 66

__global__ __launch_bounds__(256) void attn_kernel(
    const float* __restrict__ Qg, const float* __restrict__ Kg,
    const float* __restrict__ Vg, const int* __restrict__ maskg,
    float* __restrict__ Og)
{
    extern __shared__ float sm[];
    float* Qs = sm;
    float* Ks = Qs + 64 * QPAD;
    float* Vs = Ks + 64 * KPAD;
    float* Ps = Vs + 64 * VPAD;

    const int bh = blockIdx.y;
    const int b = bh >> 4;
    const int h = bh & 15;
    const int qb = blockIdx.x;
    const int tid = threadIdx.x;
    const int warp = tid >> 5;
    const int lane = tid & 31;

    const float* Qbase = Qg + ((size_t)(b * SEQ + qb * 64)) * DM + h * DK;
    const int* maskp = maskg + b * SEQ;

    for (int idx = tid; idx < 1024; idx += 256) {
        int r = idx >> 4;
        int c = (idx & 15) * 4;
        float4 v = *(const float4*)(Qbase + (size_t)r * DM + c);
        Qs[r * QPAD + c + 0] = v.x;
        Qs[r * QPAD + c + 1] = v.y;
        Qs[r * QPAD + c + 2] = v.z;
        Qs[r * QPAD + c + 3] = v.w;
    }

    float m_r[8], l_r[8], o0[8], o1[8];
#pragma unroll
    for (int r = 0; r < 8; r++) { m_r[r] = -1e30f; l_r[r] = 0.f; o0[r] = 0.f; o1[r] = 0.f; }

    for (int kb = 0; kb < SEQ / 64; kb++) {
        __syncthreads();
        const float* Kbase = Kg + ((size_t)(b * SEQ + kb * 64)) * DM + h * DK;
        const float* Vbase = Vg + ((size_t)(b * SEQ + kb * 64)) * DM + h * DK;
        for (int idx = tid; idx < 1024; idx += 256) {
            int r = idx >> 4;
            int c = (idx & 15) * 4;
            float4 kv = *(const float4*)(Kbase + (size_t)r * DM + c);
            Ks[r * KPAD + c + 0] = kv.x;
            Ks[r * KPAD + c + 1] = kv.y;
            Ks[r * KPAD + c + 2] = kv.z;
            Ks[r * KPAD + c + 3] = kv.w;
            float4 vv = *(const float4*)(Vbase + (size_t)r * DM + c);
            Vs[r * VPAD + c + 0] = vv.x;
            Vs[r * VPAD + c + 1] = vv.y;
            Vs[r * VPAD + c + 2] = vv.z;
            Vs[r * VPAD + c + 3] = vv.w;
        }
        __syncthreads();

        const int mk0 = maskp[kb * 64 + lane];
        const int mk1 = maskp[kb * 64 + lane + 32];

#pragma unroll 2
        for (int r = 0; r < 8; r++) {
            const int row = warp * 8 + r;
            const float* qrow = Qs + row * QPAD;
            const float* k0p = Ks + lane * KPAD;
            const float* k1p = Ks + (lane + 32) * KPAD;
            float s0 = 0.f, s1 = 0.f;
#pragma unroll 16
            for (int d = 0; d < DK; d++) {
                float q = qrow[d];
                s0 += q * k0p[d];
                s1 += q * k1p[d];
            }
            s0 *= 0.125f;
            s1 *= 0.125f;
            if (mk0 == 0) s0 = -1e30f;
            if (mk1 == 0) s1 = -1e30f;

            float smax = fmaxf(s0, s1);
#pragma unroll
            for (int off = 16; off > 0; off >>= 1)
                smax = fmaxf(smax, __shfl_xor_sync(0xffffffffu, smax, off));

            float mnew = fmaxf(m_r[r], smax);
            float corr = __expf(m_r[r] - mnew);
            float p0 = __expf(s0 - mnew);
            float p1 = __expf(s1 - mnew);
            float psum = p0 + p1;
#pragma unroll
            for (int off = 16; off > 0; off >>= 1)
                psum += __shfl_xor_sync(0xffffffffu, psum, off);

            l_r[r] = l_r[r] * corr + psum;
            m_r[r] = mnew;
            o0[r] *= corr;
            o1[r] *= corr;
            Ps[row * 64 + lane] = p0;
            Ps[row * 64 + lane + 32] = p1;
        }
        __syncwarp();

#pragma unroll 2
        for (int r = 0; r < 8; r++) {
            const int row = warp * 8 + r;
            const float* prow = Ps + row * 64;
            float a0 = o0[r], a1 = o1[r];
#pragma unroll 8
            for (int k = 0; k < 64; k++) {
                float p = prow[k];
                float2 v = *(const float2*)(Vs + k * VPAD + 2 * lane);
                a0 += p * v.x;
                a1 += p * v.y;
            }
            o0[r] = a0;
            o1[r] = a1;
        }
        __syncwarp();
    }

#pragma unroll
    for (int r = 0; r < 8; r++) {
        const int row = warp * 8 + r;
        float inv = 1.f / l_r[r];
        size_t off = ((size_t)(b * SEQ + qb * 64 + row)) * DM + h * DK + 2 * lane;
        Og[off + 0] = rna_tf32(o0[r] * inv);
        Og[off + 1] = rna_tf32(o1[r] * inv);
    }
}

// ---------------- fused residual + LayerNorm (+optional tf32-rounded copy) --------
__global__ __launch_bounds__(256) void ln_residual(
    const float* __restrict__ X, const float* __restrict__ R,
    const float* __restrict__ gamma, const float* __restrict__ beta,
    float* __restrict__ out, float* __restrict__ outr)
{
    const int row = blockIdx.x;
    const int tid = threadIdx.x;
    const float* x = X + (size_t)row * DM;
    const float* r = R + (size_t)row * DM;

    float vals[4];
    float sum = 0.f, sumsq = 0.f;
#pragma unroll
    for (int i = 0; i < 4; i++) {
        float v = x[tid + i * 256] + r[tid + i * 256];
        vals[i] = v;
        sum += v;
        sumsq += v * v;
    }

    __shared__ float2 wred[8];
    __shared__ float2 fin;
    float2 agg = make_float2(sum, sumsq);
#pragma unroll
    for (int off = 16; off > 0; off >>= 1) {
        agg.x += __shfl_xor_sync(0xffffffffu, agg.x, off);
        agg.y += __shfl_xor_sync(0xffffffffu, agg.y, off);
    }
    const int warp = tid >> 5, lane = tid & 31;
    if (lane == 0) wred[warp] = agg;
    __syncthreads();
    if (warp == 0) {
        float2 a = (lane < 8) ? wred[lane] : make_float2(0.f, 0.f);
#pragma unroll
        for (int off = 4; off > 0; off >>= 1) {
            a.x += __shfl_xor_sync(0xffffffffu, a.x, off);
            a.y += __shfl_xor_sync(0xffffffffu, a.y, off);
        }
        if (lane == 0) fin = a;
    }
    __syncthreads();

    float mu = fin.x * (1.f / DM);
    float var = fin.y * (1.f / DM) - mu * mu;
    float rstd = rsqrtf(var + LN_EPS);

    float* o = out + (size_t)row * DM;
    float* orr = outr ? outr + (size_t)row * DM : nullptr;
#pragma unroll
    for (int i = 0; i < 4; i++) {
        int c = tid + i * 256;
        float y = (vals[i] - mu) * rstd * gamma[c] + beta[c];
        o[c] = y;
        if (orr) orr[c] = rna_tf32(y);
    }
}

// ---------------- launch ----------------------------------------------------------
extern "C" void kernel_launch(void* const* d_in, const int* in_sizes, int n_in,
                              void* d_out, int out_size)
{
    const float* x    = (const float*)d_in[0];
    const int*   mask = (const int*)  d_in[1];
    const float* w_q  = (const float*)d_in[2];
    const float* b_q  = (const float*)d_in[3];
    const float* w_k  = (const float*)d_in[4];
    const float* b_k  = (const float*)d_in[5];
    const float* w_v  = (const float*)d_in[6];
    const float* b_v  = (const float*)d_in[7];
    const float* w_o  = (const float*)d_in[8];
    const float* b_o  = (const float*)d_in[9];
    const float* w1   = (const float*)d_in[10];
    const float* b1   = (const float*)d_in[11];
    const float* w2   = (const float*)d_in[12];
    const float* b2   = (const float*)d_in[13];
    const float* g1   = (const float*)d_in[14];
    const float* be1  = (const float*)d_in[15];
    const float* g2   = (const float*)d_in[16];
    const float* be2  = (const float*)d_in[17];
    float* out = (float*)d_out;

    float *pq, *pk, *pv, *pctx, *pattn, *ph, *phr, *pxr, *pff1, *pff2;
    float *pwtq, *pwtk, *pwtv, *pwto, *pwt1, *pwt2;
    cudaGetSymbolAddress((void**)&pq,    g_q);
    cudaGetSymbolAddress((void**)&pk,    g_k);
    cudaGetSymbolAddress((void**)&pv,    g_v);
    cudaGetSymbolAddress((void**)&pctx,  g_ctx);
    cudaGetSymbolAddress((void**)&pattn, g_attn);
    cudaGetSymbolAddress((void**)&ph,    g_h);
    cudaGetSymbolAddress((void**)&phr,   g_hr);
    cudaGetSymbolAddress((void**)&pxr,   g_xr);
    cudaGetSymbolAddress((void**)&pff1,  g_ff1);
    cudaGetSymbolAddress((void**)&pff2,  g_ff2);
    cudaGetSymbolAddress((void**)&pwtq,  g_wtq);
    cudaGetSymbolAddress((void**)&pwtk,  g_wtk);
    cudaGetSymbolAddress((void**)&pwtv,  g_wtv);
    cudaGetSymbolAddress((void**)&pwto,  g_wto);
    cudaGetSymbolAddress((void**)&pwt1,  g_wt1);
    cudaGetSymbolAddress((void**)&pwt2,  g_wt2);

    cudaFuncSetAttribute(gemm_tf32, cudaFuncAttributeMaxDynamicSharedMemorySize, GEMM_SMEM);

    // weight transposes (+ tf32 rounding) and input rounding
    transpose_rna<<<dim3(DM / 32, DM / 32), dim3(32, 8)>>>(w_q, pwtq, DM, DM);
    transpose_rna<<<dim3(DM / 32, DM / 32), dim3(32, 8)>>>(w_k, pwtk, DM, DM);
    transpose_rna<<<dim3(DM / 32, DM / 32), dim3(32, 8)>>>(w_v, pwtv, DM, DM);
    transpose_rna<<<dim3(DM / 32, DM / 32), dim3(32, 8)>>>(w_o, pwto, DM, DM);
    transpose_rna<<<dim3(DFF / 32, DM / 32), dim3(32, 8)>>>(w1, pwt1, DM, DFF);
    transpose_rna<<<dim3(DM / 32, DFF / 32), dim3(32, 8)>>>(w2, pwt2, DFF, DM);
    round_copy<<<(MROWS * DM / 4 + 255) / 256, 256>>>(x, pxr, MROWS * DM / 4);

    dim3 gD(DM / 128, MROWS / 128);      // (8, 64)
    dim3 gF1(DFF / 128, MROWS / 128);    // (32, 64)

    // QKV projections (tf32 mma.sync tensor cores)
    gemm_tf32<<<gD, 256, GEMM_SMEM>>>(pxr, pwtq, b_q, pq, MROWS, DM, DM, 0, 0);
    gemm_tf32<<<gD, 256, GEMM_SMEM>>>(pxr, pwtk, b_k, pk, MROWS, DM, DM, 0, 0);
    gemm_tf32<<<gD, 256, GEMM_SMEM>>>(pxr, pwtv, b_v, pv, MROWS, DM, DM, 0, 0);

    // attention (fp32; output tf32-rounded for next GEMM)
    const int attn_smem = (64 * QPAD + 64 * KPAD + 64 * VPAD + 64 * 64) * (int)sizeof(float);
    cudaFuncSetAttribute(attn_kernel, cudaFuncAttributeMaxDynamicSharedMemorySize, attn_smem);
    attn_kernel<<<dim3(SEQ / 64, BATCH * NH), 256, attn_smem>>>(pq, pk, pv, mask, pctx);

    // output projection
    gemm_tf32<<<gD, 256, GEMM_SMEM>>>(pctx, pwto, b_o, pattn, MROWS, DM, DM, 0, 0);

    // LN1: h = LN(x + attn_out); hr = tf32-rounded h
    ln_residual<<<MROWS, 256>>>(x, pattn, g1, be1, ph, phr);

    // FFN (tf32; ff1 output rounded since it feeds FFN2)
    gemm_tf32<<<gF1, 256, GEMM_SMEM>>>(phr, pwt1, b1, pff1, MROWS, DFF, DM, 1, 1);
    gemm_tf32<<<gD, 256, GEMM_SMEM>>>(pff1, pwt2, b2, pff2, MROWS, DM, DFF, 0, 0);

    // LN2: out = LN(h + ff)
    ln_residual<<<MROWS, 256>>>(ph, pff2, g2, be2, out, nullptr);
}

// round 7
// speedup vs baseline: 1.4202x; 1.0498x over previous
#include <cuda_runtime.h>
#include <cuda_bf16.h>
#include <math.h>
#include <stdint.h>

// Problem constants
#define BATCH 4
#define SEQ   2048
#define DM    1024
#define NH    16
#define DK    64
#define DFF   4096
#define MROWS (BATCH * SEQ)   // 8192
#define LN_EPS 1e-5f

// ---------------- scratch (device globals; no allocation allowed) ----------------
__device__ float g_qkv[(size_t)MROWS * 3 * DM];   // fused QKV output [MROWS][3072]
__device__ float g_ctx[MROWS * DM];
__device__ float g_attn[MROWS * DM];
__device__ float g_h[MROWS * DM];
__device__ float g_hr[MROWS * DM];        // tf32-rounded copy of h
__device__ float g_xr[MROWS * DM];        // tf32-rounded copy of x
__device__ float g_ff1[(size_t)MROWS * DFF];
__device__ float g_ff2[MROWS * DM];
// transposed (+tf32-rounded) weights: [N,K] layout
__device__ float g_wqkv[(size_t)3 * DM * DM];     // [3072][1024]
__device__ float g_bqkv[3 * DM];
__device__ float g_wto[DM * DM];
__device__ float g_wt1[(size_t)DFF * DM];
__device__ float g_wt2[(size_t)DM * DFF];

// ---------------- small helpers ---------------------------------------------------
__device__ __forceinline__ float rna_tf32(float v) {
    uint32_t u;
    asm("cvt.rna.tf32.f32 %0, %1;" : "=r"(u) : "f"(v));
    return __uint_as_float(u);
}

__device__ __forceinline__ uint32_t smem_u32(const void* p) {
    uint32_t a;
    asm("{ .reg .u64 t; cvta.to.shared.u64 t, %1; cvt.u32.u64 %0, t; }" : "=r"(a) : "l"(p));
    return a;
}

__device__ __forceinline__ void cp16(uint32_t dst, const void* src) {
    asm volatile("cp.async.cg.shared.global [%0], [%1], 16;" :: "r"(dst), "l"(src) : "memory");
}

__device__ __forceinline__ void cp_commit() {
    asm volatile("cp.async.commit_group;" ::: "memory");
}

__device__ __forceinline__ void cp_wait(int pend) {
    if (pend == 0) asm volatile("cp.async.wait_group 0;" ::: "memory");
    else           asm volatile("cp.async.wait_group 1;" ::: "memory");
}

__device__ __forceinline__ void mma_tf32(float* c, uint32_t a0, uint32_t a1,
                                         uint32_t a2, uint32_t a3,
                                         uint32_t b0, uint32_t b1) {
    asm volatile(
        "mma.sync.aligned.m16n8k8.row.col.f32.tf32.tf32.f32 "
        "{%0,%1,%2,%3}, {%4,%5,%6,%7}, {%8,%9}, {%0,%1,%2,%3};"
        : "+f"(c[0]), "+f"(c[1]), "+f"(c[2]), "+f"(c[3])
        : "r"(a0), "r"(a1), "r"(a2), "r"(a3), "r"(b0), "r"(b1));
}

// ---------------- tf32 mma.sync GEMM ----------------------------------------------
// C[M,N] = A[M,K] @ B[N,K]^T + bias, optional relu, optional tf32-rounded output.
// A, B must be K-major with tf32-rounded values.
// Tile 128x128, BK=32, 8 warps (4 warpM x 2 warpN), each warp 32x64.
// 3-stage cp.async ring, ONE __syncthreads per stage, 2 CTAs/SM.
#define BK 32
#define GSTRIDE 36
#define TILE_FLOATS (128 * GSTRIDE)          // per-tile floats
#define STAGE_FLOATS (2 * TILE_FLOATS)       // A + B
#define NSTAGE 3
#define GEMM_SMEM (NSTAGE * STAGE_FLOATS * 4)  // 110592 bytes

__device__ __forceinline__ void g_load_stage(float* smem, const float* Ablk,
                                             const float* Bblk, int K, int s, int tid) {
    float* As = smem + (s % NSTAGE) * STAGE_FLOATS;
    float* Bs = As + TILE_FLOATS;
    const int k0 = s * BK;
    const int row = tid >> 1;             // 0..127
    const int cc = (tid & 1) * 4;         // starting 16B chunk
#pragma unroll
    for (int i = 0; i < 4; i++) {
        int c = cc + i;                   // cc..cc+3
        uint32_t soff = (uint32_t)(row * GSTRIDE + c * 4) * 4u;
        cp16(smem_u32(As) + soff, Ablk + (size_t)row * K + k0 + c * 4);
        cp16(smem_u32(Bs) + soff, Bblk + (size_t)row * K + k0 + c * 4);
    }
    cp_commit();
}

__global__ __launch_bounds__(256, 2) void gemm_tf32(
    const float* __restrict__ A, const float* __restrict__ B,
    const float* __restrict__ bias, float* __restrict__ C,
    int M, int N, int K, int relu, int round_out)
{
    extern __shared__ float smem[];

    const int tid = threadIdx.x;
    const int wid = tid >> 5;
    const int lane = tid & 31;
    const int g = lane >> 2;          // group row 0..7
    const int tig = lane & 3;         // thread in group 0..3

    const int wm = wid & 3;           // warpM 0..3 -> rows wm*32
    const int wn = wid >> 2;          // warpN 0..1 -> cols wn*64
    const int rowBase = wm * 32;
    const int colBase = wn * 64;

    const int bx = blockIdx.x, by = blockIdx.y;
    const float* Ablk = A + (size_t)by * 128 * K;
    const float* Bblk = B + (size_t)bx * 128 * K;
    const int nstages = K / BK;

    float acc[2][8][4];
#pragma unroll
    for (int i = 0; i < 2; i++)
#pragma unroll
        for (int j = 0; j < 8; j++)
#pragma unroll
            for (int q = 0; q < 4; q++) acc[i][j][q] = 0.f;

    // prologue: stages 0,1
    g_load_stage(smem, Ablk, Bblk, K, 0, tid);
    g_load_stage(smem, Ablk, Bblk, K, 1, tid);

    for (int s = 0; s < nstages; s++) {
        cp_wait((s + 1 < nstages) ? 1 : 0);
        __syncthreads();
        // all warps have finished compute of stage s-1, whose buffer (s-1)%3 == (s+2)%3
        if (s + 2 < nstages) g_load_stage(smem, Ablk, Bblk, K, s + 2, tid);

        const float* As = smem + (s % NSTAGE) * STAGE_FLOATS;
        const float* Bs = As + TILE_FLOATS;
        const uint32_t* Au = (const uint32_t*)As;
        const uint32_t* Bu = (const uint32_t*)Bs;

#pragma unroll
        for (int ks = 0; ks < 4; ks++) {
            const int k0 = ks * 8;
            uint32_t af[2][4];
#pragma unroll
            for (int ma = 0; ma < 2; ma++) {
                int r0 = rowBase + ma * 16 + g;
                af[ma][0] = Au[r0 * GSTRIDE + k0 + tig];
                af[ma][1] = Au[(r0 + 8) * GSTRIDE + k0 + tig];
                af[ma][2] = Au[r0 * GSTRIDE + k0 + tig + 4];
                af[ma][3] = Au[(r0 + 8) * GSTRIDE + k0 + tig + 4];
            }
            uint32_t bf[8][2];
#pragma unroll
            for (int nb = 0; nb < 8; nb++) {
                int c0 = colBase + nb * 8 + g;
                bf[nb][0] = Bu[c0 * GSTRIDE + k0 + tig];
                bf[nb][1] = Bu[c0 * GSTRIDE + k0 + tig + 4];
            }
#pragma unroll
            for (int ma = 0; ma < 2; ma++)
#pragma unroll
                for (int nb = 0; nb < 8; nb++)
                    mma_tf32(acc[ma][nb], af[ma][0], af[ma][1], af[ma][2], af[ma][3],
                             bf[nb][0], bf[nb][1]);
        }
    }

    // epilogue: write from registers with bias / relu / round
#pragma unroll
    for (int ma = 0; ma < 2; ma++) {
        int r0 = by * 128 + rowBase + ma * 16 + g;
        int r1 = r0 + 8;
#pragma unroll
        for (int nb = 0; nb < 8; nb++) {
            int col = bx * 128 + colBase + nb * 8 + 2 * tig;
            float b0 = bias[col], b1 = bias[col + 1];
            float2 v0, v1;
            v0.x = acc[ma][nb][0] + b0;
            v0.y = acc[ma][nb][1] + b1;
            v1.x = acc[ma][nb][2] + b0;
            v1.y = acc[ma][nb][3] + b1;
            if (relu) {
                v0.x = fmaxf(v0.x, 0.f); v0.y = fmaxf(v0.y, 0.f);
                v1.x = fmaxf(v1.x, 0.f); v1.y = fmaxf(v1.y, 0.f);
            }
            if (round_out) {
                v0.x = rna_tf32(v0.x); v0.y = rna_tf32(v0.y);
                v1.x = rna_tf32(v1.x); v1.y = rna_tf32(v1.y);
            }
            *(float2*)(C + (size_t)r0 * N + col) = v0;
            *(float2*)(C + (size_t)r1 * N + col) = v1;
        }
    }
}

// ---------------- transpose + tf32-round weights: in[K,N] -> out[N,K] -------------
__global__ __launch_bounds__(256) void transpose_rna(
    const float* __restrict__ in, float* __restrict__ out, int K, int N)
{
    __shared__ float t[32][33];
    int x = blockIdx.x * 32 + threadIdx.x;   // N index
    int y0 = blockIdx.y * 32;                // K base
#pragma unroll
    for (int j = 0; j < 32; j += 8)
        t[threadIdx.y + j][threadIdx.x] = rna_tf32(in[(size_t)(y0 + threadIdx.y + j) * N + x]);
    __syncthreads();
    int xo = blockIdx.y * 32 + threadIdx.x;  // K index
    int yo = blockIdx.x * 32;                // N base
#pragma unroll
    for (int j = 0; j < 32; j += 8)
        out[(size_t)(yo + threadIdx.y + j) * K + xo] = t[threadIdx.x][threadIdx.y + j];
}

// ---------------- elementwise tf32 rounding copy ----------------------------------
__global__ __launch_bounds__(256) void round_copy(
    const float* __restrict__ in, float* __restrict__ out, int n4)
{
    int i = blockIdx.x * blockDim.x + threadIdx.x;
    if (i < n4) {
        float4 v = ((const float4*)in)[i];
        v.x = rna_tf32(v.x); v.y = rna_tf32(v.y);
        v.z = rna_tf32(v.z); v.w = rna_tf32(v.w);
        ((float4*)out)[i] = v;
    }
}

// ---------------- bias concat for fused QKV ---------------------------------------
__global__ void concat_bias3(const float* __restrict__ b0, const float* __restrict__ b1,
                             const float* __restrict__ b2, float* __restrict__ out)
{
    int i = blockIdx.x * blockDim.x + threadIdx.x;   // 0..3071
    if (i < DM) out[i] = b0[i];
    else if (i < 2 * DM) out[i] = b1[i - DM];
    else if (i < 3 * DM) out[i] = b2[i - 2 * DM];
}

// ---------------- Attention (flash-style, fp32; output tf32-rounded) ---------------
// Q/K/V are strided views into the fused QKV buffer (row stride = rstr floats).
#define QPAD 64
#define KPAD 65
#define VPAD 66

__global__ __launch_bounds__(256) void attn_kernel(
    const float* __restrict__ Qg, const float* __restrict__ Kg,
    const float* __restrict__ Vg, const int* __restrict__ maskg,
    float* __restrict__ Og, int rstr)
{
    extern __shared__ float sm[];
    float* Qs = sm;
    float* Ks = Qs + 64 * QPAD;
    float* Vs = Ks + 64 * KPAD;
    float* Ps = Vs + 64 * VPAD;

    const int bh = blockIdx.y;
    const int b = bh >> 4;
    const int h = bh & 15;
    const int qb = blockIdx.x;
    const int tid = threadIdx.x;
    const int warp = tid >> 5;
    const int lane = tid & 31;

    const float* Qbase = Qg + ((size_t)(b * SEQ + qb * 64)) * rstr + h * DK;
    const int* maskp = maskg + b * SEQ;

    for (int idx = tid; idx < 1024; idx += 256) {
        int r = idx >> 4;
        int c = (idx & 15) * 4;
        float4 v = *(const float4*)(Qbase + (size_t)r * rstr + c);
        Qs[r * QPAD + c + 0] = v.x;
        Qs[r * QPAD + c + 1] = v.y;
        Qs[r * QPAD + c + 2] = v.z;
        Qs[r * QPAD + c + 3] = v.w;
    }

    float m_r[8], l_r[8], o0[8], o1[8];
#pragma unroll
    for (int r = 0; r < 8; r++) { m_r[r] = -1e30f; l_r[r] = 0.f; o0[r] = 0.f; o1[r] = 0.f; }

    for (int kb = 0; kb < SEQ / 64; kb++) {
        __syncthreads();
        const float* Kbase = Kg + ((size_t)(b * SEQ + kb * 64)) * rstr + h * DK;
        const float* Vbase = Vg + ((size_t)(b * SEQ + kb * 64)) * rstr + h * DK;
        for (int idx = tid; idx < 1024; idx += 256) {
            int r = idx >> 4;
            int c = (idx & 15) * 4;
            float4 kv = *(const float4*)(Kbase + (size_t)r * rstr + c);
            Ks[r * KPAD + c + 0] = kv.x;
            Ks[r * KPAD + c + 1] = kv.y;
            Ks[r * KPAD + c + 2] = kv.z;
            Ks[r * KPAD + c + 3] = kv.w;
            float4 vv = *(const float4*)(Vbase + (size_t)r * rstr + c);
            Vs[r * VPAD + c + 0] = vv.x;
            Vs[r * VPAD + c + 1] = vv.y;
            Vs[r * VPAD + c + 2] = vv.z;
            Vs[r * VPAD + c + 3] = vv.w;
        }
        __syncthreads();

        const int mk0 = maskp[kb * 64 + lane];
        const int mk1 = maskp[kb * 64 + lane + 32];

#pragma unroll 2
        for (int r = 0; r < 8; r++) {
            const int row = warp * 8 + r;
            const float* qrow = Qs + row * QPAD;
            const float* k0p = Ks + lane * KPAD;
            const float* k1p = Ks + (lane + 32) * KPAD;
            float s0 = 0.f, s1 = 0.f;
#pragma unroll 16
            for (int d = 0; d < DK; d++) {
                float q = qrow[d];
                s0 += q * k0p[d];
                s1 += q * k1p[d];
            }
            s0 *= 0.125f;
            s1 *= 0.125f;
            if (mk0 == 0) s0 = -1e30f;
            if (mk1 == 0) s1 = -1e30f;

            float smax = fmaxf(s0, s1);
#pragma unroll
            for (int off = 16; off > 0; off >>= 1)
                smax = fmaxf(smax, __shfl_xor_sync(0xffffffffu, smax, off));

            float mnew = fmaxf(m_r[r], smax);
            float corr = __expf(m_r[r] - mnew);
            float p0 = __expf(s0 - mnew);
            float p1 = __expf(s1 - mnew);
            float psum = p0 + p1;
#pragma unroll
            for (int off = 16; off > 0; off >>= 1)
                psum += __shfl_xor_sync(0xffffffffu, psum, off);

            l_r[r] = l_r[r] * corr + psum;
            m_r[r] = mnew;
            o0[r] *= corr;
            o1[r] *= corr;
            Ps[row * 64 + lane] = p0;
            Ps[row * 64 + lane + 32] = p1;
        }
        __syncwarp();

#pragma unroll 2
        for (int r = 0; r < 8; r++) {
            const int row = warp * 8 + r;
            const float* prow = Ps + row * 64;
            float a0 = o0[r], a1 = o1[r];
#pragma unroll 8
            for (int k = 0; k < 64; k++) {
                float p = prow[k];
                float2 v = *(const float2*)(Vs + k * VPAD + 2 * lane);
                a0 += p * v.x;
                a1 += p * v.y;
            }
            o0[r] = a0;
            o1[r] = a1;
        }
        __syncwarp();
    }

#pragma unroll
    for (int r = 0; r < 8; r++) {
        const int row = warp * 8 + r;
        float inv = 1.f / l_r[r];
        size_t off = ((size_t)(b * SEQ + qb * 64 + row)) * DM + h * DK + 2 * lane;
        Og[off + 0] = rna_tf32(o0[r] * inv);
        Og[off + 1] = rna_tf32(o1[r] * inv);
    }
}

// ---------------- fused residual + LayerNorm (+optional tf32-rounded copy) --------
__global__ __launch_bounds__(256) void ln_residual(
    const float* __restrict__ X, const float* __restrict__ R,
    const float* __restrict__ gamma, const float* __restrict__ beta,
    float* __restrict__ out, float* __restrict__ outr)
{
    const int row = blockIdx.x;
    const int tid = threadIdx.x;
    const float* x = X + (size_t)row * DM;
    const float* r = R + (size_t)row * DM;

    float vals[4];
    float sum = 0.f, sumsq = 0.f;
#pragma unroll
    for (int i = 0; i < 4; i++) {
        float v = x[tid + i * 256] + r[tid + i * 256];
        vals[i] = v;
        sum += v;
        sumsq += v * v;
    }

    __shared__ float2 wred[8];
    __shared__ float2 fin;
    float2 agg = make_float2(sum, sumsq);
#pragma unroll
    for (int off = 16; off > 0; off >>= 1) {
        agg.x += __shfl_xor_sync(0xffffffffu, agg.x, off);
        agg.y += __shfl_xor_sync(0xffffffffu, agg.y, off);
    }
    const int warp = tid >> 5, lane = tid & 31;
    if (lane == 0) wred[warp] = agg;
    __syncthreads();
    if (warp == 0) {
        float2 a = (lane < 8) ? wred[lane] : make_float2(0.f, 0.f);
#pragma unroll
        for (int off = 4; off > 0; off >>= 1) {
            a.x += __shfl_xor_sync(0xffffffffu, a.x, off);
            a.y += __shfl_xor_sync(0xffffffffu, a.y, off);
        }
        if (lane == 0) fin = a;
    }
    __syncthreads();

    float mu = fin.x * (1.f / DM);
    float var = fin.y * (1.f / DM) - mu * mu;
    float rstd = rsqrtf(var + LN_EPS);

    float* o = out + (size_t)row * DM;
    float* orr = outr ? outr + (size_t)row * DM : nullptr;
#pragma unroll
    for (int i = 0; i < 4; i++) {
        int c = tid + i * 256;
        float y = (vals[i] - mu) * rstd * gamma[c] + beta[c];
        o[c] = y;
        if (orr) orr[c] = rna_tf32(y);
    }
}

// ---------------- launch ----------------------------------------------------------
extern "C" void kernel_launch(void* const* d_in, const int* in_sizes, int n_in,
                              void* d_out, int out_size)
{
    const float* x    = (const float*)d_in[0];
    const int*   mask = (const int*)  d_in[1];
    const float* w_q  = (const float*)d_in[2];
    const float* b_q  = (const float*)d_in[3];
    const float* w_k  = (const float*)d_in[4];
    const float* b_k  = (const float*)d_in[5];
    const float* w_v  = (const float*)d_in[6];
    const float* b_v  = (const float*)d_in[7];
    const float* w_o  = (const float*)d_in[8];
    const float* b_o  = (const float*)d_in[9];
    const float* w1   = (const float*)d_in[10];
    const float* b1   = (const float*)d_in[11];
    const float* w2   = (const float*)d_in[12];
    const float* b2   = (const float*)d_in[13];
    const float* g1   = (const float*)d_in[14];
    const float* be1  = (const float*)d_in[15];
    const float* g2   = (const float*)d_in[16];
    const float* be2  = (const float*)d_in[17];
    float* out = (float*)d_out;

    float *pqkv, *pctx, *pattn, *ph, *phr, *pxr, *pff1, *pff2;
    float *pwqkv, *pbqkv, *pwto, *pwt1, *pwt2;
    cudaGetSymbolAddress((void**)&pqkv,  g_qkv);
    cudaGetSymbolAddress((void**)&pctx,  g_ctx);
    cudaGetSymbolAddress((void**)&pattn, g_attn);
    cudaGetSymbolAddress((void**)&ph,    g_h);
    cudaGetSymbolAddress((void**)&phr,   g_hr);
    cudaGetSymbolAddress((void**)&pxr,   g_xr);
    cudaGetSymbolAddress((void**)&pff1,  g_ff1);
    cudaGetSymbolAddress((void**)&pff2,  g_ff2);
    cudaGetSymbolAddress((void**)&pwqkv, g_wqkv);
    cudaGetSymbolAddress((void**)&pbqkv, g_bqkv);
    cudaGetSymbolAddress((void**)&pwto,  g_wto);
    cudaGetSymbolAddress((void**)&pwt1,  g_wt1);
    cudaGetSymbolAddress((void**)&pwt2,  g_wt2);

    cudaFuncSetAttribute(gemm_tf32, cudaFuncAttributeMaxDynamicSharedMemorySize, GEMM_SMEM);

    // weight transposes (+ tf32 rounding) into fused QKV buffer, bias concat, x round
    transpose_rna<<<dim3(DM / 32, DM / 32), dim3(32, 8)>>>(w_q, pwqkv, DM, DM);
    transpose_rna<<<dim3(DM / 32, DM / 32), dim3(32, 8)>>>(w_k, pwqkv + DM * DM, DM, DM);
    transpose_rna<<<dim3(DM / 32, DM / 32), dim3(32, 8)>>>(w_v, pwqkv + 2 * DM * DM, DM, DM);
    transpose_rna<<<dim3(DM / 32, DM / 32), dim3(32, 8)>>>(w_o, pwto, DM, DM);
    transpose_rna<<<dim3(DFF / 32, DM / 32), dim3(32, 8)>>>(w1, pwt1, DM, DFF);
    transpose_rna<<<dim3(DM / 32, DFF / 32), dim3(32, 8)>>>(w2, pwt2, DFF, DM);
    concat_bias3<<<12, 256>>>(b_q, b_k, b_v, pbqkv);
    round_copy<<<(MROWS * DM / 4 + 255) / 256, 256>>>(x, pxr, MROWS * DM / 4);

    dim3 gQKV(3 * DM / 128, MROWS / 128);  // (24, 64)
    dim3 gD(DM / 128, MROWS / 128);        // (8, 64)
    dim3 gF1(DFF / 128, MROWS / 128);      // (32, 64)

    // fused QKV projection (tf32 mma.sync tensor cores)
    gemm_tf32<<<gQKV, 256, GEMM_SMEM>>>(pxr, pwqkv, pbqkv, pqkv, MROWS, 3 * DM, DM, 0, 0);

    // attention (fp32; Q/K/V strided views of fused buffer; output tf32-rounded)
    const int attn_smem = (64 * QPAD + 64 * KPAD + 64 * VPAD + 64 * 64) * (int)sizeof(float);
    cudaFuncSetAttribute(attn_kernel, cudaFuncAttributeMaxDynamicSharedMemorySize, attn_smem);
    attn_kernel<<<dim3(SEQ / 64, BATCH * NH), 256, attn_smem>>>(
        pqkv, pqkv + DM, pqkv + 2 * DM, mask, pctx, 3 * DM);

    // output projection
    gemm_tf32<<<gD, 256, GEMM_SMEM>>>(pctx, pwto, b_o, pattn, MROWS, DM, DM, 0, 0);

    // LN1: h = LN(x + attn_out); hr = tf32-rounded h
    ln_residual<<<MROWS, 256>>>(x, pattn, g1, be1, ph, phr);

    // FFN (tf32; ff1 output rounded since it feeds FFN2)
    gemm_tf32<<<gF1, 256, GEMM_SMEM>>>(phr, pwt1, b1, pff1, MROWS, DFF, DM, 1, 1);
    gemm_tf32<<<gD, 256, GEMM_SMEM>>>(pff1, pwt2, b2, pff2, MROWS, DM, DFF, 0, 0);

    // LN2: out = LN(h + ff)
    ln_residual<<<MROWS, 256>>>(ph, pff2, g2, be2, out, nullptr);
}

// round 8
// speedup vs baseline: 4.2551x; 2.9962x over previous
#include <cuda_runtime.h>
#include <cuda_bf16.h>
#include <math.h>
#include <stdint.h>

// Problem constants
#define BATCH 4
#define SEQ   2048
#define DM    1024
#define NH    16
#define DK    64
#define DFF   4096
#define MROWS (BATCH * SEQ)   // 8192
#define LN_EPS 1e-5f

// ---------------- scratch (device globals; no allocation allowed) ----------------
__device__ float g_qkv[(size_t)MROWS * 3 * DM];   // fused QKV output [MROWS][3072]
__device__ float g_ctx[MROWS * DM];
__device__ float g_attn[MROWS * DM];
__device__ float g_h[MROWS * DM];
__device__ float g_hr[MROWS * DM];        // tf32-rounded copy of h
__device__ float g_xr[MROWS * DM];        // tf32-rounded copy of x
__device__ float g_ff1[(size_t)MROWS * DFF];
__device__ float g_ff2[MROWS * DM];
// transposed (+tf32-rounded) weights: [N,K] layout
__device__ float g_wqkv[(size_t)3 * DM * DM];     // [3072][1024]
__device__ float g_bqkv[3 * DM];
__device__ float g_wto[DM * DM];
__device__ float g_wt1[(size_t)DFF * DM];
__device__ float g_wt2[(size_t)DM * DFF];

// ---------------- small helpers ---------------------------------------------------
__device__ __forceinline__ float rna_tf32(float v) {
    uint32_t u;
    asm("cvt.rna.tf32.f32 %0, %1;" : "=r"(u) : "f"(v));
    return __uint_as_float(u);
}

__device__ __forceinline__ uint32_t smem_u32(const void* p) {
    uint32_t a;
    asm("{ .reg .u64 t; cvta.to.shared.u64 t, %1; cvt.u32.u64 %0, t; }" : "=r"(a) : "l"(p));
    return a;
}

__device__ __forceinline__ void cp16(uint32_t dst, const void* src) {
    asm volatile("cp.async.cg.shared.global [%0], [%1], 16;" :: "r"(dst), "l"(src) : "memory");
}

__device__ __forceinline__ void cp_commit() {
    asm volatile("cp.async.commit_group;" ::: "memory");
}

__device__ __forceinline__ void cp_wait(int pend) {
    if (pend == 0) asm volatile("cp.async.wait_group 0;" ::: "memory");
    else           asm volatile("cp.async.wait_group 1;" ::: "memory");
}

__device__ __forceinline__ void mma_tf32(float* c, uint32_t a0, uint32_t a1,
                                         uint32_t a2, uint32_t a3,
                                         uint32_t b0, uint32_t b1) {
    asm volatile(
        "mma.sync.aligned.m16n8k8.row.col.f32.tf32.tf32.f32 "
        "{%0,%1,%2,%3}, {%4,%5,%6,%7}, {%8,%9}, {%0,%1,%2,%3};"
        : "+f"(c[0]), "+f"(c[1]), "+f"(c[2]), "+f"(c[3])
        : "r"(a0), "r"(a1), "r"(a2), "r"(a3), "r"(b0), "r"(b1));
}

__device__ __forceinline__ uint32_t fi(float v) { return __float_as_uint(v); }

// ---------------- tf32 mma.sync GEMM ----------------------------------------------
// (unchanged from R7 — known-good)
#define BK 32
#define GSTRIDE 36
#define TILE_FLOATS (128 * GSTRIDE)
#define STAGE_FLOATS (2 * TILE_FLOATS)
#define NSTAGE 3
#define GEMM_SMEM (NSTAGE * STAGE_FLOATS * 4)  // 110592 bytes

__device__ __forceinline__ void g_load_stage(float* smem, const float* Ablk,
                                             const float* Bblk, int K, int s, int tid) {
    float* As = smem + (s % NSTAGE) * STAGE_FLOATS;
    float* Bs = As + TILE_FLOATS;
    const int k0 = s * BK;
    const int row = tid >> 1;
    const int cc = (tid & 1) * 4;
#pragma unroll
    for (int i = 0; i < 4; i++) {
        int c = cc + i;
        uint32_t soff = (uint32_t)(row * GSTRIDE + c * 4) * 4u;
        cp16(smem_u32(As) + soff, Ablk + (size_t)row * K + k0 + c * 4);
        cp16(smem_u32(Bs) + soff, Bblk + (size_t)row * K + k0 + c * 4);
    }
    cp_commit();
}

__global__ __launch_bounds__(256, 2) void gemm_tf32(
    const float* __restrict__ A, const float* __restrict__ B,
    const float* __restrict__ bias, float* __restrict__ C,
    int M, int N, int K, int relu, int round_out)
{
    extern __shared__ float smem[];

    const int tid = threadIdx.x;
    const int wid = tid >> 5;
    const int lane = tid & 31;
    const int g = lane >> 2;
    const int tig = lane & 3;

    const int wm = wid & 3;
    const int wn = wid >> 2;
    const int rowBase = wm * 32;
    const int colBase = wn * 64;

    const int bx = blockIdx.x, by = blockIdx.y;
    const float* Ablk = A + (size_t)by * 128 * K;
    const float* Bblk = B + (size_t)bx * 128 * K;
    const int nstages = K / BK;

    float acc[2][8][4];
#pragma unroll
    for (int i = 0; i < 2; i++)
#pragma unroll
        for (int j = 0; j < 8; j++)
#pragma unroll
            for (int q = 0; q < 4; q++) acc[i][j][q] = 0.f;

    g_load_stage(smem, Ablk, Bblk, K, 0, tid);
    g_load_stage(smem, Ablk, Bblk, K, 1, tid);

    for (int s = 0; s < nstages; s++) {
        cp_wait((s + 1 < nstages) ? 1 : 0);
        __syncthreads();
        if (s + 2 < nstages) g_load_stage(smem, Ablk, Bblk, K, s + 2, tid);

        const float* As = smem + (s % NSTAGE) * STAGE_FLOATS;
        const float* Bs = As + TILE_FLOATS;
        const uint32_t* Au = (const uint32_t*)As;
        const uint32_t* Bu = (const uint32_t*)Bs;

#pragma unroll
        for (int ks = 0; ks < 4; ks++) {
            const int k0 = ks * 8;
            uint32_t af[2][4];
#pragma unroll
            for (int ma = 0; ma < 2; ma++) {
                int r0 = rowBase + ma * 16 + g;
                af[ma][0] = Au[r0 * GSTRIDE + k0 + tig];
                af[ma][1] = Au[(r0 + 8) * GSTRIDE + k0 + tig];
                af[ma][2] = Au[r0 * GSTRIDE + k0 + tig + 4];
                af[ma][3] = Au[(r0 + 8) * GSTRIDE + k0 + tig + 4];
            }
            uint32_t bf[8][2];
#pragma unroll
            for (int nb = 0; nb < 8; nb++) {
                int c0 = colBase + nb * 8 + g;
                bf[nb][0] = Bu[c0 * GSTRIDE + k0 + tig];
                bf[nb][1] = Bu[c0 * GSTRIDE + k0 + tig + 4];
            }
#pragma unroll
            for (int ma = 0; ma < 2; ma++)
#pragma unroll
                for (int nb = 0; nb < 8; nb++)
                    mma_tf32(acc[ma][nb], af[ma][0], af[ma][1], af[ma][2], af[ma][3],
                             bf[nb][0], bf[nb][1]);
        }
    }

#pragma unroll
    for (int ma = 0; ma < 2; ma++) {
        int r0 = by * 128 + rowBase + ma * 16 + g;
        int r1 = r0 + 8;
#pragma unroll
        for (int nb = 0; nb < 8; nb++) {
            int col = bx * 128 + colBase + nb * 8 + 2 * tig;
            float b0 = bias[col], b1 = bias[col + 1];
            float2 v0, v1;
            v0.x = acc[ma][nb][0] + b0;
            v0.y = acc[ma][nb][1] + b1;
            v1.x = acc[ma][nb][2] + b0;
            v1.y = acc[ma][nb][3] + b1;
            if (relu) {
                v0.x = fmaxf(v0.x, 0.f); v0.y = fmaxf(v0.y, 0.f);
                v1.x = fmaxf(v1.x, 0.f); v1.y = fmaxf(v1.y, 0.f);
            }
            if (round_out) {
                v0.x = rna_tf32(v0.x); v0.y = rna_tf32(v0.y);
                v1.x = rna_tf32(v1.x); v1.y = rna_tf32(v1.y);
            }
            *(float2*)(C + (size_t)r0 * N + col) = v0;
            *(float2*)(C + (size_t)r1 * N + col) = v1;
        }
    }
}

// ---------------- transpose + tf32-round weights: in[K,N] -> out[N,K] -------------
__global__ __launch_bounds__(256) void transpose_rna(
    const float* __restrict__ in, float* __restrict__ out, int K, int N)
{
    __shared__ float t[32][33];
    int x = blockIdx.x * 32 + threadIdx.x;
    int y0 = blockIdx.y * 32;
#pragma unroll
    for (int j = 0; j < 32; j += 8)
        t[threadIdx.y + j][threadIdx.x] = rna_tf32(in[(size_t)(y0 + threadIdx.y + j) * N + x]);
    __syncthreads();
    int xo = blockIdx.y * 32 + threadIdx.x;
    int yo = blockIdx.x * 32;
#pragma unroll
    for (int j = 0; j < 32; j += 8)
        out[(size_t)(yo + threadIdx.y + j) * K + xo] = t[threadIdx.x][threadIdx.y + j];
}

// ---------------- elementwise tf32 rounding copy ----------------------------------
__global__ __launch_bounds__(256) void round_copy(
    const float* __restrict__ in, float* __restrict__ out, int n4)
{
    int i = blockIdx.x * blockDim.x + threadIdx.x;
    if (i < n4) {
        float4 v = ((const float4*)in)[i];
        v.x = rna_tf32(v.x); v.y = rna_tf32(v.y);
        v.z = rna_tf32(v.z); v.w = rna_tf32(v.w);
        ((float4*)out)[i] = v;
    }
}

// ---------------- bias concat for fused QKV ---------------------------------------
__global__ void concat_bias3(const float* __restrict__ b0, const float* __restrict__ b1,
                             const float* __restrict__ b2, float* __restrict__ out)
{
    int i = blockIdx.x * blockDim.x + threadIdx.x;
    if (i < DM) out[i] = b0[i];
    else if (i < 2 * DM) out[i] = b1[i - DM];
    else if (i < 3 * DM) out[i] = b2[i - 2 * DM];
}

// ---------------- Flash attention on tf32 mma.sync --------------------------------
// CTA: 128 queries (8 warps x m16), iterate 64-key blocks, dk=64.
// Q/K/V are rna-tf32 values in the fused qkv buffer (row stride rstr floats).
// Logical-k permutation: logical cols {tig, tig+4} <-> physical {2tig, 2tig+1}
// so every fragment load is one float2 LDS. QP=KP=72, VP=68 => conflict-free.
#define AQT 128
#define AKT 64
#define AQP 72
#define AKP 72
#define AVP 68
// smem (floats): Q[128*72]=9216 | K 2x[64*72]=9216 | V 2x[64*68]=8704 | mask 2x64=128
#define A_OFF_K 9216
#define A_OFF_V 18432
#define A_OFF_M 27136
#define ATTN_SMEM ((27136 + 128) * 4)   // 109056 bytes

__device__ __forceinline__ void attn_load_kv(float* sm, const float* Kb, const float* Vb,
                                             const int* mb, int buf, int tid, int rstr) {
    float* Ks = sm + A_OFF_K + buf * (AKT * AKP);
    float* Vs = sm + A_OFF_V + buf * (AKT * AVP);
    int* mk = (int*)(sm + A_OFF_M) + buf * 64;
#pragma unroll
    for (int i = 0; i < 4; i++) {
        int idx = tid + i * 256;
        int r = idx >> 4;
        int c = (idx & 15) * 4;
        cp16(smem_u32(Ks + r * AKP + c), Kb + (size_t)r * rstr + c);
        cp16(smem_u32(Vs + r * AVP + c), Vb + (size_t)r * rstr + c);
    }
    if (tid < 16) cp16(smem_u32(mk + tid * 4), mb + tid * 4);
    cp_commit();
}

__global__ __launch_bounds__(256, 2) void attn_mma(
    const float* __restrict__ Qg, const float* __restrict__ Kg,
    const float* __restrict__ Vg, const int* __restrict__ maskg,
    float* __restrict__ Og, int rstr)
{
    extern __shared__ float sm[];
    const int tid = threadIdx.x;
    const int warp = tid >> 5;
    const int lane = tid & 31;
    const int g = lane >> 2;
    const int tig = lane & 3;

    const int bh = blockIdx.y;
    const int b = bh >> 4;
    const int h = bh & 15;
    const int qb = blockIdx.x;

    const float* Qbase = Qg + (size_t)(b * SEQ + qb * AQT) * rstr + h * DK;
    const int* maskp = maskg + b * SEQ;

    // load Q tile (128 x 64) into smem
#pragma unroll
    for (int i = 0; i < 8; i++) {
        int idx = tid + i * 256;
        int r = idx >> 4;
        int c = (idx & 15) * 4;
        cp16(smem_u32(sm + r * AQP + c), Qbase + (size_t)r * rstr + c);
    }
    cp_commit();

    // prologue: kb=0 into buffer 0
    attn_load_kv(sm, Kg + (size_t)(b * SEQ) * rstr + h * DK,
                 Vg + (size_t)(b * SEQ) * rstr + h * DK, maskp, 0, tid, rstr);

    float o[8][4];
#pragma unroll
    for (int nt = 0; nt < 8; nt++)
#pragma unroll
        for (int j = 0; j < 4; j++) o[nt][j] = 0.f;
    float m0 = -1e30f, m1 = -1e30f, l0 = 0.f, l1 = 0.f;

    const int qrow0 = warp * 16 + g;        // local query rows qrow0, qrow0+8

    for (int kb = 0; kb < SEQ / AKT; kb++) {
        cp_wait(0);
        __syncthreads();
        if (kb + 1 < SEQ / AKT) {
            const float* Kb = Kg + (size_t)(b * SEQ + (kb + 1) * AKT) * rstr + h * DK;
            const float* Vb = Vg + (size_t)(b * SEQ + (kb + 1) * AKT) * rstr + h * DK;
            attn_load_kv(sm, Kb, Vb, maskp + (kb + 1) * AKT, (kb + 1) & 1, tid, rstr);
        }

        const float* Ks = sm + A_OFF_K + (kb & 1) * (AKT * AKP);
        const float* Vs = sm + A_OFF_V + (kb & 1) * (AKT * AVP);
        const int* mk = (const int*)(sm + A_OFF_M) + (kb & 1) * 64;

        // ---- S = Q @ K^T (m16 x n64 x k64 per warp) ----
        float s[8][4];
#pragma unroll
        for (int nt = 0; nt < 8; nt++)
#pragma unroll
            for (int j = 0; j < 4; j++) s[nt][j] = 0.f;

#pragma unroll
        for (int ks = 0; ks < 8; ks++) {
            float2 q0 = *(const float2*)(sm + qrow0 * AQP + ks * 8 + 2 * tig);
            float2 q1 = *(const float2*)(sm + (qrow0 + 8) * AQP + ks * 8 + 2 * tig);
#pragma unroll
            for (int nt = 0; nt < 8; nt++) {
                float2 kk = *(const float2*)(Ks + (nt * 8 + g) * AKP + ks * 8 + 2 * tig);
                mma_tf32(s[nt], fi(q0.x), fi(q1.x), fi(q0.y), fi(q1.y),
                         fi(kk.x), fi(kk.y));
            }
        }

        // ---- mask + scale + online softmax ----
        float mx0 = -1e30f, mx1 = -1e30f;
#pragma unroll
        for (int nt = 0; nt < 8; nt++) {
            int c0 = nt * 8 + 2 * tig;
            int mk0v = mk[c0];
            int mk1v = mk[c0 + 1];
            float v0 = s[nt][0] * 0.125f; if (mk0v == 0) v0 = -1e30f;
            float v1 = s[nt][1] * 0.125f; if (mk1v == 0) v1 = -1e30f;
            float v2 = s[nt][2] * 0.125f; if (mk0v == 0) v2 = -1e30f;
            float v3 = s[nt][3] * 0.125f; if (mk1v == 0) v3 = -1e30f;
            s[nt][0] = v0; s[nt][1] = v1; s[nt][2] = v2; s[nt][3] = v3;
            mx0 = fmaxf(mx0, fmaxf(v0, v1));
            mx1 = fmaxf(mx1, fmaxf(v2, v3));
        }
        mx0 = fmaxf(mx0, __shfl_xor_sync(0xffffffffu, mx0, 1));
        mx0 = fmaxf(mx0, __shfl_xor_sync(0xffffffffu, mx0, 2));
        mx1 = fmaxf(mx1, __shfl_xor_sync(0xffffffffu, mx1, 1));
        mx1 = fmaxf(mx1, __shfl_xor_sync(0xffffffffu, mx1, 2));

        float mn0 = fmaxf(m0, mx0);
        float mn1 = fmaxf(m1, mx1);
        float corr0 = __expf(m0 - mn0);
        float corr1 = __expf(m1 - mn1);
        m0 = mn0; m1 = mn1;

        float ps0 = 0.f, ps1 = 0.f;
#pragma unroll
        for (int nt = 0; nt < 8; nt++) {
            float p0 = __expf(s[nt][0] - mn0);
            float p1 = __expf(s[nt][1] - mn0);
            float p2 = __expf(s[nt][2] - mn1);
            float p3 = __expf(s[nt][3] - mn1);
            ps0 += p0 + p1;
            ps1 += p2 + p3;
            s[nt][0] = rna_tf32(p0); s[nt][1] = rna_tf32(p1);
            s[nt][2] = rna_tf32(p2); s[nt][3] = rna_tf32(p3);
        }
        ps0 += __shfl_xor_sync(0xffffffffu, ps0, 1);
        ps0 += __shfl_xor_sync(0xffffffffu, ps0, 2);
        ps1 += __shfl_xor_sync(0xffffffffu, ps1, 1);
        ps1 += __shfl_xor_sync(0xffffffffu, ps1, 2);
        l0 = l0 * corr0 + ps0;
        l1 = l1 * corr1 + ps1;

#pragma unroll
        for (int nt = 0; nt < 8; nt++) {
            o[nt][0] *= corr0; o[nt][1] *= corr0;
            o[nt][2] *= corr1; o[nt][3] *= corr1;
        }

        // ---- O += P @ V  (P a-frags straight from S accumulators) ----
#pragma unroll
        for (int ks = 0; ks < 8; ks++) {
            uint32_t a0 = fi(s[ks][0]);   // (row g,   phys key 2tig)   = logical tig
            uint32_t a1 = fi(s[ks][2]);   // (row g+8, phys key 2tig)
            uint32_t a2 = fi(s[ks][1]);   // (row g,   phys key 2tig+1) = logical tig+4
            uint32_t a3 = fi(s[ks][3]);
            const float* vr0 = Vs + (ks * 8 + 2 * tig) * AVP;
            const float* vr1 = vr0 + AVP;
#pragma unroll
            for (int nt = 0; nt < 8; nt++) {
                int d = nt * 8 + g;
                mma_tf32(o[nt], a0, a1, a2, a3, fi(vr0[d]), fi(vr1[d]));
            }
        }
    }

    // ---- epilogue: normalize + store (rna for O-projection input) ----
    float inv0 = 1.f / l0;
    float inv1 = 1.f / l1;
    int grow = b * SEQ + qb * AQT + qrow0;
#pragma unroll
    for (int nt = 0; nt < 8; nt++) {
        int col = h * DK + nt * 8 + 2 * tig;
        float2 v0, v1;
        v0.x = rna_tf32(o[nt][0] * inv0);
        v0.y = rna_tf32(o[nt][1] * inv0);
        v1.x = rna_tf32(o[nt][2] * inv1);
        v1.y = rna_tf32(o[nt][3] * inv1);
        *(float2*)(Og + (size_t)grow * DM + col) = v0;
        *(float2*)(Og + (size_t)(grow + 8) * DM + col) = v1;
    }
}

// ---------------- fused residual + LayerNorm (+optional tf32-rounded copy) --------
__global__ __launch_bounds__(256) void ln_residual(
    const float* __restrict__ X, const float* __restrict__ R,
    const float* __restrict__ gamma, const float* __restrict__ beta,
    float* __restrict__ out, float* __restrict__ outr)
{
    const int row = blockIdx.x;
    const int tid = threadIdx.x;
    const float* x = X + (size_t)row * DM;
    const float* r = R + (size_t)row * DM;

    float vals[4];
    float sum = 0.f, sumsq = 0.f;
#pragma unroll
    for (int i = 0; i < 4; i++) {
        float v = x[tid + i * 256] + r[tid + i * 256];
        vals[i] = v;
        sum += v;
        sumsq += v * v;
    }

    __shared__ float2 wred[8];
    __shared__ float2 fin;
    float2 agg = make_float2(sum, sumsq);
#pragma unroll
    for (int off = 16; off > 0; off >>= 1) {
        agg.x += __shfl_xor_sync(0xffffffffu, agg.x, off);
        agg.y += __shfl_xor_sync(0xffffffffu, agg.y, off);
    }
    const int warp = tid >> 5, lane = tid & 31;
    if (lane == 0) wred[warp] = agg;
    __syncthreads();
    if (warp == 0) {
        float2 a = (lane < 8) ? wred[lane] : make_float2(0.f, 0.f);
#pragma unroll
        for (int off = 4; off > 0; off >>= 1) {
            a.x += __shfl_xor_sync(0xffffffffu, a.x, off);
            a.y += __shfl_xor_sync(0xffffffffu, a.y, off);
        }
        if (lane == 0) fin = a;
    }
    __syncthreads();

    float mu = fin.x * (1.f / DM);
    float var = fin.y * (1.f / DM) - mu * mu;
    float rstd = rsqrtf(var + LN_EPS);

    float* o = out + (size_t)row * DM;
    float* orr = outr ? outr + (size_t)row * DM : nullptr;
#pragma unroll
    for (int i = 0; i < 4; i++) {
        int c = tid + i * 256;
        float y = (vals[i] - mu) * rstd * gamma[c] + beta[c];
        o[c] = y;
        if (orr) orr[c] = rna_tf32(y);
    }
}

// ---------------- launch ----------------------------------------------------------
extern "C" void kernel_launch(void* const* d_in, const int* in_sizes, int n_in,
                              void* d_out, int out_size)
{
    const float* x    = (const float*)d_in[0];
    const int*   mask = (const int*)  d_in[1];
    const float* w_q  = (const float*)d_in[2];
    const float* b_q  = (const float*)d_in[3];
    const float* w_k  = (const float*)d_in[4];
    const float* b_k  = (const float*)d_in[5];
    const float* w_v  = (const float*)d_in[6];
    const float* b_v  = (const float*)d_in[7];
    const float* w_o  = (const float*)d_in[8];
    const float* b_o  = (const float*)d_in[9];
    const float* w1   = (const float*)d_in[10];
    const float* b1   = (const float*)d_in[11];
    const float* w2   = (const float*)d_in[12];
    const float* b2   = (const float*)d_in[13];
    const float* g1   = (const float*)d_in[14];
    const float* be1  = (const float*)d_in[15];
    const float* g2   = (const float*)d_in[16];
    const float* be2  = (const float*)d_in[17];
    float* out = (float*)d_out;

    float *pqkv, *pctx, *pattn, *ph, *phr, *pxr, *pff1, *pff2;
    float *pwqkv, *pbqkv, *pwto, *pwt1, *pwt2;
    cudaGetSymbolAddress((void**)&pqkv,  g_qkv);
    cudaGetSymbolAddress((void**)&pctx,  g_ctx);
    cudaGetSymbolAddress((void**)&pattn, g_attn);
    cudaGetSymbolAddress((void**)&ph,    g_h);
    cudaGetSymbolAddress((void**)&phr,   g_hr);
    cudaGetSymbolAddress((void**)&pxr,   g_xr);
    cudaGetSymbolAddress((void**)&pff1,  g_ff1);
    cudaGetSymbolAddress((void**)&pff2,  g_ff2);
    cudaGetSymbolAddress((void**)&pwqkv, g_wqkv);
    cudaGetSymbolAddress((void**)&pbqkv, g_bqkv);
    cudaGetSymbolAddress((void**)&pwto,  g_wto);
    cudaGetSymbolAddress((void**)&pwt1,  g_wt1);
    cudaGetSymbolAddress((void**)&pwt2,  g_wt2);

    cudaFuncSetAttribute(gemm_tf32, cudaFuncAttributeMaxDynamicSharedMemorySize, GEMM_SMEM);
    cudaFuncSetAttribute(attn_mma, cudaFuncAttributeMaxDynamicSharedMemorySize, ATTN_SMEM);

    dim3 gQKV(3 * DM / 128, MROWS / 128);  // (24, 64)
    dim3 gD(DM / 128, MROWS / 128);        // (8, 64)
    dim3 gF1(DFF / 128, MROWS / 128);      // (32, 64)

    // launches 1-5: prep so that launch #6 is the QKV GEMM (ncu -s 5 -c 1 profiles it)
    transpose_rna<<<dim3(DM / 32, DM / 32), dim3(32, 8)>>>(w_q, pwqkv, DM, DM);
    transpose_rna<<<dim3(DM / 32, DM / 32), dim3(32, 8)>>>(w_k, pwqkv + DM * DM, DM, DM);
    transpose_rna<<<dim3(DM / 32, DM / 32), dim3(32, 8)>>>(w_v, pwqkv + 2 * DM * DM, DM, DM);
    concat_bias3<<<12, 256>>>(b_q, b_k, b_v, pbqkv);
    round_copy<<<(MROWS * DM / 4 + 255) / 256, 256>>>(x, pxr, MROWS * DM / 4);

    // fused QKV projection (rna-tf32 output so attention MMA truncation is exact)
    gemm_tf32<<<gQKV, 256, GEMM_SMEM>>>(pxr, pwqkv, pbqkv, pqkv, MROWS, 3 * DM, DM, 0, 1);

    // remaining weight transposes (independent of attention)
    transpose_rna<<<dim3(DM / 32, DM / 32), dim3(32, 8)>>>(w_o, pwto, DM, DM);
    transpose_rna<<<dim3(DFF / 32, DM / 32), dim3(32, 8)>>>(w1, pwt1, DM, DFF);
    transpose_rna<<<dim3(DM / 32, DFF / 32), dim3(32, 8)>>>(w2, pwt2, DFF, DM);

    // flash attention on tensor cores
    attn_mma<<<dim3(SEQ / AQT, BATCH * NH), 256, ATTN_SMEM>>>(
        pqkv, pqkv + DM, pqkv + 2 * DM, mask, pctx, 3 * DM);

    // output projection
    gemm_tf32<<<gD, 256, GEMM_SMEM>>>(pctx, pwto, b_o, pattn, MROWS, DM, DM, 0, 0);

    // LN1: h = LN(x + attn_out); hr = tf32-rounded h
    ln_residual<<<MROWS, 256>>>(x, pattn, g1, be1, ph, phr);

    // FFN
    gemm_tf32<<<gF1, 256, GEMM_SMEM>>>(phr, pwt1, b1, pff1, MROWS, DFF, DM, 1, 1);
    gemm_tf32<<<gD, 256, GEMM_SMEM>>>(pff1, pwt2, b2, pff2, MROWS, DM, DFF, 0, 0);

    // LN2: out = LN(h + ff)
    ln_residual<<<MROWS, 256>>>(ph, pff2, g2, be2, out, nullptr);
}

// round 9
// speedup vs baseline: 7.2264x; 1.6983x over previous
#include <cuda_runtime.h>
#include <cuda_fp16.h>
#include <math.h>
#include <stdint.h>

// Problem constants
#define BATCH 4
#define SEQ   2048
#define DM    1024
#define NH    16
#define DK    64
#define DFF   4096
#define MROWS (BATCH * SEQ)   // 8192
#define LN_EPS 1e-5f

// ---------------- scratch (device globals; no allocation allowed) ----------------
__device__ float  g_qkv[(size_t)MROWS * 3 * DM];   // fused QKV (tf32-rounded) for attn
__device__ __half g_xh[MROWS * DM];
__device__ __half g_ctxh[MROWS * DM];
__device__ float  g_attn[MROWS * DM];
__device__ float  g_h[MROWS * DM];
__device__ __half g_hh[MROWS * DM];
__device__ __half g_ff1h[(size_t)MROWS * DFF];
__device__ float  g_ff2[MROWS * DM];
// transposed (+fp16) weights: [N,K] layout
__device__ __half g_wqkvh[(size_t)3 * DM * DM];
__device__ float  g_bqkv[3 * DM];
__device__ __half g_wtoh[DM * DM];
__device__ __half g_wt1h[(size_t)DFF * DM];
__device__ __half g_wt2h[(size_t)DM * DFF];

// ---------------- small helpers ---------------------------------------------------
__device__ __forceinline__ float rna_tf32(float v) {
    uint32_t u;
    asm("cvt.rna.tf32.f32 %0, %1;" : "=r"(u) : "f"(v));
    return __uint_as_float(u);
}

__device__ __forceinline__ uint32_t smem_u32(const void* p) {
    uint32_t a;
    asm("{ .reg .u64 t; cvta.to.shared.u64 t, %1; cvt.u32.u64 %0, t; }" : "=r"(a) : "l"(p));
    return a;
}

__device__ __forceinline__ void cp16(uint32_t dst, const void* src) {
    asm volatile("cp.async.cg.shared.global [%0], [%1], 16;" :: "r"(dst), "l"(src) : "memory");
}

__device__ __forceinline__ void cp_commit() {
    asm volatile("cp.async.commit_group;" ::: "memory");
}

__device__ __forceinline__ void cp_wait(int pend) {
    if (pend == 0) asm volatile("cp.async.wait_group 0;" ::: "memory");
    else           asm volatile("cp.async.wait_group 1;" ::: "memory");
}

__device__ __forceinline__ void mma_tf32(float* c, uint32_t a0, uint32_t a1,
                                         uint32_t a2, uint32_t a3,
                                         uint32_t b0, uint32_t b1) {
    asm volatile(
        "mma.sync.aligned.m16n8k8.row.col.f32.tf32.tf32.f32 "
        "{%0,%1,%2,%3}, {%4,%5,%6,%7}, {%8,%9}, {%0,%1,%2,%3};"
        : "+f"(c[0]), "+f"(c[1]), "+f"(c[2]), "+f"(c[3])
        : "r"(a0), "r"(a1), "r"(a2), "r"(a3), "r"(b0), "r"(b1));
}

__device__ __forceinline__ void mma_f16(float* c, uint32_t a0, uint32_t a1,
                                        uint32_t a2, uint32_t a3,
                                        uint32_t b0, uint32_t b1) {
    asm volatile(
        "mma.sync.aligned.m16n8k16.row.col.f32.f16.f16.f32 "
        "{%0,%1,%2,%3}, {%4,%5,%6,%7}, {%8,%9}, {%0,%1,%2,%3};"
        : "+f"(c[0]), "+f"(c[1]), "+f"(c[2]), "+f"(c[3])
        : "r"(a0), "r"(a1), "r"(a2), "r"(a3), "r"(b0), "r"(b1));
}

__device__ __forceinline__ void ldsm4(uint32_t& r0, uint32_t& r1, uint32_t& r2,
                                      uint32_t& r3, uint32_t addr) {
    asm volatile("ldmatrix.sync.aligned.m8n8.x4.shared.b16 {%0,%1,%2,%3}, [%4];"
                 : "=r"(r0), "=r"(r1), "=r"(r2), "=r"(r3) : "r"(addr));
}

__device__ __forceinline__ uint32_t fi(float v) { return __float_as_uint(v); }

// ---------------- fp16 mma.sync GEMM ----------------------------------------------
// C[M,N] = A[M,K] @ B[N,K]^T + bias, optional relu.
// A, B are __half, K-major. mode: 0=float out, 1=float+tf32-round, 2=half out.
// Tile 128x128, BK=64 halves, 8 warps (4x2), warp tile 32x64, ldmatrix frags.
// HST=72 halves/row: 144B row stride => ldmatrix phases conflict-free.
#define HBK 64
#define HST 72
#define HTILE (128 * HST)        // halves per tile (9216)
#define HSTAGE (2 * HTILE)       // A+B halves
#define HNST 3
#define GEMM_SMEM (HNST * HSTAGE * 2)   // 110592 bytes

__device__ __forceinline__ void h_load_stage(__half* smem, const __half* Ablk,
                                             const __half* Bblk, int K, int s, int tid) {
    __half* As = smem + (s % HNST) * HSTAGE;
    __half* Bs = As + HTILE;
    const int k0 = s * HBK;
    const int row = tid >> 1;          // 0..127
    const int c0 = (tid & 1) * 4;      // 16B chunks 0..7 per row (8 halves each)
#pragma unroll
    for (int i = 0; i < 4; i++) {
        int c = c0 + i;
        cp16(smem_u32(As + row * HST + c * 8), Ablk + (size_t)row * K + k0 + c * 8);
        cp16(smem_u32(Bs + row * HST + c * 8), Bblk + (size_t)row * K + k0 + c * 8);
    }
    cp_commit();
}

__global__ __launch_bounds__(256, 2) void gemm_f16(
    const __half* __restrict__ A, const __half* __restrict__ B,
    const float* __restrict__ bias, void* __restrict__ C,
    int M, int N, int K, int relu, int mode)
{
    extern __shared__ __half hsm[];

    const int tid = threadIdx.x;
    const int wid = tid >> 5;
    const int lane = tid & 31;
    const int g = lane >> 2;
    const int tig = lane & 3;
    const int lr = lane & 7;
    const int sub = lane >> 3;

    const int rowBase = (wid & 3) * 32;
    const int colBase = (wid >> 2) * 64;

    // ldmatrix per-lane row/koff (element units)
    int a_row[2], b_row[4];
#pragma unroll
    for (int ma = 0; ma < 2; ma++)
        a_row[ma] = rowBase + ma * 16 + ((sub & 1) << 3) + lr;
    const int a_koff = (sub >> 1) << 3;
#pragma unroll
    for (int nbp = 0; nbp < 4; nbp++)
        b_row[nbp] = colBase + nbp * 16 + ((sub >> 1) << 3) + lr;
    const int b_koff = (sub & 1) << 3;

    const int bx = blockIdx.x, by = blockIdx.y;
    const __half* Ablk = A + (size_t)by * 128 * K;
    const __half* Bblk = B + (size_t)bx * 128 * K;
    const int nstages = K / HBK;

    float acc[2][8][4];
#pragma unroll
    for (int i = 0; i < 2; i++)
#pragma unroll
        for (int j = 0; j < 8; j++)
#pragma unroll
            for (int q = 0; q < 4; q++) acc[i][j][q] = 0.f;

    h_load_stage(hsm, Ablk, Bblk, K, 0, tid);
    h_load_stage(hsm, Ablk, Bblk, K, 1, tid);

    for (int s = 0; s < nstages; s++) {
        cp_wait((s + 1 < nstages) ? 1 : 0);
        __syncthreads();
        if (s + 2 < nstages) h_load_stage(hsm, Ablk, Bblk, K, s + 2, tid);

        const __half* As = hsm + (s % HNST) * HSTAGE;
        const __half* Bs = As + HTILE;
        const uint32_t abase = smem_u32(As);
        const uint32_t bbase = smem_u32(Bs);

#pragma unroll
        for (int ks = 0; ks < 4; ks++) {
            const int k0 = ks * 16;
            uint32_t a[2][4];
#pragma unroll
            for (int ma = 0; ma < 2; ma++)
                ldsm4(a[ma][0], a[ma][1], a[ma][2], a[ma][3],
                      abase + (uint32_t)(a_row[ma] * HST + k0 + a_koff) * 2u);
            uint32_t bb[4][4];
#pragma unroll
            for (int nbp = 0; nbp < 4; nbp++)
                ldsm4(bb[nbp][0], bb[nbp][1], bb[nbp][2], bb[nbp][3],
                      bbase + (uint32_t)(b_row[nbp] * HST + k0 + b_koff) * 2u);
#pragma unroll
            for (int ma = 0; ma < 2; ma++)
#pragma unroll
                for (int nb = 0; nb < 8; nb++)
                    mma_f16(acc[ma][nb], a[ma][0], a[ma][1], a[ma][2], a[ma][3],
                            bb[nb >> 1][(nb & 1) * 2], bb[nb >> 1][(nb & 1) * 2 + 1]);
        }
    }

    // epilogue
#pragma unroll
    for (int ma = 0; ma < 2; ma++) {
        int r0 = by * 128 + rowBase + ma * 16 + g;
        int r1 = r0 + 8;
#pragma unroll
        for (int nb = 0; nb < 8; nb++) {
            int col = bx * 128 + colBase + nb * 8 + 2 * tig;
            float b0 = bias[col], b1 = bias[col + 1];
            float2 v0, v1;
            v0.x = acc[ma][nb][0] + b0;
            v0.y = acc[ma][nb][1] + b1;
            v1.x = acc[ma][nb][2] + b0;
            v1.y = acc[ma][nb][3] + b1;
            if (relu) {
                v0.x = fmaxf(v0.x, 0.f); v0.y = fmaxf(v0.y, 0.f);
                v1.x = fmaxf(v1.x, 0.f); v1.y = fmaxf(v1.y, 0.f);
            }
            if (mode == 2) {
                __half* Ch = (__half*)C;
                *(__half2*)(Ch + (size_t)r0 * N + col) = __floats2half2_rn(v0.x, v0.y);
                *(__half2*)(Ch + (size_t)r1 * N + col) = __floats2half2_rn(v1.x, v1.y);
            } else {
                if (mode == 1) {
                    v0.x = rna_tf32(v0.x); v0.y = rna_tf32(v0.y);
                    v1.x = rna_tf32(v1.x); v1.y = rna_tf32(v1.y);
                }
                float* Cf = (float*)C;
                *(float2*)(Cf + (size_t)r0 * N + col) = v0;
                *(float2*)(Cf + (size_t)r1 * N + col) = v1;
            }
        }
    }
}

// ---------------- transpose + fp16 convert weights: in[K,N] -> out[N,K] -----------
__global__ __launch_bounds__(256) void transpose_h(
    const float* __restrict__ in, __half* __restrict__ out, int K, int N)
{
    __shared__ float t[32][33];
    int x = blockIdx.x * 32 + threadIdx.x;
    int y0 = blockIdx.y * 32;
#pragma unroll
    for (int j = 0; j < 32; j += 8)
        t[threadIdx.y + j][threadIdx.x] = in[(size_t)(y0 + threadIdx.y + j) * N + x];
    __syncthreads();
    int xo = blockIdx.y * 32 + threadIdx.x;
    int yo = blockIdx.x * 32;
#pragma unroll
    for (int j = 0; j < 32; j += 8)
        out[(size_t)(yo + threadIdx.y + j) * K + xo] = __float2half_rn(t[threadIdx.x][threadIdx.y + j]);
}

// ---------------- float -> half copy ----------------------------------------------
__global__ __launch_bounds__(256) void half_copy(
    const float* __restrict__ in, __half* __restrict__ out, int n4)
{
    int i = blockIdx.x * blockDim.x + threadIdx.x;
    if (i < n4) {
        float4 v = ((const float4*)in)[i];
        __half2* o = (__half2*)out;
        o[2 * i + 0] = __floats2half2_rn(v.x, v.y);
        o[2 * i + 1] = __floats2half2_rn(v.z, v.w);
    }
}

// ---------------- bias concat for fused QKV ---------------------------------------
__global__ void concat_bias3(const float* __restrict__ b0, const float* __restrict__ b1,
                             const float* __restrict__ b2, float* __restrict__ out)
{
    int i = blockIdx.x * blockDim.x + threadIdx.x;
    if (i < DM) out[i] = b0[i];
    else if (i < 2 * DM) out[i] = b1[i - DM];
    else if (i < 3 * DM) out[i] = b2[i - 2 * DM];
}

// ---------------- Flash attention on tf32 mma.sync (half output) -------------------
#define AQT 128
#define AKT 64
#define AQP 72
#define AKP 72
#define AVP 68
#define A_OFF_K 9216
#define A_OFF_V 18432
#define A_OFF_M 27136
#define ATTN_SMEM ((27136 + 128) * 4)   // 109056 bytes

__device__ __forceinline__ void attn_load_kv(float* sm, const float* Kb, const float* Vb,
                                             const int* mb, int buf, int tid, int rstr) {
    float* Ks = sm + A_OFF_K + buf * (AKT * AKP);
    float* Vs = sm + A_OFF_V + buf * (AKT * AVP);
    int* mk = (int*)(sm + A_OFF_M) + buf * 64;
#pragma unroll
    for (int i = 0; i < 4; i++) {
        int idx = tid + i * 256;
        int r = idx >> 4;
        int c = (idx & 15) * 4;
        cp16(smem_u32(Ks + r * AKP + c), Kb + (size_t)r * rstr + c);
        cp16(smem_u32(Vs + r * AVP + c), Vb + (size_t)r * rstr + c);
    }
    if (tid < 16) cp16(smem_u32(mk + tid * 4), mb + tid * 4);
    cp_commit();
}

__global__ __launch_bounds__(256, 2) void attn_mma(
    const float* __restrict__ Qg, const float* __restrict__ Kg,
    const float* __restrict__ Vg, const int* __restrict__ maskg,
    __half* __restrict__ Og, int rstr)
{
    extern __shared__ float sm[];
    const int tid = threadIdx.x;
    const int warp = tid >> 5;
    const int lane = tid & 31;
    const int g = lane >> 2;
    const int tig = lane & 3;

    const int bh = blockIdx.y;
    const int b = bh >> 4;
    const int h = bh & 15;
    const int qb = blockIdx.x;

    const float* Qbase = Qg + (size_t)(b * SEQ + qb * AQT) * rstr + h * DK;
    const int* maskp = maskg + b * SEQ;

#pragma unroll
    for (int i = 0; i < 8; i++) {
        int idx = tid + i * 256;
        int r = idx >> 4;
        int c = (idx & 15) * 4;
        cp16(smem_u32(sm + r * AQP + c), Qbase + (size_t)r * rstr + c);
    }
    cp_commit();

    attn_load_kv(sm, Kg + (size_t)(b * SEQ) * rstr + h * DK,
                 Vg + (size_t)(b * SEQ) * rstr + h * DK, maskp, 0, tid, rstr);

    float o[8][4];
#pragma unroll
    for (int nt = 0; nt < 8; nt++)
#pragma unroll
        for (int j = 0; j < 4; j++) o[nt][j] = 0.f;
    float m0 = -1e30f, m1 = -1e30f, l0 = 0.f, l1 = 0.f;

    const int qrow0 = warp * 16 + g;

    for (int kb = 0; kb < SEQ / AKT; kb++) {
        cp_wait(0);
        __syncthreads();
        if (kb + 1 < SEQ / AKT) {
            const float* Kb = Kg + (size_t)(b * SEQ + (kb + 1) * AKT) * rstr + h * DK;
            const float* Vb = Vg + (size_t)(b * SEQ + (kb + 1) * AKT) * rstr + h * DK;
            attn_load_kv(sm, Kb, Vb, maskp + (kb + 1) * AKT, (kb + 1) & 1, tid, rstr);
        }

        const float* Ks = sm + A_OFF_K + (kb & 1) * (AKT * AKP);
        const float* Vs = sm + A_OFF_V + (kb & 1) * (AKT * AVP);
        const int* mk = (const int*)(sm + A_OFF_M) + (kb & 1) * 64;

        float s[8][4];
#pragma unroll
        for (int nt = 0; nt < 8; nt++)
#pragma unroll
            for (int j = 0; j < 4; j++) s[nt][j] = 0.f;

#pragma unroll
        for (int ks = 0; ks < 8; ks++) {
            float2 q0 = *(const float2*)(sm + qrow0 * AQP + ks * 8 + 2 * tig);
            float2 q1 = *(const float2*)(sm + (qrow0 + 8) * AQP + ks * 8 + 2 * tig);
#pragma unroll
            for (int nt = 0; nt < 8; nt++) {
                float2 kk = *(const float2*)(Ks + (nt * 8 + g) * AKP + ks * 8 + 2 * tig);
                mma_tf32(s[nt], fi(q0.x), fi(q1.x), fi(q0.y), fi(q1.y),
                         fi(kk.x), fi(kk.y));
            }
        }

        float mx0 = -1e30f, mx1 = -1e30f;
#pragma unroll
        for (int nt = 0; nt < 8; nt++) {
            int c0 = nt * 8 + 2 * tig;
            int mk0v = mk[c0];
            int mk1v = mk[c0 + 1];
            float v0 = s[nt][0] * 0.125f; if (mk0v == 0) v0 = -1e30f;
            float v1 = s[nt][1] * 0.125f; if (mk1v == 0) v1 = -1e30f;
            float v2 = s[nt][2] * 0.125f; if (mk0v == 0) v2 = -1e30f;
            float v3 = s[nt][3] * 0.125f; if (mk1v == 0) v3 = -1e30f;
            s[nt][0] = v0; s[nt][1] = v1; s[nt][2] = v2; s[nt][3] = v3;
            mx0 = fmaxf(mx0, fmaxf(v0, v1));
            mx1 = fmaxf(mx1, fmaxf(v2, v3));
        }
        mx0 = fmaxf(mx0, __shfl_xor_sync(0xffffffffu, mx0, 1));
        mx0 = fmaxf(mx0, __shfl_xor_sync(0xffffffffu, mx0, 2));
        mx1 = fmaxf(mx1, __shfl_xor_sync(0xffffffffu, mx1, 1));
        mx1 = fmaxf(mx1, __shfl_xor_sync(0xffffffffu, mx1, 2));

        float mn0 = fmaxf(m0, mx0);
        float mn1 = fmaxf(m1, mx1);
        float corr0 = __expf(m0 - mn0);
        float corr1 = __expf(m1 - mn1);
        m0 = mn0; m1 = mn1;

        float ps0 = 0.f, ps1 = 0.f;
#pragma unroll
        for (int nt = 0; nt < 8; nt++) {
            float p0 = __expf(s[nt][0] - mn0);
            float p1 = __expf(s[nt][1] - mn0);
            float p2 = __expf(s[nt][2] - mn1);
            float p3 = __expf(s[nt][3] - mn1);
            ps0 += p0 + p1;
            ps1 += p2 + p3;
            s[nt][0] = rna_tf32(p0); s[nt][1] = rna_tf32(p1);
            s[nt][2] = rna_tf32(p2); s[nt][3] = rna_tf32(p3);
        }
        ps0 += __shfl_xor_sync(0xffffffffu, ps0, 1);
        ps0 += __shfl_xor_sync(0xffffffffu, ps0, 2);
        ps1 += __shfl_xor_sync(0xffffffffu, ps1, 1);
        ps1 += __shfl_xor_sync(0xffffffffu, ps1, 2);
        l0 = l0 * corr0 + ps0;
        l1 = l1 * corr1 + ps1;

#pragma unroll
        for (int nt = 0; nt < 8; nt++) {
            o[nt][0] *= corr0; o[nt][1] *= corr0;
            o[nt][2] *= corr1; o[nt][3] *= corr1;
        }

#pragma unroll
        for (int ks = 0; ks < 8; ks++) {
            uint32_t a0 = fi(s[ks][0]);
            uint32_t a1 = fi(s[ks][2]);
            uint32_t a2 = fi(s[ks][1]);
            uint32_t a3 = fi(s[ks][3]);
            const float* vr0 = Vs + (ks * 8 + 2 * tig) * AVP;
            const float* vr1 = vr0 + AVP;
#pragma unroll
            for (int nt = 0; nt < 8; nt++) {
                int d = nt * 8 + g;
                mma_tf32(o[nt], a0, a1, a2, a3, fi(vr0[d]), fi(vr1[d]));
            }
        }
    }

    float inv0 = 1.f / l0;
    float inv1 = 1.f / l1;
    int grow = b * SEQ + qb * AQT + qrow0;
#pragma unroll
    for (int nt = 0; nt < 8; nt++) {
        int col = h * DK + nt * 8 + 2 * tig;
        *(__half2*)(Og + (size_t)grow * DM + col) =
            __floats2half2_rn(o[nt][0] * inv0, o[nt][1] * inv0);
        *(__half2*)(Og + (size_t)(grow + 8) * DM + col) =
            __floats2half2_rn(o[nt][2] * inv1, o[nt][3] * inv1);
    }
}

// ---------------- fused residual + LayerNorm (+optional half copy) ----------------
__global__ __launch_bounds__(256) void ln_residual(
    const float* __restrict__ X, const float* __restrict__ R,
    const float* __restrict__ gamma, const float* __restrict__ beta,
    float* __restrict__ out, __half* __restrict__ outh)
{
    const int row = blockIdx.x;
    const int tid = threadIdx.x;
    const float* x = X + (size_t)row * DM;
    const float* r = R + (size_t)row * DM;

    float vals[4];
    float sum = 0.f, sumsq = 0.f;
#pragma unroll
    for (int i = 0; i < 4; i++) {
        float v = x[tid + i * 256] + r[tid + i * 256];
        vals[i] = v;
        sum += v;
        sumsq += v * v;
    }

    __shared__ float2 wred[8];
    __shared__ float2 fin;
    float2 agg = make_float2(sum, sumsq);
#pragma unroll
    for (int off = 16; off > 0; off >>= 1) {
        agg.x += __shfl_xor_sync(0xffffffffu, agg.x, off);
        agg.y += __shfl_xor_sync(0xffffffffu, agg.y, off);
    }
    const int warp = tid >> 5, lane = tid & 31;
    if (lane == 0) wred[warp] = agg;
    __syncthreads();
    if (warp == 0) {
        float2 a = (lane < 8) ? wred[lane] : make_float2(0.f, 0.f);
#pragma unroll
        for (int off = 4; off > 0; off >>= 1) {
            a.x += __shfl_xor_sync(0xffffffffu, a.x, off);
            a.y += __shfl_xor_sync(0xffffffffu, a.y, off);
        }
        if (lane == 0) fin = a;
    }
    __syncthreads();

    float mu = fin.x * (1.f / DM);
    float var = fin.y * (1.f / DM) - mu * mu;
    float rstd = rsqrtf(var + LN_EPS);

    float* o = out + (size_t)row * DM;
    __half* oh = outh ? outh + (size_t)row * DM : nullptr;
#pragma unroll
    for (int i = 0; i < 4; i++) {
        int c = tid + i * 256;
        float y = (vals[i] - mu) * rstd * gamma[c] + beta[c];
        o[c] = y;
        if (oh) oh[c] = __float2half_rn(y);
    }
}

// ---------------- launch ----------------------------------------------------------
extern "C" void kernel_launch(void* const* d_in, const int* in_sizes, int n_in,
                              void* d_out, int out_size)
{
    const float* x    = (const float*)d_in[0];
    const int*   mask = (const int*)  d_in[1];
    const float* w_q  = (const float*)d_in[2];
    const float* b_q  = (const float*)d_in[3];
    const float* w_k  = (const float*)d_in[4];
    const float* b_k  = (const float*)d_in[5];
    const float* w_v  = (const float*)d_in[6];
    const float* b_v  = (const float*)d_in[7];
    const float* w_o  = (const float*)d_in[8];
    const float* b_o  = (const float*)d_in[9];
    const float* w1   = (const float*)d_in[10];
    const float* b1   = (const float*)d_in[11];
    const float* w2   = (const float*)d_in[12];
    const float* b2   = (const float*)d_in[13];
    const float* g1   = (const float*)d_in[14];
    const float* be1  = (const float*)d_in[15];
    const float* g2   = (const float*)d_in[16];
    const float* be2  = (const float*)d_in[17];
    float* out = (float*)d_out;

    float *pqkv, *pattn, *ph, *pff2, *pbqkv;
    __half *pxh, *pctxh, *phh, *pff1h, *pwqkvh, *pwtoh, *pwt1h, *pwt2h;
    cudaGetSymbolAddress((void**)&pqkv,   g_qkv);
    cudaGetSymbolAddress((void**)&pattn,  g_attn);
    cudaGetSymbolAddress((void**)&ph,     g_h);
    cudaGetSymbolAddress((void**)&pff2,   g_ff2);
    cudaGetSymbolAddress((void**)&pbqkv,  g_bqkv);
    cudaGetSymbolAddress((void**)&pxh,    g_xh);
    cudaGetSymbolAddress((void**)&pctxh,  g_ctxh);
    cudaGetSymbolAddress((void**)&phh,    g_hh);
    cudaGetSymbolAddress((void**)&pff1h,  g_ff1h);
    cudaGetSymbolAddress((void**)&pwqkvh, g_wqkvh);
    cudaGetSymbolAddress((void**)&pwtoh,  g_wtoh);
    cudaGetSymbolAddress((void**)&pwt1h,  g_wt1h);
    cudaGetSymbolAddress((void**)&pwt2h,  g_wt2h);

    cudaFuncSetAttribute(gemm_f16, cudaFuncAttributeMaxDynamicSharedMemorySize, GEMM_SMEM);
    cudaFuncSetAttribute(attn_mma, cudaFuncAttributeMaxDynamicSharedMemorySize, ATTN_SMEM);

    dim3 gQKV(3 * DM / 128, MROWS / 128);  // (24, 64)
    dim3 gD(DM / 128, MROWS / 128);        // (8, 64)
    dim3 gF1(DFF / 128, MROWS / 128);      // (32, 64)

    // prep
    transpose_h<<<dim3(DM / 32, DM / 32), dim3(32, 8)>>>(w_q, pwqkvh, DM, DM);
    transpose_h<<<dim3(DM / 32, DM / 32), dim3(32, 8)>>>(w_k, pwqkvh + DM * DM, DM, DM);
    transpose_h<<<dim3(DM / 32, DM / 32), dim3(32, 8)>>>(w_v, pwqkvh + 2 * DM * DM, DM, DM);
    concat_bias3<<<12, 256>>>(b_q, b_k, b_v, pbqkv);
    half_copy<<<(MROWS * DM / 4 + 255) / 256, 256>>>(x, pxh, MROWS * DM / 4);

    // fused QKV projection (fp16 mma; float+tf32-rounded out for tf32 attention)
    gemm_f16<<<gQKV, 256, GEMM_SMEM>>>(pxh, pwqkvh, pbqkv, pqkv, MROWS, 3 * DM, DM, 0, 1);

    // remaining weight transposes
    transpose_h<<<dim3(DM / 32, DM / 32), dim3(32, 8)>>>(w_o, pwtoh, DM, DM);
    transpose_h<<<dim3(DFF / 32, DM / 32), dim3(32, 8)>>>(w1, pwt1h, DM, DFF);
    transpose_h<<<dim3(DM / 32, DFF / 32), dim3(32, 8)>>>(w2, pwt2h, DFF, DM);

    // flash attention (tf32 mma), half output for O-projection
    attn_mma<<<dim3(SEQ / AQT, BATCH * NH), 256, ATTN_SMEM>>>(
        pqkv, pqkv + DM, pqkv + 2 * DM, mask, pctxh, 3 * DM);

    // output projection (fp16)
    gemm_f16<<<gD, 256, GEMM_SMEM>>>(pctxh, pwtoh, b_o, pattn, MROWS, DM, DM, 0, 0);

    // LN1: h = LN(x + attn_out); hh = half copy
    ln_residual<<<MROWS, 256>>>(x, pattn, g1, be1, ph, phh);

    // FFN (fp16; ff1 stored half directly)
    gemm_f16<<<gF1, 256, GEMM_SMEM>>>(phh, pwt1h, b1, pff1h, MROWS, DFF, DM, 1, 2);
    gemm_f16<<<gD, 256, GEMM_SMEM>>>(pff1h, pwt2h, b2, pff2, MROWS, DM, DFF, 0, 0);

    // LN2: out = LN(h + ff)
    ln_residual<<<MROWS, 256>>>(ph, pff2, g2, be2, out, nullptr);
}

// round 10
// speedup vs baseline: 8.4461x; 1.1688x over previous
#include <cuda_runtime.h>
#include <cuda_fp16.h>
#include <math.h>
#include <stdint.h>

// Problem constants
#define BATCH 4
#define SEQ   2048
#define DM    1024
#define NH    16
#define DK    64
#define DFF   4096
#define MROWS (BATCH * SEQ)   // 8192
#define LN_EPS 1e-5f

// ---------------- scratch (device globals; no allocation allowed) ----------------
__device__ __half g_qkvh[(size_t)MROWS * 3 * DM];  // fused QKV (half) for attention
__device__ __half g_xh[MROWS * DM];
__device__ __half g_ctxh[MROWS * DM];
__device__ float  g_attn[MROWS * DM];
__device__ float  g_h[MROWS * DM];
__device__ __half g_hh[MROWS * DM];
__device__ __half g_ff1h[(size_t)MROWS * DFF];
__device__ float  g_ff2[MROWS * DM];
// transposed (+fp16) weights: [N,K] layout
__device__ __half g_wqkvh[(size_t)3 * DM * DM];
__device__ float  g_bqkv[3 * DM];
__device__ __half g_wtoh[DM * DM];
__device__ __half g_wt1h[(size_t)DFF * DM];
__device__ __half g_wt2h[(size_t)DM * DFF];

// ---------------- small helpers ---------------------------------------------------
__device__ __forceinline__ float rna_tf32(float v) {
    uint32_t u;
    asm("cvt.rna.tf32.f32 %0, %1;" : "=r"(u) : "f"(v));
    return __uint_as_float(u);
}

__device__ __forceinline__ uint32_t smem_u32(const void* p) {
    uint32_t a;
    asm("{ .reg .u64 t; cvta.to.shared.u64 t, %1; cvt.u32.u64 %0, t; }" : "=r"(a) : "l"(p));
    return a;
}

__device__ __forceinline__ void cp16(uint32_t dst, const void* src) {
    asm volatile("cp.async.cg.shared.global [%0], [%1], 16;" :: "r"(dst), "l"(src) : "memory");
}

__device__ __forceinline__ void cp_commit() {
    asm volatile("cp.async.commit_group;" ::: "memory");
}

__device__ __forceinline__ void cp_wait(int pend) {
    if (pend == 0) asm volatile("cp.async.wait_group 0;" ::: "memory");
    else           asm volatile("cp.async.wait_group 1;" ::: "memory");
}

__device__ __forceinline__ void mma_f16(float* c, uint32_t a0, uint32_t a1,
                                        uint32_t a2, uint32_t a3,
                                        uint32_t b0, uint32_t b1) {
    asm volatile(
        "mma.sync.aligned.m16n8k16.row.col.f32.f16.f16.f32 "
        "{%0,%1,%2,%3}, {%4,%5,%6,%7}, {%8,%9}, {%0,%1,%2,%3};"
        : "+f"(c[0]), "+f"(c[1]), "+f"(c[2]), "+f"(c[3])
        : "r"(a0), "r"(a1), "r"(a2), "r"(a3), "r"(b0), "r"(b1));
}

__device__ __forceinline__ void ldsm4(uint32_t& r0, uint32_t& r1, uint32_t& r2,
                                      uint32_t& r3, uint32_t addr) {
    asm volatile("ldmatrix.sync.aligned.m8n8.x4.shared.b16 {%0,%1,%2,%3}, [%4];"
                 : "=r"(r0), "=r"(r1), "=r"(r2), "=r"(r3) : "r"(addr));
}

__device__ __forceinline__ void ldsm4t(uint32_t& r0, uint32_t& r1, uint32_t& r2,
                                       uint32_t& r3, uint32_t addr) {
    asm volatile("ldmatrix.sync.aligned.m8n8.x4.trans.shared.b16 {%0,%1,%2,%3}, [%4];"
                 : "=r"(r0), "=r"(r1), "=r"(r2), "=r"(r3) : "r"(addr));
}

__device__ __forceinline__ uint32_t fh2(float a, float b) {
    __half2 h = __floats2half2_rn(a, b);
    return *(uint32_t*)&h;
}

// ---------------- fp16 mma.sync GEMM (unchanged, known-good) -----------------------
#define HBK 64
#define HST 72
#define HTILE (128 * HST)
#define HSTAGE (2 * HTILE)
#define HNST 3
#define GEMM_SMEM (HNST * HSTAGE * 2)   // 110592 bytes

__device__ __forceinline__ void h_load_stage(__half* smem, const __half* Ablk,
                                             const __half* Bblk, int K, int s, int tid) {
    __half* As = smem + (s % HNST) * HSTAGE;
    __half* Bs = As + HTILE;
    const int k0 = s * HBK;
    const int row = tid >> 1;
    const int c0 = (tid & 1) * 4;
#pragma unroll
    for (int i = 0; i < 4; i++) {
        int c = c0 + i;
        cp16(smem_u32(As + row * HST + c * 8), Ablk + (size_t)row * K + k0 + c * 8);
        cp16(smem_u32(Bs + row * HST + c * 8), Bblk + (size_t)row * K + k0 + c * 8);
    }
    cp_commit();
}

__global__ __launch_bounds__(256, 2) void gemm_f16(
    const __half* __restrict__ A, const __half* __restrict__ B,
    const float* __restrict__ bias, void* __restrict__ C,
    int M, int N, int K, int relu, int mode)
{
    extern __shared__ __half hsm[];

    const int tid = threadIdx.x;
    const int wid = tid >> 5;
    const int lane = tid & 31;
    const int g = lane >> 2;
    const int tig = lane & 3;
    const int lr = lane & 7;
    const int sub = lane >> 3;

    const int rowBase = (wid & 3) * 32;
    const int colBase = (wid >> 2) * 64;

    int a_row[2], b_row[4];
#pragma unroll
    for (int ma = 0; ma < 2; ma++)
        a_row[ma] = rowBase + ma * 16 + ((sub & 1) << 3) + lr;
    const int a_koff = (sub >> 1) << 3;
#pragma unroll
    for (int nbp = 0; nbp < 4; nbp++)
        b_row[nbp] = colBase + nbp * 16 + ((sub >> 1) << 3) + lr;
    const int b_koff = (sub & 1) << 3;

    const int bx = blockIdx.x, by = blockIdx.y;
    const __half* Ablk = A + (size_t)by * 128 * K;
    const __half* Bblk = B + (size_t)bx * 128 * K;
    const int nstages = K / HBK;

    float acc[2][8][4];
#pragma unroll
    for (int i = 0; i < 2; i++)
#pragma unroll
        for (int j = 0; j < 8; j++)
#pragma unroll
            for (int q = 0; q < 4; q++) acc[i][j][q] = 0.f;

    h_load_stage(hsm, Ablk, Bblk, K, 0, tid);
    h_load_stage(hsm, Ablk, Bblk, K, 1, tid);

    for (int s = 0; s < nstages; s++) {
        cp_wait((s + 1 < nstages) ? 1 : 0);
        __syncthreads();
        if (s + 2 < nstages) h_load_stage(hsm, Ablk, Bblk, K, s + 2, tid);

        const __half* As = hsm + (s % HNST) * HSTAGE;
        const __half* Bs = As + HTILE;
        const uint32_t abase = smem_u32(As);
        const uint32_t bbase = smem_u32(Bs);

#pragma unroll
        for (int ks = 0; ks < 4; ks++) {
            const int k0 = ks * 16;
            uint32_t a[2][4];
#pragma unroll
            for (int ma = 0; ma < 2; ma++)
                ldsm4(a[ma][0], a[ma][1], a[ma][2], a[ma][3],
                      abase + (uint32_t)(a_row[ma] * HST + k0 + a_koff) * 2u);
            uint32_t bb[4][4];
#pragma unroll
            for (int nbp = 0; nbp < 4; nbp++)
                ldsm4(bb[nbp][0], bb[nbp][1], bb[nbp][2], bb[nbp][3],
                      bbase + (uint32_t)(b_row[nbp] * HST + k0 + b_koff) * 2u);
#pragma unroll
            for (int ma = 0; ma < 2; ma++)
#pragma unroll
                for (int nb = 0; nb < 8; nb++)
                    mma_f16(acc[ma][nb], a[ma][0], a[ma][1], a[ma][2], a[ma][3],
                            bb[nb >> 1][(nb & 1) * 2], bb[nb >> 1][(nb & 1) * 2 + 1]);
        }
    }

#pragma unroll
    for (int ma = 0; ma < 2; ma++) {
        int r0 = by * 128 + rowBase + ma * 16 + g;
        int r1 = r0 + 8;
#pragma unroll
        for (int nb = 0; nb < 8; nb++) {
            int col = bx * 128 + colBase + nb * 8 + 2 * tig;
            float b0 = bias[col], b1 = bias[col + 1];
            float2 v0, v1;
            v0.x = acc[ma][nb][0] + b0;
            v0.y = acc[ma][nb][1] + b1;
            v1.x = acc[ma][nb][2] + b0;
            v1.y = acc[ma][nb][3] + b1;
            if (relu) {
                v0.x = fmaxf(v0.x, 0.f); v0.y = fmaxf(v0.y, 0.f);
                v1.x = fmaxf(v1.x, 0.f); v1.y = fmaxf(v1.y, 0.f);
            }
            if (mode == 2) {
                __half* Ch = (__half*)C;
                *(__half2*)(Ch + (size_t)r0 * N + col) = __floats2half2_rn(v0.x, v0.y);
                *(__half2*)(Ch + (size_t)r1 * N + col) = __floats2half2_rn(v1.x, v1.y);
            } else {
                if (mode == 1) {
                    v0.x = rna_tf32(v0.x); v0.y = rna_tf32(v0.y);
                    v1.x = rna_tf32(v1.x); v1.y = rna_tf32(v1.y);
                }
                float* Cf = (float*)C;
                *(float2*)(Cf + (size_t)r0 * N + col) = v0;
                *(float2*)(Cf + (size_t)r1 * N + col) = v1;
            }
        }
    }
}

// ---------------- transpose + fp16 convert weights: in[K,N] -> out[N,K] -----------
__global__ __launch_bounds__(256) void transpose_h(
    const float* __restrict__ in, __half* __restrict__ out, int K, int N)
{
    __shared__ float t[32][33];
    int x = blockIdx.x * 32 + threadIdx.x;
    int y0 = blockIdx.y * 32;
#pragma unroll
    for (int j = 0; j < 32; j += 8)
        t[threadIdx.y + j][threadIdx.x] = in[(size_t)(y0 + threadIdx.y + j) * N + x];
    __syncthreads();
    int xo = blockIdx.y * 32 + threadIdx.x;
    int yo = blockIdx.x * 32;
#pragma unroll
    for (int j = 0; j < 32; j += 8)
        out[(size_t)(yo + threadIdx.y + j) * K + xo] = __float2half_rn(t[threadIdx.x][threadIdx.y + j]);
}

// ---------------- float -> half copy ----------------------------------------------
__global__ __launch_bounds__(256) void half_copy(
    const float* __restrict__ in, __half* __restrict__ out, int n4)
{
    int i = blockIdx.x * blockDim.x + threadIdx.x;
    if (i < n4) {
        float4 v = ((const float4*)in)[i];
        __half2* o = (__half2*)out;
        o[2 * i + 0] = __floats2half2_rn(v.x, v.y);
        o[2 * i + 1] = __floats2half2_rn(v.z, v.w);
    }
}

// ---------------- bias concat for fused QKV ---------------------------------------
__global__ void concat_bias3(const float* __restrict__ b0, const float* __restrict__ b1,
                             const float* __restrict__ b2, float* __restrict__ out)
{
    int i = blockIdx.x * blockDim.x + threadIdx.x;
    if (i < DM) out[i] = b0[i];
    else if (i < 2 * DM) out[i] = b1[i - DM];
    else if (i < 3 * DM) out[i] = b2[i - 2 * DM];
}

// ---------------- Flash attention, fully fp16 mma.sync ----------------------------
// CTA: 128 queries (8 warps x m16), 64-key blocks (double-buffered), dk=64.
// Q/K/V are __half in the fused qkv buffer (row stride rstr halves).
// Q a-frags hoisted out of the key loop; K via ldmatrix.x4; V via ldmatrix.x4.trans.
// All smem rows stride 72 halves (144B) -> every ldmatrix phase conflict-free.
#define AQT 128
#define AKT 64
#define NKB (SEQ / AKT)
#define APH 72
// half offsets: Q[128*72]=9216 | K 2x[64*72]=9216 | V 2x[64*72]=9216 | mask
#define AH_K 9216
#define AH_V 18432
#define AB_M 55296                      // byte offset of mask area
#define ATTN_SMEM (AB_M + 2 * 64 * 4)   // 55808 bytes

__device__ __forceinline__ void attn_load_kv(char* smb, const __half* Kb, const __half* Vb,
                                             const int* mb, int buf, int tid, int rstr) {
    __half* Ks = (__half*)smb + AH_K + buf * (AKT * APH);
    __half* Vs = (__half*)smb + AH_V + buf * (AKT * APH);
    int* mk = (int*)(smb + AB_M) + buf * 64;
#pragma unroll
    for (int i = 0; i < 2; i++) {
        int idx = tid + i * 256;
        int r = idx >> 3;
        int c = idx & 7;
        cp16(smem_u32(Ks + r * APH + c * 8), Kb + (size_t)r * rstr + c * 8);
        cp16(smem_u32(Vs + r * APH + c * 8), Vb + (size_t)r * rstr + c * 8);
    }
    if (tid < 16) cp16(smem_u32(mk + tid * 4), mb + tid * 4);
    cp_commit();
}

__global__ __launch_bounds__(256, 2) void attn_mma(
    const __half* __restrict__ Qg, const __half* __restrict__ Kg,
    const __half* __restrict__ Vg, const int* __restrict__ maskg,
    __half* __restrict__ Og, int rstr)
{
    extern __shared__ char asmb[];
    const int tid = threadIdx.x;
    const int warp = tid >> 5;
    const int lane = tid & 31;
    const int g = lane >> 2;
    const int tig = lane & 3;
    const int lr = lane & 7;
    const int sub = lane >> 3;

    const int bh = blockIdx.y;
    const int b = bh >> 4;
    const int h = bh & 15;
    const int qb = blockIdx.x;

    const __half* Qbase = Qg + (size_t)(b * SEQ + qb * AQT) * rstr + h * DK;
    const int* maskp = maskg + b * SEQ;

    // Q tile load: 128 rows x 64 halves = 1024 16B chunks
    {
        __half* Qs = (__half*)asmb;
#pragma unroll
        for (int i = 0; i < 4; i++) {
            int idx = tid + i * 256;
            int r = idx >> 3;
            int c = idx & 7;
            cp16(smem_u32(Qs + r * APH + c * 8), Qbase + (size_t)r * rstr + c * 8);
        }
        cp_commit();
    }
    attn_load_kv(asmb, Kg + (size_t)(b * SEQ) * rstr + h * DK,
                 Vg + (size_t)(b * SEQ) * rstr + h * DK, maskp, 0, tid, rstr);

    // ldmatrix lane-address components
    const int a_ro = warp * 16 + ((sub & 1) << 3) + lr;   // Q row
    const int a_ko = (sub >> 1) << 3;
    const int b_ro = ((sub >> 1) << 3) + lr;              // K row within 16-blk
    const int b_ko = (sub & 1) << 3;
    const int v_ro = ((sub & 1) << 3) + lr;               // V key within 16-blk
    const int v_co = (sub >> 1) << 3;

    // wait for Q (kv0 may still be in flight), preload Q a-frags
    cp_wait(1);
    __syncthreads();
    uint32_t qa[4][4];
    {
        uint32_t qbse = smem_u32(asmb);
#pragma unroll
        for (int ks = 0; ks < 4; ks++)
            ldsm4(qa[ks][0], qa[ks][1], qa[ks][2], qa[ks][3],
                  qbse + (uint32_t)(a_ro * APH + ks * 16 + a_ko) * 2u);
    }

    float o[8][4];
#pragma unroll
    for (int nt = 0; nt < 8; nt++)
#pragma unroll
        for (int j = 0; j < 4; j++) o[nt][j] = 0.f;
    float m0 = -1e30f, m1 = -1e30f, l0 = 0.f, l1 = 0.f;

    for (int kb = 0; kb < NKB; kb++) {
        cp_wait(0);
        __syncthreads();
        if (kb + 1 < NKB) {
            const __half* Kb = Kg + (size_t)(b * SEQ + (kb + 1) * AKT) * rstr + h * DK;
            const __half* Vb = Vg + (size_t)(b * SEQ + (kb + 1) * AKT) * rstr + h * DK;
            attn_load_kv(asmb, Kb, Vb, maskp + (kb + 1) * AKT, (kb + 1) & 1, tid, rstr);
        }

        const uint32_t kbse = smem_u32((__half*)asmb + AH_K + (kb & 1) * (AKT * APH));
        const uint32_t vbse = smem_u32((__half*)asmb + AH_V + (kb & 1) * (AKT * APH));
        const int* mk = (const int*)(asmb + AB_M) + (kb & 1) * 64;

        // ---- S = Q @ K^T ----
        float s[8][4];
#pragma unroll
        for (int nt = 0; nt < 8; nt++)
#pragma unroll
            for (int j = 0; j < 4; j++) s[nt][j] = 0.f;

#pragma unroll
        for (int ks = 0; ks < 4; ks++) {
            uint32_t kf[4][4];
#pragma unroll
            for (int ntp = 0; ntp < 4; ntp++)
                ldsm4(kf[ntp][0], kf[ntp][1], kf[ntp][2], kf[ntp][3],
                      kbse + (uint32_t)((ntp * 16 + b_ro) * APH + ks * 16 + b_ko) * 2u);
#pragma unroll
            for (int nt = 0; nt < 8; nt++)
                mma_f16(s[nt], qa[ks][0], qa[ks][1], qa[ks][2], qa[ks][3],
                        kf[nt >> 1][(nt & 1) * 2], kf[nt >> 1][(nt & 1) * 2 + 1]);
        }

        // ---- mask + scale + online softmax ----
        float mx0 = -1e30f, mx1 = -1e30f;
#pragma unroll
        for (int nt = 0; nt < 8; nt++) {
            int c0 = nt * 8 + 2 * tig;
            int mk0v = mk[c0];
            int mk1v = mk[c0 + 1];
            float v0 = s[nt][0] * 0.125f; if (mk0v == 0) v0 = -1e30f;
            float v1 = s[nt][1] * 0.125f; if (mk1v == 0) v1 = -1e30f;
            float v2 = s[nt][2] * 0.125f; if (mk0v == 0) v2 = -1e30f;
            float v3 = s[nt][3] * 0.125f; if (mk1v == 0) v3 = -1e30f;
            s[nt][0] = v0; s[nt][1] = v1; s[nt][2] = v2; s[nt][3] = v3;
            mx0 = fmaxf(mx0, fmaxf(v0, v1));
            mx1 = fmaxf(mx1, fmaxf(v2, v3));
        }
        mx0 = fmaxf(mx0, __shfl_xor_sync(0xffffffffu, mx0, 1));
        mx0 = fmaxf(mx0, __shfl_xor_sync(0xffffffffu, mx0, 2));
        mx1 = fmaxf(mx1, __shfl_xor_sync(0xffffffffu, mx1, 1));
        mx1 = fmaxf(mx1, __shfl_xor_sync(0xffffffffu, mx1, 2));

        float mn0 = fmaxf(m0, mx0);
        float mn1 = fmaxf(m1, mx1);
        float corr0 = __expf(m0 - mn0);
        float corr1 = __expf(m1 - mn1);
        m0 = mn0; m1 = mn1;

        float ps0 = 0.f, ps1 = 0.f;
#pragma unroll
        for (int nt = 0; nt < 8; nt++) {
            float p0 = __expf(s[nt][0] - mn0);
            float p1 = __expf(s[nt][1] - mn0);
            float p2 = __expf(s[nt][2] - mn1);
            float p3 = __expf(s[nt][3] - mn1);
            ps0 += p0 + p1;
            ps1 += p2 + p3;
            s[nt][0] = p0; s[nt][1] = p1; s[nt][2] = p2; s[nt][3] = p3;
        }
        ps0 += __shfl_xor_sync(0xffffffffu, ps0, 1);
        ps0 += __shfl_xor_sync(0xffffffffu, ps0, 2);
        ps1 += __shfl_xor_sync(0xffffffffu, ps1, 1);
        ps1 += __shfl_xor_sync(0xffffffffu, ps1, 2);
        l0 = l0 * corr0 + ps0;
        l1 = l1 * corr1 + ps1;

#pragma unroll
        for (int nt = 0; nt < 8; nt++) {
            o[nt][0] *= corr0; o[nt][1] *= corr0;
            o[nt][2] *= corr1; o[nt][3] *= corr1;
        }

        // ---- O += P @ V (P packed from S accums; V via ldmatrix.trans) ----
#pragma unroll
        for (int ks = 0; ks < 4; ks++) {
            uint32_t pa0 = fh2(s[2 * ks][0],     s[2 * ks][1]);
            uint32_t pa1 = fh2(s[2 * ks][2],     s[2 * ks][3]);
            uint32_t pa2 = fh2(s[2 * ks + 1][0], s[2 * ks + 1][1]);
            uint32_t pa3 = fh2(s[2 * ks + 1][2], s[2 * ks + 1][3]);
#pragma unroll
            for (int dp = 0; dp < 4; dp++) {
                uint32_t vf[4];
                ldsm4t(vf[0], vf[1], vf[2], vf[3],
                       vbse + (uint32_t)((ks * 16 + v_ro) * APH + dp * 16 + v_co) * 2u);
                mma_f16(o[2 * dp],     pa0, pa1, pa2, pa3, vf[0], vf[1]);
                mma_f16(o[2 * dp + 1], pa0, pa1, pa2, pa3, vf[2], vf[3]);
            }
        }
    }

    // ---- epilogue: normalize + half store ----
    float inv0 = 1.f / l0;
    float inv1 = 1.f / l1;
    int grow = b * SEQ + qb * AQT + warp * 16 + g;
#pragma unroll
    for (int nt = 0; nt < 8; nt++) {
        int col = h * DK + nt * 8 + 2 * tig;
        *(__half2*)(Og + (size_t)grow * DM + col) =
            __floats2half2_rn(o[nt][0] * inv0, o[nt][1] * inv0);
        *(__half2*)(Og + (size_t)(grow + 8) * DM + col) =
            __floats2half2_rn(o[nt][2] * inv1, o[nt][3] * inv1);
    }
}

// ---------------- fused residual + LayerNorm (+optional half copy) ----------------
__global__ __launch_bounds__(256) void ln_residual(
    const float* __restrict__ X, const float* __restrict__ R,
    const float* __restrict__ gamma, const float* __restrict__ beta,
    float* __restrict__ out, __half* __restrict__ outh)
{
    const int row = blockIdx.x;
    const int tid = threadIdx.x;
    const float* x = X + (size_t)row * DM;
    const float* r = R + (size_t)row * DM;

    float vals[4];
    float sum = 0.f, sumsq = 0.f;
#pragma unroll
    for (int i = 0; i < 4; i++) {
        float v = x[tid + i * 256] + r[tid + i * 256];
        vals[i] = v;
        sum += v;
        sumsq += v * v;
    }

    __shared__ float2 wred[8];
    __shared__ float2 fin;
    float2 agg = make_float2(sum, sumsq);
#pragma unroll
    for (int off = 16; off > 0; off >>= 1) {
        agg.x += __shfl_xor_sync(0xffffffffu, agg.x, off);
        agg.y += __shfl_xor_sync(0xffffffffu, agg.y, off);
    }
    const int warp = tid >> 5, lane = tid & 31;
    if (lane == 0) wred[warp] = agg;
    __syncthreads();
    if (warp == 0) {
        float2 a = (lane < 8) ? wred[lane] : make_float2(0.f, 0.f);
#pragma unroll
        for (int off = 4; off > 0; off >>= 1) {
            a.x += __shfl_xor_sync(0xffffffffu, a.x, off);
            a.y += __shfl_xor_sync(0xffffffffu, a.y, off);
        }
        if (lane == 0) fin = a;
    }
    __syncthreads();

    float mu = fin.x * (1.f / DM);
    float var = fin.y * (1.f / DM) - mu * mu;
    float rstd = rsqrtf(var + LN_EPS);

    float* o = out + (size_t)row * DM;
    __half* oh = outh ? outh + (size_t)row * DM : nullptr;
#pragma unroll
    for (int i = 0; i < 4; i++) {
        int c = tid + i * 256;
        float y = (vals[i] - mu) * rstd * gamma[c] + beta[c];
        o[c] = y;
        if (oh) oh[c] = __float2half_rn(y);
    }
}

// ---------------- launch ----------------------------------------------------------
extern "C" void kernel_launch(void* const* d_in, const int* in_sizes, int n_in,
                              void* d_out, int out_size)
{
    const float* x    = (const float*)d_in[0];
    const int*   mask = (const int*)  d_in[1];
    const float* w_q  = (const float*)d_in[2];
    const float* b_q  = (const float*)d_in[3];
    const float* w_k  = (const float*)d_in[4];
    const float* b_k  = (const float*)d_in[5];
    const float* w_v  = (const float*)d_in[6];
    const float* b_v  = (const float*)d_in[7];
    const float* w_o  = (const float*)d_in[8];
    const float* b_o  = (const float*)d_in[9];
    const float* w1   = (const float*)d_in[10];
    const float* b1   = (const float*)d_in[11];
    const float* w2   = (const float*)d_in[12];
    const float* b2   = (const float*)d_in[13];
    const float* g1   = (const float*)d_in[14];
    const float* be1  = (const float*)d_in[15];
    const float* g2   = (const float*)d_in[16];
    const float* be2  = (const float*)d_in[17];
    float* out = (float*)d_out;

    float *pattn, *ph, *pff2, *pbqkv;
    __half *pqkvh, *pxh, *pctxh, *phh, *pff1h, *pwqkvh, *pwtoh, *pwt1h, *pwt2h;
    cudaGetSymbolAddress((void**)&pattn,  g_attn);
    cudaGetSymbolAddress((void**)&ph,     g_h);
    cudaGetSymbolAddress((void**)&pff2,   g_ff2);
    cudaGetSymbolAddress((void**)&pbqkv,  g_bqkv);
    cudaGetSymbolAddress((void**)&pqkvh,  g_qkvh);
    cudaGetSymbolAddress((void**)&pxh,    g_xh);
    cudaGetSymbolAddress((void**)&pctxh,  g_ctxh);
    cudaGetSymbolAddress((void**)&phh,    g_hh);
    cudaGetSymbolAddress((void**)&pff1h,  g_ff1h);
    cudaGetSymbolAddress((void**)&pwqkvh, g_wqkvh);
    cudaGetSymbolAddress((void**)&pwtoh,  g_wtoh);
    cudaGetSymbolAddress((void**)&pwt1h,  g_wt1h);
    cudaGetSymbolAddress((void**)&pwt2h,  g_wt2h);

    cudaFuncSetAttribute(gemm_f16, cudaFuncAttributeMaxDynamicSharedMemorySize, GEMM_SMEM);
    cudaFuncSetAttribute(attn_mma, cudaFuncAttributeMaxDynamicSharedMemorySize, ATTN_SMEM);

    dim3 gQKV(3 * DM / 128, MROWS / 128);  // (24, 64)
    dim3 gD(DM / 128, MROWS / 128);        // (8, 64)
    dim3 gF1(DFF / 128, MROWS / 128);      // (32, 64)

    // prep
    transpose_h<<<dim3(DM / 32, DM / 32), dim3(32, 8)>>>(w_q, pwqkvh, DM, DM);
    transpose_h<<<dim3(DM / 32, DM / 32), dim3(32, 8)>>>(w_k, pwqkvh + DM * DM, DM, DM);
    transpose_h<<<dim3(DM / 32, DM / 32), dim3(32, 8)>>>(w_v, pwqkvh + 2 * DM * DM, DM, DM);
    concat_bias3<<<12, 256>>>(b_q, b_k, b_v, pbqkv);
    half_copy<<<(MROWS * DM / 4 + 255) / 256, 256>>>(x, pxh, MROWS * DM / 4);

    // fused QKV projection (fp16 mma; half output feeds fp16 attention)
    gemm_f16<<<gQKV, 256, GEMM_SMEM>>>(pxh, pwqkvh, pbqkv, pqkvh, MROWS, 3 * DM, DM, 0, 2);

    // remaining weight transposes
    transpose_h<<<dim3(DM / 32, DM / 32), dim3(32, 8)>>>(w_o, pwtoh, DM, DM);
    transpose_h<<<dim3(DFF / 32, DM / 32), dim3(32, 8)>>>(w1, pwt1h, DM, DFF);
    transpose_h<<<dim3(DM / 32, DFF / 32), dim3(32, 8)>>>(w2, pwt2h, DFF, DM);

    // flash attention (fp16 mma), half output for O-projection
    attn_mma<<<dim3(SEQ / AQT, BATCH * NH), 256, ATTN_SMEM>>>(
        pqkvh, pqkvh + DM, pqkvh + 2 * DM, mask, pctxh, 3 * DM);

    // output projection (fp16)
    gemm_f16<<<gD, 256, GEMM_SMEM>>>(pctxh, pwtoh, b_o, pattn, MROWS, DM, DM, 0, 0);

    // LN1: h = LN(x + attn_out); hh = half copy
    ln_residual<<<MROWS, 256>>>(x, pattn, g1, be1, ph, phh);

    // FFN (fp16; ff1 stored half directly)
    gemm_f16<<<gF1, 256, GEMM_SMEM>>>(phh, pwt1h, b1, pff1h, MROWS, DFF, DM, 1, 2);
    gemm_f16<<<gD, 256, GEMM_SMEM>>>(pff1h, pwt2h, b2, pff2, MROWS, DM, DFF, 0, 0);

    // LN2: out = LN(h + ff)
    ln_residual<<<MROWS, 256>>>(ph, pff2, g2, be2, out, nullptr);
}

// round 11
// speedup vs baseline: 8.5520x; 1.0125x over previous
#include <cuda_runtime.h>
#include <cuda_fp16.h>
#include <math.h>
#include <stdint.h>

// Problem constants
#define BATCH 4
#define SEQ   2048
#define DM    1024
#define NH    16
#define DK    64
#define DFF   4096
#define MROWS (BATCH * SEQ)   // 8192
#define LN_EPS 1e-5f

// ---------------- scratch (device globals; no allocation allowed) ----------------
__device__ __half g_qkvh[(size_t)MROWS * 3 * DM];  // fused QKV (half) for attention
__device__ __half g_xh[MROWS * DM];
__device__ __half g_ctxh[MROWS * DM];
__device__ float  g_attn[MROWS * DM];
__device__ float  g_h[MROWS * DM];
__device__ __half g_hh[MROWS * DM];
__device__ __half g_ff1h[(size_t)MROWS * DFF];
__device__ float  g_ff2[MROWS * DM];
// transposed (+fp16) weights: [N,K] layout
__device__ __half g_wqkvh[(size_t)3 * DM * DM];
__device__ float  g_bqkv[3 * DM];
__device__ __half g_wtoh[DM * DM];
__device__ __half g_wt1h[(size_t)DFF * DM];
__device__ __half g_wt2h[(size_t)DM * DFF];

// ---------------- small helpers ---------------------------------------------------
__device__ __forceinline__ uint32_t smem_u32(const void* p) {
    uint32_t a;
    asm("{ .reg .u64 t; cvta.to.shared.u64 t, %1; cvt.u32.u64 %0, t; }" : "=r"(a) : "l"(p));
    return a;
}

__device__ __forceinline__ void cp16(uint32_t dst, const void* src) {
    asm volatile("cp.async.cg.shared.global [%0], [%1], 16;" :: "r"(dst), "l"(src) : "memory");
}

__device__ __forceinline__ void cp_commit() {
    asm volatile("cp.async.commit_group;" ::: "memory");
}

__device__ __forceinline__ void cp_wait(int pend) {
    if (pend == 0) asm volatile("cp.async.wait_group 0;" ::: "memory");
    else           asm volatile("cp.async.wait_group 1;" ::: "memory");
}

__device__ __forceinline__ void mma_f16(float* c, uint32_t a0, uint32_t a1,
                                        uint32_t a2, uint32_t a3,
                                        uint32_t b0, uint32_t b1) {
    asm volatile(
        "mma.sync.aligned.m16n8k16.row.col.f32.f16.f16.f32 "
        "{%0,%1,%2,%3}, {%4,%5,%6,%7}, {%8,%9}, {%0,%1,%2,%3};"
        : "+f"(c[0]), "+f"(c[1]), "+f"(c[2]), "+f"(c[3])
        : "r"(a0), "r"(a1), "r"(a2), "r"(a3), "r"(b0), "r"(b1));
}

__device__ __forceinline__ void ldsm4(uint32_t& r0, uint32_t& r1, uint32_t& r2,
                                      uint32_t& r3, uint32_t addr) {
    asm volatile("ldmatrix.sync.aligned.m8n8.x4.shared.b16 {%0,%1,%2,%3}, [%4];"
                 : "=r"(r0), "=r"(r1), "=r"(r2), "=r"(r3) : "r"(addr));
}

__device__ __forceinline__ void ldsm4t(uint32_t& r0, uint32_t& r1, uint32_t& r2,
                                       uint32_t& r3, uint32_t addr) {
    asm volatile("ldmatrix.sync.aligned.m8n8.x4.trans.shared.b16 {%0,%1,%2,%3}, [%4];"
                 : "=r"(r0), "=r"(r1), "=r"(r2), "=r"(r3) : "r"(addr));
}

__device__ __forceinline__ uint32_t fh2(float a, float b) {
    __half2 h = __floats2half2_rn(a, b);
    return *(uint32_t*)&h;
}

// ---------------- fp16 mma.sync GEMM (unchanged, known-good) -----------------------
#define HBK 64
#define HST 72
#define HTILE (128 * HST)
#define HSTAGE (2 * HTILE)
#define HNST 3
#define GEMM_SMEM (HNST * HSTAGE * 2)   // 110592 bytes

__device__ __forceinline__ void h_load_stage(__half* smem, const __half* Ablk,
                                             const __half* Bblk, int K, int s, int tid) {
    __half* As = smem + (s % HNST) * HSTAGE;
    __half* Bs = As + HTILE;
    const int k0 = s * HBK;
    const int row = tid >> 1;
    const int c0 = (tid & 1) * 4;
#pragma unroll
    for (int i = 0; i < 4; i++) {
        int c = c0 + i;
        cp16(smem_u32(As + row * HST + c * 8), Ablk + (size_t)row * K + k0 + c * 8);
        cp16(smem_u32(Bs + row * HST + c * 8), Bblk + (size_t)row * K + k0 + c * 8);
    }
    cp_commit();
}

__global__ __launch_bounds__(256, 2) void gemm_f16(
    const __half* __restrict__ A, const __half* __restrict__ B,
    const float* __restrict__ bias, void* __restrict__ C,
    int M, int N, int K, int relu, int mode)
{
    extern __shared__ __half hsm[];

    const int tid = threadIdx.x;
    const int wid = tid >> 5;
    const int lane = tid & 31;
    const int g = lane >> 2;
    const int tig = lane & 3;
    const int lr = lane & 7;
    const int sub = lane >> 3;

    const int rowBase = (wid & 3) * 32;
    const int colBase = (wid >> 2) * 64;

    int a_row[2], b_row[4];
#pragma unroll
    for (int ma = 0; ma < 2; ma++)
        a_row[ma] = rowBase + ma * 16 + ((sub & 1) << 3) + lr;
    const int a_koff = (sub >> 1) << 3;
#pragma unroll
    for (int nbp = 0; nbp < 4; nbp++)
        b_row[nbp] = colBase + nbp * 16 + ((sub >> 1) << 3) + lr;
    const int b_koff = (sub & 1) << 3;

    const int bx = blockIdx.x, by = blockIdx.y;
    const __half* Ablk = A + (size_t)by * 128 * K;
    const __half* Bblk = B + (size_t)bx * 128 * K;
    const int nstages = K / HBK;

    float acc[2][8][4];
#pragma unroll
    for (int i = 0; i < 2; i++)
#pragma unroll
        for (int j = 0; j < 8; j++)
#pragma unroll
            for (int q = 0; q < 4; q++) acc[i][j][q] = 0.f;

    h_load_stage(hsm, Ablk, Bblk, K, 0, tid);
    h_load_stage(hsm, Ablk, Bblk, K, 1, tid);

    for (int s = 0; s < nstages; s++) {
        cp_wait((s + 1 < nstages) ? 1 : 0);
        __syncthreads();
        if (s + 2 < nstages) h_load_stage(hsm, Ablk, Bblk, K, s + 2, tid);

        const __half* As = hsm + (s % HNST) * HSTAGE;
        const __half* Bs = As + HTILE;
        const uint32_t abase = smem_u32(As);
        const uint32_t bbase = smem_u32(Bs);

#pragma unroll
        for (int ks = 0; ks < 4; ks++) {
            const int k0 = ks * 16;
            uint32_t a[2][4];
#pragma unroll
            for (int ma = 0; ma < 2; ma++)
                ldsm4(a[ma][0], a[ma][1], a[ma][2], a[ma][3],
                      abase + (uint32_t)(a_row[ma] * HST + k0 + a_koff) * 2u);
            uint32_t bb[4][4];
#pragma unroll
            for (int nbp = 0; nbp < 4; nbp++)
                ldsm4(bb[nbp][0], bb[nbp][1], bb[nbp][2], bb[nbp][3],
                      bbase + (uint32_t)(b_row[nbp] * HST + k0 + b_koff) * 2u);
#pragma unroll
            for (int ma = 0; ma < 2; ma++)
#pragma unroll
                for (int nb = 0; nb < 8; nb++)
                    mma_f16(acc[ma][nb], a[ma][0], a[ma][1], a[ma][2], a[ma][3],
                            bb[nb >> 1][(nb & 1) * 2], bb[nb >> 1][(nb & 1) * 2 + 1]);
        }
    }

#pragma unroll
    for (int ma = 0; ma < 2; ma++) {
        int r0 = by * 128 + rowBase + ma * 16 + g;
        int r1 = r0 + 8;
#pragma unroll
        for (int nb = 0; nb < 8; nb++) {
            int col = bx * 128 + colBase + nb * 8 + 2 * tig;
            float b0 = bias[col], b1 = bias[col + 1];
            float2 v0, v1;
            v0.x = acc[ma][nb][0] + b0;
            v0.y = acc[ma][nb][1] + b1;
            v1.x = acc[ma][nb][2] + b0;
            v1.y = acc[ma][nb][3] + b1;
            if (relu) {
                v0.x = fmaxf(v0.x, 0.f); v0.y = fmaxf(v0.y, 0.f);
                v1.x = fmaxf(v1.x, 0.f); v1.y = fmaxf(v1.y, 0.f);
            }
            if (mode == 2) {
                __half* Ch = (__half*)C;
                *(__half2*)(Ch + (size_t)r0 * N + col) = __floats2half2_rn(v0.x, v0.y);
                *(__half2*)(Ch + (size_t)r1 * N + col) = __floats2half2_rn(v1.x, v1.y);
            } else {
                float* Cf = (float*)C;
                *(float2*)(Cf + (size_t)r0 * N + col) = v0;
                *(float2*)(Cf + (size_t)r1 * N + col) = v1;
            }
        }
    }
}

// ---------------- merged prep kernel -----------------------------------------------
// One launch does: 6 weight transposes (float[K,N] -> half[N,K]), bias concat,
// x -> half copy. Flat block-range dispatch, 256 threads/block.
#define PREP_T_QKVO 4096     // wq,wk,wv,wo: 4 x 1024 tiles
#define PREP_T_W1   4096     // w1: 128 x 32 tiles
#define PREP_T_W2   4096     // w2: 32 x 128 tiles
#define PREP_T_COPY 8192     // 2M float4 / 256
#define PREP_T_BIAS 12
#define PREP_BLOCKS (PREP_T_QKVO + PREP_T_W1 + PREP_T_W2 + PREP_T_COPY + PREP_T_BIAS)

__device__ __forceinline__ void prep_transpose(const float* __restrict__ in,
                                               __half* __restrict__ out,
                                               int K, int N, int bx, int by,
                                               int tx, int ty) {
    __shared__ float t[32][33];
    int x = bx * 32 + tx;
#pragma unroll
    for (int j = 0; j < 32; j += 8)
        t[ty + j][tx] = in[(size_t)(by * 32 + ty + j) * N + x];
    __syncthreads();
    int xo = by * 32 + tx;
#pragma unroll
    for (int j = 0; j < 32; j += 8)
        out[(size_t)(bx * 32 + ty + j) * K + xo] = __float2half_rn(t[tx][ty + j]);
}

__global__ __launch_bounds__(256) void prep_all(
    const float* __restrict__ x,
    const float* __restrict__ w_q, const float* __restrict__ w_k,
    const float* __restrict__ w_v, const float* __restrict__ w_o,
    const float* __restrict__ w1, const float* __restrict__ w2,
    const float* __restrict__ b_q, const float* __restrict__ b_k,
    const float* __restrict__ b_v,
    __half* __restrict__ wqkvh, __half* __restrict__ wtoh,
    __half* __restrict__ wt1h, __half* __restrict__ wt2h,
    __half* __restrict__ xh, float* __restrict__ bqkv)
{
    const int blk = blockIdx.x;
    const int tid = threadIdx.x;
    const int tx = tid & 31;
    const int ty = tid >> 5;

    if (blk < PREP_T_QKVO) {
        int which = blk >> 10;              // 0..3
        int t = blk & 1023;
        int bx = t & 31, by = t >> 5;       // 32x32 tiles over 1024x1024
        const float* in = (which == 0) ? w_q : (which == 1) ? w_k :
                          (which == 2) ? w_v : w_o;
        __half* out = (which == 0) ? wqkvh :
                      (which == 1) ? wqkvh + DM * DM :
                      (which == 2) ? wqkvh + 2 * DM * DM : wtoh;
        prep_transpose(in, out, DM, DM, bx, by, tx, ty);
    } else if (blk < PREP_T_QKVO + PREP_T_W1) {
        int t = blk - PREP_T_QKVO;
        int bx = t & 127, by = t >> 7;      // N=4096 -> 128 x-tiles, K=1024 -> 32 y-tiles
        prep_transpose(w1, wt1h, DM, DFF, bx, by, tx, ty);
    } else if (blk < PREP_T_QKVO + PREP_T_W1 + PREP_T_W2) {
        int t = blk - PREP_T_QKVO - PREP_T_W1;
        int bx = t & 31, by = t >> 5;       // N=1024 -> 32 x-tiles, K=4096 -> 128 y-tiles
        prep_transpose(w2, wt2h, DFF, DM, bx, by, tx, ty);
    } else if (blk < PREP_T_QKVO + PREP_T_W1 + PREP_T_W2 + PREP_T_COPY) {
        int i = (blk - PREP_T_QKVO - PREP_T_W1 - PREP_T_W2) * 256 + tid;
        float4 v = ((const float4*)x)[i];
        __half2* o = (__half2*)xh;
        o[2 * i + 0] = __floats2half2_rn(v.x, v.y);
        o[2 * i + 1] = __floats2half2_rn(v.z, v.w);
    } else {
        int i = (blk - PREP_T_QKVO - PREP_T_W1 - PREP_T_W2 - PREP_T_COPY) * 256 + tid;
        if (i < DM) bqkv[i] = b_q[i];
        else if (i < 2 * DM) bqkv[i] = b_k[i - DM];
        else if (i < 3 * DM) bqkv[i] = b_v[i - 2 * DM];
    }
}

// ---------------- Flash attention, fully fp16 mma.sync (unchanged) ----------------
#define AQT 128
#define AKT 64
#define NKB (SEQ / AKT)
#define APH 72
#define AH_K 9216
#define AH_V 18432
#define AB_M 55296
#define ATTN_SMEM (AB_M + 2 * 64 * 4)   // 55808 bytes

__device__ __forceinline__ void attn_load_kv(char* smb, const __half* Kb, const __half* Vb,
                                             const int* mb, int buf, int tid, int rstr) {
    __half* Ks = (__half*)smb + AH_K + buf * (AKT * APH);
    __half* Vs = (__half*)smb + AH_V + buf * (AKT * APH);
    int* mk = (int*)(smb + AB_M) + buf * 64;
#pragma unroll
    for (int i = 0; i < 2; i++) {
        int idx = tid + i * 256;
        int r = idx >> 3;
        int c = idx & 7;
        cp16(smem_u32(Ks + r * APH + c * 8), Kb + (size_t)r * rstr + c * 8);
        cp16(smem_u32(Vs + r * APH + c * 8), Vb + (size_t)r * rstr + c * 8);
    }
    if (tid < 16) cp16(smem_u32(mk + tid * 4), mb + tid * 4);
    cp_commit();
}

__global__ __launch_bounds__(256, 2) void attn_mma(
    const __half* __restrict__ Qg, const __half* __restrict__ Kg,
    const __half* __restrict__ Vg, const int* __restrict__ maskg,
    __half* __restrict__ Og, int rstr)
{
    extern __shared__ char asmb[];
    const int tid = threadIdx.x;
    const int warp = tid >> 5;
    const int lane = tid & 31;
    const int g = lane >> 2;
    const int tig = lane & 3;
    const int lr = lane & 7;
    const int sub = lane >> 3;

    const int bh = blockIdx.y;
    const int b = bh >> 4;
    const int h = bh & 15;
    const int qb = blockIdx.x;

    const __half* Qbase = Qg + (size_t)(b * SEQ + qb * AQT) * rstr + h * DK;
    const int* maskp = maskg + b * SEQ;

    {
        __half* Qs = (__half*)asmb;
#pragma unroll
        for (int i = 0; i < 4; i++) {
            int idx = tid + i * 256;
            int r = idx >> 3;
            int c = idx & 7;
            cp16(smem_u32(Qs + r * APH + c * 8), Qbase + (size_t)r * rstr + c * 8);
        }
        cp_commit();
    }
    attn_load_kv(asmb, Kg + (size_t)(b * SEQ) * rstr + h * DK,
                 Vg + (size_t)(b * SEQ) * rstr + h * DK, maskp, 0, tid, rstr);

    const int a_ro = warp * 16 + ((sub & 1) << 3) + lr;
    const int a_ko = (sub >> 1) << 3;
    const int b_ro = ((sub >> 1) << 3) + lr;
    const int b_ko = (sub & 1) << 3;
    const int v_ro = ((sub & 1) << 3) + lr;
    const int v_co = (sub >> 1) << 3;

    cp_wait(1);
    __syncthreads();
    uint32_t qa[4][4];
    {
        uint32_t qbse = smem_u32(asmb);
#pragma unroll
        for (int ks = 0; ks < 4; ks++)
            ldsm4(qa[ks][0], qa[ks][1], qa[ks][2], qa[ks][3],
                  qbse + (uint32_t)(a_ro * APH + ks * 16 + a_ko) * 2u);
    }

    float o[8][4];
#pragma unroll
    for (int nt = 0; nt < 8; nt++)
#pragma unroll
        for (int j = 0; j < 4; j++) o[nt][j] = 0.f;
    float m0 = -1e30f, m1 = -1e30f, l0 = 0.f, l1 = 0.f;

    for (int kb = 0; kb < NKB; kb++) {
        cp_wait(0);
        __syncthreads();
        if (kb + 1 < NKB) {
            const __half* Kb = Kg + (size_t)(b * SEQ + (kb + 1) * AKT) * rstr + h * DK;
            const __half* Vb = Vg + (size_t)(b * SEQ + (kb + 1) * AKT) * rstr + h * DK;
            attn_load_kv(asmb, Kb, Vb, maskp + (kb + 1) * AKT, (kb + 1) & 1, tid, rstr);
        }

        const uint32_t kbse = smem_u32((__half*)asmb + AH_K + (kb & 1) * (AKT * APH));
        const uint32_t vbse = smem_u32((__half*)asmb + AH_V + (kb & 1) * (AKT * APH));
        const int* mk = (const int*)(asmb + AB_M) + (kb & 1) * 64;

        float s[8][4];
#pragma unroll
        for (int nt = 0; nt < 8; nt++)
#pragma unroll
            for (int j = 0; j < 4; j++) s[nt][j] = 0.f;

#pragma unroll
        for (int ks = 0; ks < 4; ks++) {
            uint32_t kf[4][4];
#pragma unroll
            for (int ntp = 0; ntp < 4; ntp++)
                ldsm4(kf[ntp][0], kf[ntp][1], kf[ntp][2], kf[ntp][3],
                      kbse + (uint32_t)((ntp * 16 + b_ro) * APH + ks * 16 + b_ko) * 2u);
#pragma unroll
            for (int nt = 0; nt < 8; nt++)
                mma_f16(s[nt], qa[ks][0], qa[ks][1], qa[ks][2], qa[ks][3],
                        kf[nt >> 1][(nt & 1) * 2], kf[nt >> 1][(nt & 1) * 2 + 1]);
        }

        float mx0 = -1e30f, mx1 = -1e30f;
#pragma unroll
        for (int nt = 0; nt < 8; nt++) {
            int c0 = nt * 8 + 2 * tig;
            int mk0v = mk[c0];
            int mk1v = mk[c0 + 1];
            float v0 = s[nt][0] * 0.125f; if (mk0v == 0) v0 = -1e30f;
            float v1 = s[nt][1] * 0.125f; if (mk1v == 0) v1 = -1e30f;
            float v2 = s[nt][2] * 0.125f; if (mk0v == 0) v2 = -1e30f;
            float v3 = s[nt][3] * 0.125f; if (mk1v == 0) v3 = -1e30f;
            s[nt][0] = v0; s[nt][1] = v1; s[nt][2] = v2; s[nt][3] = v3;
            mx0 = fmaxf(mx0, fmaxf(v0, v1));
            mx1 = fmaxf(mx1, fmaxf(v2, v3));
        }
        mx0 = fmaxf(mx0, __shfl_xor_sync(0xffffffffu, mx0, 1));
        mx0 = fmaxf(mx0, __shfl_xor_sync(0xffffffffu, mx0, 2));
        mx1 = fmaxf(mx1, __shfl_xor_sync(0xffffffffu, mx1, 1));
        mx1 = fmaxf(mx1, __shfl_xor_sync(0xffffffffu, mx1, 2));

        float mn0 = fmaxf(m0, mx0);
        float mn1 = fmaxf(m1, mx1);
        float corr0 = __expf(m0 - mn0);
        float corr1 = __expf(m1 - mn1);
        m0 = mn0; m1 = mn1;

        float ps0 = 0.f, ps1 = 0.f;
#pragma unroll
        for (int nt = 0; nt < 8; nt++) {
            float p0 = __expf(s[nt][0] - mn0);
            float p1 = __expf(s[nt][1] - mn0);
            float p2 = __expf(s[nt][2] - mn1);
            float p3 = __expf(s[nt][3] - mn1);
            ps0 += p0 + p1;
            ps1 += p2 + p3;
            s[nt][0] = p0; s[nt][1] = p1; s[nt][2] = p2; s[nt][3] = p3;
        }
        ps0 += __shfl_xor_sync(0xffffffffu, ps0, 1);
        ps0 += __shfl_xor_sync(0xffffffffu, ps0, 2);
        ps1 += __shfl_xor_sync(0xffffffffu, ps1, 1);
        ps1 += __shfl_xor_sync(0xffffffffu, ps1, 2);
        l0 = l0 * corr0 + ps0;
        l1 = l1 * corr1 + ps1;

#pragma unroll
        for (int nt = 0; nt < 8; nt++) {
            o[nt][0] *= corr0; o[nt][1] *= corr0;
            o[nt][2] *= corr1; o[nt][3] *= corr1;
        }

#pragma unroll
        for (int ks = 0; ks < 4; ks++) {
            uint32_t pa0 = fh2(s[2 * ks][0],     s[2 * ks][1]);
            uint32_t pa1 = fh2(s[2 * ks][2],     s[2 * ks][3]);
            uint32_t pa2 = fh2(s[2 * ks + 1][0], s[2 * ks + 1][1]);
            uint32_t pa3 = fh2(s[2 * ks + 1][2], s[2 * ks + 1][3]);
#pragma unroll
            for (int dp = 0; dp < 4; dp++) {
                uint32_t vf[4];
                ldsm4t(vf[0], vf[1], vf[2], vf[3],
                       vbse + (uint32_t)((ks * 16 + v_ro) * APH + dp * 16 + v_co) * 2u);
                mma_f16(o[2 * dp],     pa0, pa1, pa2, pa3, vf[0], vf[1]);
                mma_f16(o[2 * dp + 1], pa0, pa1, pa2, pa3, vf[2], vf[3]);
            }
        }
    }

    float inv0 = 1.f / l0;
    float inv1 = 1.f / l1;
    int grow = b * SEQ + qb * AQT + warp * 16 + g;
#pragma unroll
    for (int nt = 0; nt < 8; nt++) {
        int col = h * DK + nt * 8 + 2 * tig;
        *(__half2*)(Og + (size_t)grow * DM + col) =
            __floats2half2_rn(o[nt][0] * inv0, o[nt][1] * inv0);
        *(__half2*)(Og + (size_t)(grow + 8) * DM + col) =
            __floats2half2_rn(o[nt][2] * inv1, o[nt][3] * inv1);
    }
}

// ---------------- fused residual + LayerNorm (float4 vectorized) ------------------
__global__ __launch_bounds__(256) void ln_residual(
    const float* __restrict__ X, const float* __restrict__ R,
    const float* __restrict__ gamma, const float* __restrict__ beta,
    float* __restrict__ out, __half* __restrict__ outh)
{
    const int row = blockIdx.x;
    const int tid = threadIdx.x;
    const float4* x4 = (const float4*)(X + (size_t)row * DM);
    const float4* r4 = (const float4*)(R + (size_t)row * DM);

    float4 xv = x4[tid];
    float4 rv = r4[tid];
    float4 v;
    v.x = xv.x + rv.x; v.y = xv.y + rv.y;
    v.z = xv.z + rv.z; v.w = xv.w + rv.w;
    float sum = v.x + v.y + v.z + v.w;
    float sumsq = v.x * v.x + v.y * v.y + v.z * v.z + v.w * v.w;

    __shared__ float2 wred[8];
    __shared__ float2 fin;
    float2 agg = make_float2(sum, sumsq);
#pragma unroll
    for (int off = 16; off > 0; off >>= 1) {
        agg.x += __shfl_xor_sync(0xffffffffu, agg.x, off);
        agg.y += __shfl_xor_sync(0xffffffffu, agg.y, off);
    }
    const int warp = tid >> 5, lane = tid & 31;
    if (lane == 0) wred[warp] = agg;
    __syncthreads();
    if (warp == 0) {
        float2 a = (lane < 8) ? wred[lane] : make_float2(0.f, 0.f);
#pragma unroll
        for (int off = 4; off > 0; off >>= 1) {
            a.x += __shfl_xor_sync(0xffffffffu, a.x, off);
            a.y += __shfl_xor_sync(0xffffffffu, a.y, off);
        }
        if (lane == 0) fin = a;
    }
    __syncthreads();

    float mu = fin.x * (1.f / DM);
    float var = fin.y * (1.f / DM) - mu * mu;
    float rstd = rsqrtf(var + LN_EPS);

    float4 gv = ((const float4*)gamma)[tid];
    float4 bv = ((const float4*)beta)[tid];
    float4 y;
    y.x = (v.x - mu) * rstd * gv.x + bv.x;
    y.y = (v.y - mu) * rstd * gv.y + bv.y;
    y.z = (v.z - mu) * rstd * gv.z + bv.z;
    y.w = (v.w - mu) * rstd * gv.w + bv.w;
    ((float4*)(out + (size_t)row * DM))[tid] = y;
    if (outh) {
        __half2* oh = (__half2*)(outh + (size_t)row * DM);
        oh[2 * tid + 0] = __floats2half2_rn(y.x, y.y);
        oh[2 * tid + 1] = __floats2half2_rn(y.z, y.w);
    }
}

// ---------------- launch ----------------------------------------------------------
extern "C" void kernel_launch(void* const* d_in, const int* in_sizes, int n_in,
                              void* d_out, int out_size)
{
    const float* x    = (const float*)d_in[0];
    const int*   mask = (const int*)  d_in[1];
    const float* w_q  = (const float*)d_in[2];
    const float* b_q  = (const float*)d_in[3];
    const float* w_k  = (const float*)d_in[4];
    const float* b_k  = (const float*)d_in[5];
    const float* w_v  = (const float*)d_in[6];
    const float* b_v  = (const float*)d_in[7];
    const float* w_o  = (const float*)d_in[8];
    const float* b_o  = (const float*)d_in[9];
    const float* w1   = (const float*)d_in[10];
    const float* b1   = (const float*)d_in[11];
    const float* w2   = (const float*)d_in[12];
    const float* b2   = (const float*)d_in[13];
    const float* g1   = (const float*)d_in[14];
    const float* be1  = (const float*)d_in[15];
    const float* g2   = (const float*)d_in[16];
    const float* be2  = (const float*)d_in[17];
    float* out = (float*)d_out;

    float *pattn, *ph, *pff2, *pbqkv;
    __half *pqkvh, *pxh, *pctxh, *phh, *pff1h, *pwqkvh, *pwtoh, *pwt1h, *pwt2h;
    cudaGetSymbolAddress((void**)&pattn,  g_attn);
    cudaGetSymbolAddress((void**)&ph,     g_h);
    cudaGetSymbolAddress((void**)&pff2,   g_ff2);
    cudaGetSymbolAddress((void**)&pbqkv,  g_bqkv);
    cudaGetSymbolAddress((void**)&pqkvh,  g_qkvh);
    cudaGetSymbolAddress((void**)&pxh,    g_xh);
    cudaGetSymbolAddress((void**)&pctxh,  g_ctxh);
    cudaGetSymbolAddress((void**)&phh,    g_hh);
    cudaGetSymbolAddress((void**)&pff1h,  g_ff1h);
    cudaGetSymbolAddress((void**)&pwqkvh, g_wqkvh);
    cudaGetSymbolAddress((void**)&pwtoh,  g_wtoh);
    cudaGetSymbolAddress((void**)&pwt1h,  g_wt1h);
    cudaGetSymbolAddress((void**)&pwt2h,  g_wt2h);

    cudaFuncSetAttribute(gemm_f16, cudaFuncAttributeMaxDynamicSharedMemorySize, GEMM_SMEM);
    cudaFuncSetAttribute(attn_mma, cudaFuncAttributeMaxDynamicSharedMemorySize, ATTN_SMEM);

    dim3 gQKV(3 * DM / 128, MROWS / 128);  // (24, 64)
    dim3 gD(DM / 128, MROWS / 128);        // (8, 64)
    dim3 gF1(DFF / 128, MROWS / 128);      // (32, 64)

    // ALL prep in one launch: 6 transposes + bias concat + x->half
    prep_all<<<PREP_BLOCKS, 256>>>(x, w_q, w_k, w_v, w_o, w1, w2, b_q, b_k, b_v,
                                   pwqkvh, pwtoh, pwt1h, pwt2h, pxh, pbqkv);

    // fused QKV projection (fp16 mma; half output feeds fp16 attention)
    gemm_f16<<<gQKV, 256, GEMM_SMEM>>>(pxh, pwqkvh, pbqkv, pqkvh, MROWS, 3 * DM, DM, 0, 2);

    // flash attention (fp16 mma), half output for O-projection
    attn_mma<<<dim3(SEQ / AQT, BATCH * NH), 256, ATTN_SMEM>>>(
        pqkvh, pqkvh + DM, pqkvh + 2 * DM, mask, pctxh, 3 * DM);

    // output projection (fp16)
    gemm_f16<<<gD, 256, GEMM_SMEM>>>(pctxh, pwtoh, b_o, pattn, MROWS, DM, DM, 0, 0);

    // LN1: h = LN(x + attn_out); hh = half copy
    ln_residual<<<MROWS, 256>>>(x, pattn, g1, be1, ph, phh);

    // FFN (fp16; ff1 stored half directly)
    gemm_f16<<<gF1, 256, GEMM_SMEM>>>(phh, pwt1h, b1, pff1h, MROWS, DFF, DM, 1, 2);
    gemm_f16<<<gD, 256, GEMM_SMEM>>>(pff1h, pwt2h, b2, pff2, MROWS, DM, DFF, 0, 0);

    // LN2: out = LN(h + ff)
    ln_residual<<<MROWS, 256>>>(ph, pff2, g2, be2, out, nullptr);
}

// round 12
// speedup vs baseline: 9.8192x; 1.1482x over previous
#include <cuda_runtime.h>
#include <cuda_fp16.h>
#include <math.h>
#include <stdint.h>

// Problem constants
#define BATCH 4
#define SEQ   2048
#define DM    1024
#define NH    16
#define DK    64
#define DFF   4096
#define MROWS (BATCH * SEQ)   // 8192
#define LN_EPS 1e-5f

// ---------------- scratch (device globals; no allocation allowed) ----------------
__device__ __half g_qkvh[(size_t)MROWS * 3 * DM];  // fused QKV (half) for attention
__device__ __half g_xh[MROWS * DM];
__device__ __half g_ctxh[MROWS * DM];
__device__ float  g_attn[MROWS * DM];
__device__ float  g_h[MROWS * DM];
__device__ __half g_hh[MROWS * DM];
__device__ __half g_ff1h[(size_t)MROWS * DFF];
__device__ float  g_ff2[MROWS * DM];
// transposed (+fp16) weights: [N,K] layout
__device__ __half g_wqkvh[(size_t)3 * DM * DM];
__device__ float  g_bqkv[3 * DM];
__device__ __half g_wtoh[DM * DM];
__device__ __half g_wt1h[(size_t)DFF * DM];
__device__ __half g_wt2h[(size_t)DM * DFF];

// ---------------- small helpers ---------------------------------------------------
__device__ __forceinline__ uint32_t smem_u32(const void* p) {
    uint32_t a;
    asm("{ .reg .u64 t; cvta.to.shared.u64 t, %1; cvt.u32.u64 %0, t; }" : "=r"(a) : "l"(p));
    return a;
}

__device__ __forceinline__ void cp16(uint32_t dst, const void* src) {
    asm volatile("cp.async.cg.shared.global [%0], [%1], 16;" :: "r"(dst), "l"(src) : "memory");
}

__device__ __forceinline__ void cp_commit() {
    asm volatile("cp.async.commit_group;" ::: "memory");
}

__device__ __forceinline__ void cp_wait(int pend) {
    if (pend == 0) asm volatile("cp.async.wait_group 0;" ::: "memory");
    else           asm volatile("cp.async.wait_group 1;" ::: "memory");
}

__device__ __forceinline__ void mma_f16(float* c, uint32_t a0, uint32_t a1,
                                        uint32_t a2, uint32_t a3,
                                        uint32_t b0, uint32_t b1) {
    asm volatile(
        "mma.sync.aligned.m16n8k16.row.col.f32.f16.f16.f32 "
        "{%0,%1,%2,%3}, {%4,%5,%6,%7}, {%8,%9}, {%0,%1,%2,%3};"
        : "+f"(c[0]), "+f"(c[1]), "+f"(c[2]), "+f"(c[3])
        : "r"(a0), "r"(a1), "r"(a2), "r"(a3), "r"(b0), "r"(b1));
}

__device__ __forceinline__ void ldsm4(uint32_t& r0, uint32_t& r1, uint32_t& r2,
                                      uint32_t& r3, uint32_t addr) {
    asm volatile("ldmatrix.sync.aligned.m8n8.x4.shared.b16 {%0,%1,%2,%3}, [%4];"
                 : "=r"(r0), "=r"(r1), "=r"(r2), "=r"(r3) : "r"(addr));
}

__device__ __forceinline__ void ldsm4t(uint32_t& r0, uint32_t& r1, uint32_t& r2,
                                       uint32_t& r3, uint32_t addr) {
    asm volatile("ldmatrix.sync.aligned.m8n8.x4.trans.shared.b16 {%0,%1,%2,%3}, [%4];"
                 : "=r"(r0), "=r"(r1), "=r"(r2), "=r"(r3) : "r"(addr));
}

__device__ __forceinline__ uint32_t fh2(float a, float b) {
    __half2 h = __floats2half2_rn(a, b);
    return *(uint32_t*)&h;
}

// ---------------- fp16 mma.sync GEMM — 512 threads, warp tile 32x32 ----------------
// C[M,N] = A[M,K] @ B[N,K]^T + bias, optional relu. mode: 0=float out, 2=half out.
// Tile 128x128, BK=64 halves, 16 warps (4 warpM x 4 warpN), 3-stage cp.async ring,
// __launch_bounds__(512,2) -> 32 warps/SM for latency hiding.
#define HBK 64
#define HST 72
#define HTILE (128 * HST)
#define HSTAGE (2 * HTILE)
#define HNST 3
#define GEMM_SMEM (HNST * HSTAGE * 2)   // 110592 bytes

__device__ __forceinline__ void h_load_stage(__half* smem, const __half* Ablk,
                                             const __half* Bblk, int K, int s, int tid) {
    __half* As = smem + (s % HNST) * HSTAGE;
    __half* Bs = As + HTILE;
    const int k0 = s * HBK;
    const int row = tid >> 2;          // 0..127
    const int c0 = (tid & 3) * 2;      // 16B chunks: 2 per thread per tile
#pragma unroll
    for (int i = 0; i < 2; i++) {
        int c = c0 + i;
        cp16(smem_u32(As + row * HST + c * 8), Ablk + (size_t)row * K + k0 + c * 8);
        cp16(smem_u32(Bs + row * HST + c * 8), Bblk + (size_t)row * K + k0 + c * 8);
    }
    cp_commit();
}

__global__ __launch_bounds__(512, 2) void gemm_f16(
    const __half* __restrict__ A, const __half* __restrict__ B,
    const float* __restrict__ bias, void* __restrict__ C,
    int M, int N, int K, int relu, int mode)
{
    extern __shared__ __half hsm[];

    const int tid = threadIdx.x;
    const int wid = tid >> 5;          // 0..15
    const int lane = tid & 31;
    const int g = lane >> 2;
    const int tig = lane & 3;
    const int lr = lane & 7;
    const int sub = lane >> 3;

    const int rowBase = (wid & 3) * 32;    // warpM 0..3
    const int colBase = (wid >> 2) * 32;   // warpN 0..3

    int a_row[2], b_row[2];
#pragma unroll
    for (int ma = 0; ma < 2; ma++)
        a_row[ma] = rowBase + ma * 16 + ((sub & 1) << 3) + lr;
    const int a_koff = (sub >> 1) << 3;
#pragma unroll
    for (int nbp = 0; nbp < 2; nbp++)
        b_row[nbp] = colBase + nbp * 16 + ((sub >> 1) << 3) + lr;
    const int b_koff = (sub & 1) << 3;

    const int bx = blockIdx.x, by = blockIdx.y;
    const __half* Ablk = A + (size_t)by * 128 * K;
    const __half* Bblk = B + (size_t)bx * 128 * K;
    const int nstages = K / HBK;

    float acc[2][4][4];
#pragma unroll
    for (int i = 0; i < 2; i++)
#pragma unroll
        for (int j = 0; j < 4; j++)
#pragma unroll
            for (int q = 0; q < 4; q++) acc[i][j][q] = 0.f;

    h_load_stage(hsm, Ablk, Bblk, K, 0, tid);
    h_load_stage(hsm, Ablk, Bblk, K, 1, tid);

    for (int s = 0; s < nstages; s++) {
        cp_wait((s + 1 < nstages) ? 1 : 0);
        __syncthreads();
        if (s + 2 < nstages) h_load_stage(hsm, Ablk, Bblk, K, s + 2, tid);

        const __half* As = hsm + (s % HNST) * HSTAGE;
        const __half* Bs = As + HTILE;
        const uint32_t abase = smem_u32(As);
        const uint32_t bbase = smem_u32(Bs);

#pragma unroll
        for (int ks = 0; ks < 4; ks++) {
            const int k0 = ks * 16;
            uint32_t a[2][4];
#pragma unroll
            for (int ma = 0; ma < 2; ma++)
                ldsm4(a[ma][0], a[ma][1], a[ma][2], a[ma][3],
                      abase + (uint32_t)(a_row[ma] * HST + k0 + a_koff) * 2u);
            uint32_t bb[2][4];
#pragma unroll
            for (int nbp = 0; nbp < 2; nbp++)
                ldsm4(bb[nbp][0], bb[nbp][1], bb[nbp][2], bb[nbp][3],
                      bbase + (uint32_t)(b_row[nbp] * HST + k0 + b_koff) * 2u);
#pragma unroll
            for (int ma = 0; ma < 2; ma++)
#pragma unroll
                for (int nb = 0; nb < 4; nb++)
                    mma_f16(acc[ma][nb], a[ma][0], a[ma][1], a[ma][2], a[ma][3],
                            bb[nb >> 1][(nb & 1) * 2], bb[nb >> 1][(nb & 1) * 2 + 1]);
        }
    }

#pragma unroll
    for (int ma = 0; ma < 2; ma++) {
        int r0 = by * 128 + rowBase + ma * 16 + g;
        int r1 = r0 + 8;
#pragma unroll
        for (int nb = 0; nb < 4; nb++) {
            int col = bx * 128 + colBase + nb * 8 + 2 * tig;
            float b0 = bias[col], b1 = bias[col + 1];
            float2 v0, v1;
            v0.x = acc[ma][nb][0] + b0;
            v0.y = acc[ma][nb][1] + b1;
            v1.x = acc[ma][nb][2] + b0;
            v1.y = acc[ma][nb][3] + b1;
            if (relu) {
                v0.x = fmaxf(v0.x, 0.f); v0.y = fmaxf(v0.y, 0.f);
                v1.x = fmaxf(v1.x, 0.f); v1.y = fmaxf(v1.y, 0.f);
            }
            if (mode == 2) {
                __half* Ch = (__half*)C;
                *(__half2*)(Ch + (size_t)r0 * N + col) = __floats2half2_rn(v0.x, v0.y);
                *(__half2*)(Ch + (size_t)r1 * N + col) = __floats2half2_rn(v1.x, v1.y);
            } else {
                float* Cf = (float*)C;
                *(float2*)(Cf + (size_t)r0 * N + col) = v0;
                *(float2*)(Cf + (size_t)r1 * N + col) = v1;
            }
        }
    }
}

// ---------------- merged prep kernel (unchanged) -----------------------------------
#define PREP_T_QKVO 4096
#define PREP_T_W1   4096
#define PREP_T_W2   4096
#define PREP_T_COPY 8192
#define PREP_T_BIAS 12
#define PREP_BLOCKS (PREP_T_QKVO + PREP_T_W1 + PREP_T_W2 + PREP_T_COPY + PREP_T_BIAS)

__device__ __forceinline__ void prep_transpose(const float* __restrict__ in,
                                               __half* __restrict__ out,
                                               int K, int N, int bx, int by,
                                               int tx, int ty) {
    __shared__ float t[32][33];
    int x = bx * 32 + tx;
#pragma unroll
    for (int j = 0; j < 32; j += 8)
        t[ty + j][tx] = in[(size_t)(by * 32 + ty + j) * N + x];
    __syncthreads();
    int xo = by * 32 + tx;
#pragma unroll
    for (int j = 0; j < 32; j += 8)
        out[(size_t)(bx * 32 + ty + j) * K + xo] = __float2half_rn(t[tx][ty + j]);
}

__global__ __launch_bounds__(256) void prep_all(
    const float* __restrict__ x,
    const float* __restrict__ w_q, const float* __restrict__ w_k,
    const float* __restrict__ w_v, const float* __restrict__ w_o,
    const float* __restrict__ w1, const float* __restrict__ w2,
    const float* __restrict__ b_q, const float* __restrict__ b_k,
    const float* __restrict__ b_v,
    __half* __restrict__ wqkvh, __half* __restrict__ wtoh,
    __half* __restrict__ wt1h, __half* __restrict__ wt2h,
    __half* __restrict__ xh, float* __restrict__ bqkv)
{
    const int blk = blockIdx.x;
    const int tid = threadIdx.x;
    const int tx = tid & 31;
    const int ty = tid >> 5;

    if (blk < PREP_T_QKVO) {
        int which = blk >> 10;
        int t = blk & 1023;
        int bx = t & 31, by = t >> 5;
        const float* in = (which == 0) ? w_q : (which == 1) ? w_k :
                          (which == 2) ? w_v : w_o;
        __half* out = (which == 0) ? wqkvh :
                      (which == 1) ? wqkvh + DM * DM :
                      (which == 2) ? wqkvh + 2 * DM * DM : wtoh;
        prep_transpose(in, out, DM, DM, bx, by, tx, ty);
    } else if (blk < PREP_T_QKVO + PREP_T_W1) {
        int t = blk - PREP_T_QKVO;
        int bx = t & 127, by = t >> 7;
        prep_transpose(w1, wt1h, DM, DFF, bx, by, tx, ty);
    } else if (blk < PREP_T_QKVO + PREP_T_W1 + PREP_T_W2) {
        int t = blk - PREP_T_QKVO - PREP_T_W1;
        int bx = t & 31, by = t >> 5;
        prep_transpose(w2, wt2h, DFF, DM, bx, by, tx, ty);
    } else if (blk < PREP_T_QKVO + PREP_T_W1 + PREP_T_W2 + PREP_T_COPY) {
        int i = (blk - PREP_T_QKVO - PREP_T_W1 - PREP_T_W2) * 256 + tid;
        float4 v = ((const float4*)x)[i];
        __half2* o = (__half2*)xh;
        o[2 * i + 0] = __floats2half2_rn(v.x, v.y);
        o[2 * i + 1] = __floats2half2_rn(v.z, v.w);
    } else {
        int i = (blk - PREP_T_QKVO - PREP_T_W1 - PREP_T_W2 - PREP_T_COPY) * 256 + tid;
        if (i < DM) bqkv[i] = b_q[i];
        else if (i < 2 * DM) bqkv[i] = b_k[i - DM];
        else if (i < 3 * DM) bqkv[i] = b_v[i - 2 * DM];
    }
}

// ---------------- Flash attention, fully fp16 mma.sync (unchanged) ----------------
#define AQT 128
#define AKT 64
#define NKB (SEQ / AKT)
#define APH 72
#define AH_K 9216
#define AH_V 18432
#define AB_M 55296
#define ATTN_SMEM (AB_M + 2 * 64 * 4)   // 55808 bytes

__device__ __forceinline__ void attn_load_kv(char* smb, const __half* Kb, const __half* Vb,
                                             const int* mb, int buf, int tid, int rstr) {
    __half* Ks = (__half*)smb + AH_K + buf * (AKT * APH);
    __half* Vs = (__half*)smb + AH_V + buf * (AKT * APH);
    int* mk = (int*)(smb + AB_M) + buf * 64;
#pragma unroll
    for (int i = 0; i < 2; i++) {
        int idx = tid + i * 256;
        int r = idx >> 3;
        int c = idx & 7;
        cp16(smem_u32(Ks + r * APH + c * 8), Kb + (size_t)r * rstr + c * 8);
        cp16(smem_u32(Vs + r * APH + c * 8), Vb + (size_t)r * rstr + c * 8);
    }
    if (tid < 16) cp16(smem_u32(mk + tid * 4), mb + tid * 4);
    cp_commit();
}

__global__ __launch_bounds__(256, 2) void attn_mma(
    const __half* __restrict__ Qg, const __half* __restrict__ Kg,
    const __half* __restrict__ Vg, const int* __restrict__ maskg,
    __half* __restrict__ Og, int rstr)
{
    extern __shared__ char asmb[];
    const int tid = threadIdx.x;
    const int warp = tid >> 5;
    const int lane = tid & 31;
    const int g = lane >> 2;
    const int tig = lane & 3;
    const int lr = lane & 7;
    const int sub = lane >> 3;

    const int bh = blockIdx.y;
    const int b = bh >> 4;
    const int h = bh & 15;
    const int qb = blockIdx.x;

    const __half* Qbase = Qg + (size_t)(b * SEQ + qb * AQT) * rstr + h * DK;
    const int* maskp = maskg + b * SEQ;

    {
        __half* Qs = (__half*)asmb;
#pragma unroll
        for (int i = 0; i < 4; i++) {
            int idx = tid + i * 256;
            int r = idx >> 3;
            int c = idx & 7;
            cp16(smem_u32(Qs + r * APH + c * 8), Qbase + (size_t)r * rstr + c * 8);
        }
        cp_commit();
    }
    attn_load_kv(asmb, Kg + (size_t)(b * SEQ) * rstr + h * DK,
                 Vg + (size_t)(b * SEQ) * rstr + h * DK, maskp, 0, tid, rstr);

    const int a_ro = warp * 16 + ((sub & 1) << 3) + lr;
    const int a_ko = (sub >> 1) << 3;
    const int b_ro = ((sub >> 1) << 3) + lr;
    const int b_ko = (sub & 1) << 3;
    const int v_ro = ((sub & 1) << 3) + lr;
    const int v_co = (sub >> 1) << 3;

    cp_wait(1);
    __syncthreads();
    uint32_t qa[4][4];
    {
        uint32_t qbse = smem_u32(asmb);
#pragma unroll
        for (int ks = 0; ks < 4; ks++)
            ldsm4(qa[ks][0], qa[ks][1], qa[ks][2], qa[ks][3],
                  qbse + (uint32_t)(a_ro * APH + ks * 16 + a_ko) * 2u);
    }

    float o[8][4];
#pragma unroll
    for (int nt = 0; nt < 8; nt++)
#pragma unroll
        for (int j = 0; j < 4; j++) o[nt][j] = 0.f;
    float m0 = -1e30f, m1 = -1e30f, l0 = 0.f, l1 = 0.f;

    for (int kb = 0; kb < NKB; kb++) {
        cp_wait(0);
        __syncthreads();
        if (kb + 1 < NKB) {
            const __half* Kb = Kg + (size_t)(b * SEQ + (kb + 1) * AKT) * rstr + h * DK;
            const __half* Vb = Vg + (size_t)(b * SEQ + (kb + 1) * AKT) * rstr + h * DK;
            attn_load_kv(asmb, Kb, Vb, maskp + (kb + 1) * AKT, (kb + 1) & 1, tid, rstr);
        }

        const uint32_t kbse = smem_u32((__half*)asmb + AH_K + (kb & 1) * (AKT * APH));
        const uint32_t vbse = smem_u32((__half*)asmb + AH_V + (kb & 1) * (AKT * APH));
        const int* mk = (const int*)(asmb + AB_M) + (kb & 1) * 64;

        float s[8][4];
#pragma unroll
        for (int nt = 0; nt < 8; nt++)
#pragma unroll
            for (int j = 0; j < 4; j++) s[nt][j] = 0.f;

#pragma unroll
        for (int ks = 0; ks < 4; ks++) {
            uint32_t kf[4][4];
#pragma unroll
            for (int ntp = 0; ntp < 4; ntp++)
                ldsm4(kf[ntp][0], kf[ntp][1], kf[ntp][2], kf[ntp][3],
                      kbse + (uint32_t)((ntp * 16 + b_ro) * APH + ks * 16 + b_ko) * 2u);
#pragma unroll
            for (int nt = 0; nt < 8; nt++)
                mma_f16(s[nt], qa[ks][0], qa[ks][1], qa[ks][2], qa[ks][3],
                        kf[nt >> 1][(nt & 1) * 2], kf[nt >> 1][(nt & 1) * 2 + 1]);
        }

        float mx0 = -1e30f, mx1 = -1e30f;
#pragma unroll
        for (int nt = 0; nt < 8; nt++) {
            int c0 = nt * 8 + 2 * tig;
            int mk0v = mk[c0];
            int mk1v = mk[c0 + 1];
            float v0 = s[nt][0] * 0.125f; if (mk0v == 0) v0 = -1e30f;
            float v1 = s[nt][1] * 0.125f; if (mk1v == 0) v1 = -1e30f;
            float v2 = s[nt][2] * 0.125f; if (mk0v == 0) v2 = -1e30f;
            float v3 = s[nt][3] * 0.125f; if (mk1v == 0) v3 = -1e30f;
            s[nt][0] = v0; s[nt][1] = v1; s[nt][2] = v2; s[nt][3] = v3;
            mx0 = fmaxf(mx0, fmaxf(v0, v1));
            mx1 = fmaxf(mx1, fmaxf(v2, v3));
        }
        mx0 = fmaxf(mx0, __shfl_xor_sync(0xffffffffu, mx0, 1));
        mx0 = fmaxf(mx0, __shfl_xor_sync(0xffffffffu, mx0, 2));
        mx1 = fmaxf(mx1, __shfl_xor_sync(0xffffffffu, mx1, 1));
        mx1 = fmaxf(mx1, __shfl_xor_sync(0xffffffffu, mx1, 2));

        float mn0 = fmaxf(m0, mx0);
        float mn1 = fmaxf(m1, mx1);
        float corr0 = __expf(m0 - mn0);
        float corr1 = __expf(m1 - mn1);
        m0 = mn0; m1 = mn1;

        float ps0 = 0.f, ps1 = 0.f;
#pragma unroll
        for (int nt = 0; nt < 8; nt++) {
            float p0 = __expf(s[nt][0] - mn0);
            float p1 = __expf(s[nt][1] - mn0);
            float p2 = __expf(s[nt][2] - mn1);
            float p3 = __expf(s[nt][3] - mn1);
            ps0 += p0 + p1;
            ps1 += p2 + p3;
            s[nt][0] = p0; s[nt][1] = p1; s[nt][2] = p2; s[nt][3] = p3;
        }
        ps0 += __shfl_xor_sync(0xffffffffu, ps0, 1);
        ps0 += __shfl_xor_sync(0xffffffffu, ps0, 2);
        ps1 += __shfl_xor_sync(0xffffffffu, ps1, 1);
        ps1 += __shfl_xor_sync(0xffffffffu, ps1, 2);
        l0 = l0 * corr0 + ps0;
        l1 = l1 * corr1 + ps1;

#pragma unroll
        for (int nt = 0; nt < 8; nt++) {
            o[nt][0] *= corr0; o[nt][1] *= corr0;
            o[nt][2] *= corr1; o[nt][3] *= corr1;
        }

#pragma unroll
        for (int ks = 0; ks < 4; ks++) {
            uint32_t pa0 = fh2(s[2 * ks][0],     s[2 * ks][1]);
            uint32_t pa1 = fh2(s[2 * ks][2],     s[2 * ks][3]);
            uint32_t pa2 = fh2(s[2 * ks + 1][0], s[2 * ks + 1][1]);
            uint32_t pa3 = fh2(s[2 * ks + 1][2], s[2 * ks + 1][3]);
#pragma unroll
            for (int dp = 0; dp < 4; dp++) {
                uint32_t vf[4];
                ldsm4t(vf[0], vf[1], vf[2], vf[3],
                       vbse + (uint32_t)((ks * 16 + v_ro) * APH + dp * 16 + v_co) * 2u);
                mma_f16(o[2 * dp],     pa0, pa1, pa2, pa3, vf[0], vf[1]);
                mma_f16(o[2 * dp + 1], pa0, pa1, pa2, pa3, vf[2], vf[3]);
            }
        }
    }

    float inv0 = 1.f / l0;
    float inv1 = 1.f / l1;
    int grow = b * SEQ + qb * AQT + warp * 16 + g;
#pragma unroll
    for (int nt = 0; nt < 8; nt++) {
        int col = h * DK + nt * 8 + 2 * tig;
        *(__half2*)(Og + (size_t)grow * DM + col) =
            __floats2half2_rn(o[nt][0] * inv0, o[nt][1] * inv0);
        *(__half2*)(Og + (size_t)(grow + 8) * DM + col) =
            __floats2half2_rn(o[nt][2] * inv1, o[nt][3] * inv1);
    }
}

// ---------------- fused residual + LayerNorm (float4 vectorized) ------------------
__global__ __launch_bounds__(256) void ln_residual(
    const float* __restrict__ X, const float* __restrict__ R,
    const float* __restrict__ gamma, const float* __restrict__ beta,
    float* __restrict__ out, __half* __restrict__ outh)
{
    const int row = blockIdx.x;
    const int tid = threadIdx.x;
    const float4* x4 = (const float4*)(X + (size_t)row * DM);
    const float4* r4 = (const float4*)(R + (size_t)row * DM);

    float4 xv = x4[tid];
    float4 rv = r4[tid];
    float4 v;
    v.x = xv.x + rv.x; v.y = xv.y + rv.y;
    v.z = xv.z + rv.z; v.w = xv.w + rv.w;
    float sum = v.x + v.y + v.z + v.w;
    float sumsq = v.x * v.x + v.y * v.y + v.z * v.z + v.w * v.w;

    __shared__ float2 wred[8];
    __shared__ float2 fin;
    float2 agg = make_float2(sum, sumsq);
#pragma unroll
    for (int off = 16; off > 0; off >>= 1) {
        agg.x += __shfl_xor_sync(0xffffffffu, agg.x, off);
        agg.y += __shfl_xor_sync(0xffffffffu, agg.y, off);
    }
    const int warp = tid >> 5, lane = tid & 31;
    if (lane == 0) wred[warp] = agg;
    __syncthreads();
    if (warp == 0) {
        float2 a = (lane < 8) ? wred[lane] : make_float2(0.f, 0.f);
#pragma unroll
        for (int off = 4; off > 0; off >>= 1) {
            a.x += __shfl_xor_sync(0xffffffffu, a.x, off);
            a.y += __shfl_xor_sync(0xffffffffu, a.y, off);
        }
        if (lane == 0) fin = a;
    }
    __syncthreads();

    float mu = fin.x * (1.f / DM);
    float var = fin.y * (1.f / DM) - mu * mu;
    float rstd = rsqrtf(var + LN_EPS);

    float4 gv = ((const float4*)gamma)[tid];
    float4 bv = ((const float4*)beta)[tid];
    float4 y;
    y.x = (v.x - mu) * rstd * gv.x + bv.x;
    y.y = (v.y - mu) * rstd * gv.y + bv.y;
    y.z = (v.z - mu) * rstd * gv.z + bv.z;
    y.w = (v.w - mu) * rstd * gv.w + bv.w;
    ((float4*)(out + (size_t)row * DM))[tid] = y;
    if (outh) {
        __half2* oh = (__half2*)(outh + (size_t)row * DM);
        oh[2 * tid + 0] = __floats2half2_rn(y.x, y.y);
        oh[2 * tid + 1] = __floats2half2_rn(y.z, y.w);
    }
}

// ---------------- launch ----------------------------------------------------------
extern "C" void kernel_launch(void* const* d_in, const int* in_sizes, int n_in,
                              void* d_out, int out_size)
{
    const float* x    = (const float*)d_in[0];
    const int*   mask = (const int*)  d_in[1];
    const float* w_q  = (const float*)d_in[2];
    const float* b_q  = (const float*)d_in[3];
    const float* w_k  = (const float*)d_in[4];
    const float* b_k  = (const float*)d_in[5];
    const float* w_v  = (const float*)d_in[6];
    const float* b_v  = (const float*)d_in[7];
    const float* w_o  = (const float*)d_in[8];
    const float* b_o  = (const float*)d_in[9];
    const float* w1   = (const float*)d_in[10];
    const float* b1   = (const float*)d_in[11];
    const float* w2   = (const float*)d_in[12];
    const float* b2   = (const float*)d_in[13];
    const float* g1   = (const float*)d_in[14];
    const float* be1  = (const float*)d_in[15];
    const float* g2   = (const float*)d_in[16];
    const float* be2  = (const float*)d_in[17];
    float* out = (float*)d_out;

    float *pattn, *ph, *pff2, *pbqkv;
    __half *pqkvh, *pxh, *pctxh, *phh, *pff1h, *pwqkvh, *pwtoh, *pwt1h, *pwt2h;
    cudaGetSymbolAddress((void**)&pattn,  g_attn);
    cudaGetSymbolAddress((void**)&ph,     g_h);
    cudaGetSymbolAddress((void**)&pff2,   g_ff2);
    cudaGetSymbolAddress((void**)&pbqkv,  g_bqkv);
    cudaGetSymbolAddress((void**)&pqkvh,  g_qkvh);
    cudaGetSymbolAddress((void**)&pxh,    g_xh);
    cudaGetSymbolAddress((void**)&pctxh,  g_ctxh);
    cudaGetSymbolAddress((void**)&phh,    g_hh);
    cudaGetSymbolAddress((void**)&pff1h,  g_ff1h);
    cudaGetSymbolAddress((void**)&pwqkvh, g_wqkvh);
    cudaGetSymbolAddress((void**)&pwtoh,  g_wtoh);
    cudaGetSymbolAddress((void**)&pwt1h,  g_wt1h);
    cudaGetSymbolAddress((void**)&pwt2h,  g_wt2h);

    cudaFuncSetAttribute(gemm_f16, cudaFuncAttributeMaxDynamicSharedMemorySize, GEMM_SMEM);
    cudaFuncSetAttribute(attn_mma, cudaFuncAttributeMaxDynamicSharedMemorySize, ATTN_SMEM);

    dim3 gQKV(3 * DM / 128, MROWS / 128);  // (24, 64)
    dim3 gD(DM / 128, MROWS / 128);        // (8, 64)
    dim3 gF1(DFF / 128, MROWS / 128);      // (32, 64)

    // ALL prep in one launch: 6 transposes + bias concat + x->half
    prep_all<<<PREP_BLOCKS, 256>>>(x, w_q, w_k, w_v, w_o, w1, w2, b_q, b_k, b_v,
                                   pwqkvh, pwtoh, pwt1h, pwt2h, pxh, pbqkv);

    // fused QKV projection (fp16 mma; half output feeds fp16 attention)
    gemm_f16<<<gQKV, 512, GEMM_SMEM>>>(pxh, pwqkvh, pbqkv, pqkvh, MROWS, 3 * DM, DM, 0, 2);

    // flash attention (fp16 mma), half output for O-projection
    attn_mma<<<dim3(SEQ / AQT, BATCH * NH), 256, ATTN_SMEM>>>(
        pqkvh, pqkvh + DM, pqkvh + 2 * DM, mask, pctxh, 3 * DM);

    // output projection (fp16)
    gemm_f16<<<gD, 512, GEMM_SMEM>>>(pctxh, pwtoh, b_o, pattn, MROWS, DM, DM, 0, 0);

    // LN1: h = LN(x + attn_out); hh = half copy
    ln_residual<<<MROWS, 256>>>(x, pattn, g1, be1, ph, phh);

    // FFN (fp16; ff1 stored half directly)
    gemm_f16<<<gF1, 512, GEMM_SMEM>>>(phh, pwt1h, b1, pff1h, MROWS, DFF, DM, 1, 2);
    gemm_f16<<<gD, 512, GEMM_SMEM>>>(pff1h, pwt2h, b2, pff2, MROWS, DM, DFF, 0, 0);

    // LN2: out = LN(h + ff)
    ln_residual<<<MROWS, 256>>>(ph, pff2, g2, be2, out, nullptr);
}

// round 14
// speedup vs baseline: 10.2271x; 1.0415x over previous
#include <cuda_runtime.h>
#include <cuda_fp16.h>
#include <math.h>
#include <stdint.h>

// Problem constants
#define BATCH 4
#define SEQ   2048
#define DM    1024
#define NH    16
#define DK    64
#define DFF   4096
#define MROWS (BATCH * SEQ)   // 8192
#define LN_EPS 1e-5f

// ---------------- scratch (device globals; no allocation allowed) ----------------
__device__ __half g_qkvh[(size_t)MROWS * 3 * DM];  // fused QKV (half) for attention
__device__ __half g_xh[MROWS * DM];
__device__ __half g_ctxh[MROWS * DM];
__device__ float  g_attn[MROWS * DM];
__device__ float  g_h[MROWS * DM];
__device__ __half g_hh[MROWS * DM];
__device__ __half g_ff1h[(size_t)MROWS * DFF];
__device__ float  g_ff2[MROWS * DM];
// transposed (+fp16) weights: [N,K] layout
__device__ __half g_wqkvh[(size_t)3 * DM * DM];
__device__ float  g_bqkv[3 * DM];
__device__ __half g_wtoh[DM * DM];
__device__ __half g_wt1h[(size_t)DFF * DM];
__device__ __half g_wt2h[(size_t)DM * DFF];

// ---------------- small helpers ---------------------------------------------------
__device__ __forceinline__ uint32_t smem_u32(const void* p) {
    uint32_t a;
    asm("{ .reg .u64 t; cvta.to.shared.u64 t, %1; cvt.u32.u64 %0, t; }" : "=r"(a) : "l"(p));
    return a;
}

__device__ __forceinline__ void cp16(uint32_t dst, const void* src) {
    asm volatile("cp.async.cg.shared.global [%0], [%1], 16;" :: "r"(dst), "l"(src) : "memory");
}

__device__ __forceinline__ void cp_commit() {
    asm volatile("cp.async.commit_group;" ::: "memory");
}

__device__ __forceinline__ void cp_wait(int pend) {
    if (pend == 0) asm volatile("cp.async.wait_group 0;" ::: "memory");
    else           asm volatile("cp.async.wait_group 1;" ::: "memory");
}

__device__ __forceinline__ void mma_f16(float* c, uint32_t a0, uint32_t a1,
                                        uint32_t a2, uint32_t a3,
                                        uint32_t b0, uint32_t b1) {
    asm volatile(
        "mma.sync.aligned.m16n8k16.row.col.f32.f16.f16.f32 "
        "{%0,%1,%2,%3}, {%4,%5,%6,%7}, {%8,%9}, {%0,%1,%2,%3};"
        : "+f"(c[0]), "+f"(c[1]), "+f"(c[2]), "+f"(c[3])
        : "r"(a0), "r"(a1), "r"(a2), "r"(a3), "r"(b0), "r"(b1));
}

__device__ __forceinline__ void ldsm4(uint32_t& r0, uint32_t& r1, uint32_t& r2,
                                      uint32_t& r3, uint32_t addr) {
    asm volatile("ldmatrix.sync.aligned.m8n8.x4.shared.b16 {%0,%1,%2,%3}, [%4];"
                 : "=r"(r0), "=r"(r1), "=r"(r2), "=r"(r3) : "r"(addr));
}

__device__ __forceinline__ void ldsm4t(uint32_t& r0, uint32_t& r1, uint32_t& r2,
                                       uint32_t& r3, uint32_t addr) {
    asm volatile("ldmatrix.sync.aligned.m8n8.x4.trans.shared.b16 {%0,%1,%2,%3}, [%4];"
                 : "=r"(r0), "=r"(r1), "=r"(r2), "=r"(r3) : "r"(addr));
}

__device__ __forceinline__ uint32_t fh2(float a, float b) {
    __half2 h = __floats2half2_rn(a, b);
    return *(uint32_t*)&h;
}

// ---------------- fp16 mma.sync GEMM — CTA 128x256, 8 warps, warp tile 64x64 -------
// C[M,N] = A[M,K] @ B[N,K]^T + bias, optional relu. mode: 0=float out, 2=half out.
// BK=64 halves, 3-stage cp.async ring, 1 CTA/SM (162KB smem), ~high regs/thread.
// ldsm:mma = 1:4 -> smem-port traffic 0.088 B/MAC.
#define HBK 64
#define HST 72
#define HROWS 384                        // 128 A rows + 256 B rows
#define HSTAGE (HROWS * HST)             // halves per stage
#define HNST 3
#define GEMM_SMEM (HNST * HSTAGE * 2)    // 165888 bytes

__device__ __forceinline__ void h_load_stage(__half* smem, const __half* Ablk,
                                             const __half* Bblk, int K, int s, int tid) {
    __half* As = smem + (s % HNST) * HSTAGE;
    __half* Bs = As + 128 * HST;
    const int k0 = s * HBK;
#pragma unroll
    for (int i = 0; i < 4; i++) {        // A: 128 rows x 8 chunks = 1024
        int c = tid + i * 256;
        int row = c >> 3, col = c & 7;
        cp16(smem_u32(As + row * HST + col * 8), Ablk + (size_t)row * K + k0 + col * 8);
    }
#pragma unroll
    for (int i = 0; i < 8; i++) {        // B: 256 rows x 8 chunks = 2048
        int c = tid + i * 256;
        int row = c >> 3, col = c & 7;
        cp16(smem_u32(Bs + row * HST + col * 8), Bblk + (size_t)row * K + k0 + col * 8);
    }
    cp_commit();
}

__global__ __launch_bounds__(256, 1) void gemm_f16(
    const __half* __restrict__ A, const __half* __restrict__ B,
    const float* __restrict__ bias, void* __restrict__ C,
    int M, int N, int K, int relu, int mode)
{
    extern __shared__ __half hsm[];

    const int tid = threadIdx.x;
    const int wid = tid >> 5;          // 0..7
    const int lane = tid & 31;
    const int g = lane >> 2;
    const int tig = lane & 3;
    const int lr = lane & 7;
    const int sub = lane >> 3;

    const int rowBase = (wid & 1) * 64;    // warpM 0..1
    const int colBase = (wid >> 1) * 64;   // warpN 0..3

    int a_row[4], b_row[4];
#pragma unroll
    for (int ma = 0; ma < 4; ma++)
        a_row[ma] = rowBase + ma * 16 + ((sub & 1) << 3) + lr;
    const int a_koff = (sub >> 1) << 3;
#pragma unroll
    for (int nbp = 0; nbp < 4; nbp++)
        b_row[nbp] = colBase + nbp * 16 + ((sub >> 1) << 3) + lr;
    const int b_koff = (sub & 1) << 3;

    const int bx = blockIdx.x, by = blockIdx.y;
    const __half* Ablk = A + (size_t)by * 128 * K;
    const __half* Bblk = B + (size_t)bx * 256 * K;
    const int nstages = K / HBK;

    float acc[4][8][4];
#pragma unroll
    for (int i = 0; i < 4; i++)
#pragma unroll
        for (int j = 0; j < 8; j++)
#pragma unroll
            for (int q = 0; q < 4; q++) acc[i][j][q] = 0.f;

    h_load_stage(hsm, Ablk, Bblk, K, 0, tid);
    h_load_stage(hsm, Ablk, Bblk, K, 1, tid);

    for (int s = 0; s < nstages; s++) {
        cp_wait((s + 1 < nstages) ? 1 : 0);
        __syncthreads();
        if (s + 2 < nstages) h_load_stage(hsm, Ablk, Bblk, K, s + 2, tid);

        const __half* As = hsm + (s % HNST) * HSTAGE;
        const uint32_t abase = smem_u32(As);
        const uint32_t bbase = smem_u32(As + 128 * HST);

#pragma unroll
        for (int ks = 0; ks < 4; ks++) {
            const int k0 = ks * 16;
            uint32_t a[4][4];
#pragma unroll
            for (int ma = 0; ma < 4; ma++)
                ldsm4(a[ma][0], a[ma][1], a[ma][2], a[ma][3],
                      abase + (uint32_t)(a_row[ma] * HST + k0 + a_koff) * 2u);
            uint32_t bb[4][4];
#pragma unroll
            for (int nbp = 0; nbp < 4; nbp++)
                ldsm4(bb[nbp][0], bb[nbp][1], bb[nbp][2], bb[nbp][3],
                      bbase + (uint32_t)(b_row[nbp] * HST + k0 + b_koff) * 2u);
#pragma unroll
            for (int ma = 0; ma < 4; ma++)
#pragma unroll
                for (int nb = 0; nb < 8; nb++)
                    mma_f16(acc[ma][nb], a[ma][0], a[ma][1], a[ma][2], a[ma][3],
                            bb[nb >> 1][(nb & 1) * 2], bb[nb >> 1][(nb & 1) * 2 + 1]);
        }
    }

#pragma unroll
    for (int ma = 0; ma < 4; ma++) {
        int r0 = by * 128 + rowBase + ma * 16 + g;
        int r1 = r0 + 8;
#pragma unroll
        for (int nb = 0; nb < 8; nb++) {
            int col = bx * 256 + colBase + nb * 8 + 2 * tig;
            float b0 = bias[col], b1 = bias[col + 1];
            float2 v0, v1;
            v0.x = acc[ma][nb][0] + b0;
            v0.y = acc[ma][nb][1] + b1;
            v1.x = acc[ma][nb][2] + b0;
            v1.y = acc[ma][nb][3] + b1;
            if (relu) {
                v0.x = fmaxf(v0.x, 0.f); v0.y = fmaxf(v0.y, 0.f);
                v1.x = fmaxf(v1.x, 0.f); v1.y = fmaxf(v1.y, 0.f);
            }
            if (mode == 2) {
                __half* Ch = (__half*)C;
                *(__half2*)(Ch + (size_t)r0 * N + col) = __floats2half2_rn(v0.x, v0.y);
                *(__half2*)(Ch + (size_t)r1 * N + col) = __floats2half2_rn(v1.x, v1.y);
            } else {
                float* Cf = (float*)C;
                *(float2*)(Cf + (size_t)r0 * N + col) = v0;
                *(float2*)(Cf + (size_t)r1 * N + col) = v1;
            }
        }
    }
}

// ---------------- merged prep kernel (unchanged) -----------------------------------
#define PREP_T_QKVO 4096
#define PREP_T_W1   4096
#define PREP_T_W2   4096
#define PREP_T_COPY 8192
#define PREP_T_BIAS 12
#define PREP_BLOCKS (PREP_T_QKVO + PREP_T_W1 + PREP_T_W2 + PREP_T_COPY + PREP_T_BIAS)

__device__ __forceinline__ void prep_transpose(const float* __restrict__ in,
                                               __half* __restrict__ out,
                                               int K, int N, int bx, int by,
                                               int tx, int ty) {
    __shared__ float t[32][33];
    int x = bx * 32 + tx;
#pragma unroll
    for (int j = 0; j < 32; j += 8)
        t[ty + j][tx] = in[(size_t)(by * 32 + ty + j) * N + x];
    __syncthreads();
    int xo = by * 32 + tx;
#pragma unroll
    for (int j = 0; j < 32; j += 8)
        out[(size_t)(bx * 32 + ty + j) * K + xo] = __float2half_rn(t[tx][ty + j]);
}

__global__ __launch_bounds__(256) void prep_all(
    const float* __restrict__ x,
    const float* __restrict__ w_q, const float* __restrict__ w_k,
    const float* __restrict__ w_v, const float* __restrict__ w_o,
    const float* __restrict__ w1, const float* __restrict__ w2,
    const float* __restrict__ b_q, const float* __restrict__ b_k,
    const float* __restrict__ b_v,
    __half* __restrict__ wqkvh, __half* __restrict__ wtoh,
    __half* __restrict__ wt1h, __half* __restrict__ wt2h,
    __half* __restrict__ xh, float* __restrict__ bqkv)
{
    const int blk = blockIdx.x;
    const int tid = threadIdx.x;
    const int tx = tid & 31;
    const int ty = tid >> 5;

    if (blk < PREP_T_QKVO) {
        int which = blk >> 10;
        int t = blk & 1023;
        int bx = t & 31, by = t >> 5;
        const float* in = (which == 0) ? w_q : (which == 1) ? w_k :
                          (which == 2) ? w_v : w_o;
        __half* out = (which == 0) ? wqkvh :
                      (which == 1) ? wqkvh + DM * DM :
                      (which == 2) ? wqkvh + 2 * DM * DM : wtoh;
        prep_transpose(in, out, DM, DM, bx, by, tx, ty);
    } else if (blk < PREP_T_QKVO + PREP_T_W1) {
        int t = blk - PREP_T_QKVO;
        int bx = t & 127, by = t >> 7;
        prep_transpose(w1, wt1h, DM, DFF, bx, by, tx, ty);
    } else if (blk < PREP_T_QKVO + PREP_T_W1 + PREP_T_W2) {
        int t = blk - PREP_T_QKVO - PREP_T_W1;
        int bx = t & 31, by = t >> 5;
        prep_transpose(w2, wt2h, DFF, DM, bx, by, tx, ty);
    } else if (blk < PREP_T_QKVO + PREP_T_W1 + PREP_T_W2 + PREP_T_COPY) {
        int i = (blk - PREP_T_QKVO - PREP_T_W1 - PREP_T_W2) * 256 + tid;
        float4 v = ((const float4*)x)[i];
        __half2* o = (__half2*)xh;
        o[2 * i + 0] = __floats2half2_rn(v.x, v.y);
        o[2 * i + 1] = __floats2half2_rn(v.z, v.w);
    } else {
        int i = (blk - PREP_T_QKVO - PREP_T_W1 - PREP_T_W2 - PREP_T_COPY) * 256 + tid;
        if (i < DM) bqkv[i] = b_q[i];
        else if (i < 2 * DM) bqkv[i] = b_k[i - DM];
        else if (i < 3 * DM) bqkv[i] = b_v[i - 2 * DM];
    }
}

// ---------------- Flash attention, fully fp16 mma.sync (unchanged) ----------------
#define AQT 128
#define AKT 64
#define NKB (SEQ / AKT)
#define APH 72
#define AH_K 9216
#define AH_V 18432
#define AB_M 55296
#define ATTN_SMEM (AB_M + 2 * 64 * 4)   // 55808 bytes

__device__ __forceinline__ void attn_load_kv(char* smb, const __half* Kb, const __half* Vb,
                                             const int* mb, int buf, int tid, int rstr) {
    __half* Ks = (__half*)smb + AH_K + buf * (AKT * APH);
    __half* Vs = (__half*)smb + AH_V + buf * (AKT * APH);
    int* mk = (int*)(smb + AB_M) + buf * 64;
#pragma unroll
    for (int i = 0; i < 2; i++) {
        int idx = tid + i * 256;
        int r = idx >> 3;
        int c = idx & 7;
        cp16(smem_u32(Ks + r * APH + c * 8), Kb + (size_t)r * rstr + c * 8);
        cp16(smem_u32(Vs + r * APH + c * 8), Vb + (size_t)r * rstr + c * 8);
    }
    if (tid < 16) cp16(smem_u32(mk + tid * 4), mb + tid * 4);
    cp_commit();
}

__global__ __launch_bounds__(256, 2) void attn_mma(
    const __half* __restrict__ Qg, const __half* __restrict__ Kg,
    const __half* __restrict__ Vg, const int* __restrict__ maskg,
    __half* __restrict__ Og, int rstr)
{
    extern __shared__ char asmb[];
    const int tid = threadIdx.x;
    const int warp = tid >> 5;
    const int lane = tid & 31;
    const int g = lane >> 2;
    const int tig = lane & 3;
    const int lr = lane & 7;
    const int sub = lane >> 3;

    const int bh = blockIdx.y;
    const int b = bh >> 4;
    const int h = bh & 15;
    const int qb = blockIdx.x;

    const __half* Qbase = Qg + (size_t)(b * SEQ + qb * AQT) * rstr + h * DK;
    const int* maskp = maskg + b * SEQ;

    {
        __half* Qs = (__half*)asmb;
#pragma unroll
        for (int i = 0; i < 4; i++) {
            int idx = tid + i * 256;
            int r = idx >> 3;
            int c = idx & 7;
            cp16(smem_u32(Qs + r * APH + c * 8), Qbase + (size_t)r * rstr + c * 8);
        }
        cp_commit();
    }
    attn_load_kv(asmb, Kg + (size_t)(b * SEQ) * rstr + h * DK,
                 Vg + (size_t)(b * SEQ) * rstr + h * DK, maskp, 0, tid, rstr);

    const int a_ro = warp * 16 + ((sub & 1) << 3) + lr;
    const int a_ko = (sub >> 1) << 3;
    const int b_ro = ((sub >> 1) << 3) + lr;
    const int b_ko = (sub & 1) << 3;
    const int v_ro = ((sub & 1) << 3) + lr;
    const int v_co = (sub >> 1) << 3;

    cp_wait(1);
    __syncthreads();
    uint32_t qa[4][4];
    {
        uint32_t qbse = smem_u32(asmb);
#pragma unroll
        for (int ks = 0; ks < 4; ks++)
            ldsm4(qa[ks][0], qa[ks][1], qa[ks][2], qa[ks][3],
                  qbse + (uint32_t)(a_ro * APH + ks * 16 + a_ko) * 2u);
    }

    float o[8][4];
#pragma unroll
    for (int nt = 0; nt < 8; nt++)
#pragma unroll
        for (int j = 0; j < 4; j++) o[nt][j] = 0.f;
    float m0 = -1e30f, m1 = -1e30f, l0 = 0.f, l1 = 0.f;

    for (int kb = 0; kb < NKB; kb++) {
        cp_wait(0);
        __syncthreads();
        if (kb + 1 < NKB) {
            const __half* Kb = Kg + (size_t)(b * SEQ + (kb + 1) * AKT) * rstr + h * DK;
            const __half* Vb = Vg + (size_t)(b * SEQ + (kb + 1) * AKT) * rstr + h * DK;
            attn_load_kv(asmb, Kb, Vb, maskp + (kb + 1) * AKT, (kb + 1) & 1, tid, rstr);
        }

        const uint32_t kbse = smem_u32((__half*)asmb + AH_K + (kb & 1) * (AKT * APH));
        const uint32_t vbse = smem_u32((__half*)asmb + AH_V + (kb & 1) * (AKT * APH));
        const int* mk = (const int*)(asmb + AB_M) + (kb & 1) * 64;

        float s[8][4];
#pragma unroll
        for (int nt = 0; nt < 8; nt++)
#pragma unroll
            for (int j = 0; j < 4; j++) s[nt][j] = 0.f;

#pragma unroll
        for (int ks = 0; ks < 4; ks++) {
            uint32_t kf[4][4];
#pragma unroll
            for (int ntp = 0; ntp < 4; ntp++)
                ldsm4(kf[ntp][0], kf[ntp][1], kf[ntp][2], kf[ntp][3],
                      kbse + (uint32_t)((ntp * 16 + b_ro) * APH + ks * 16 + b_ko) * 2u);
#pragma unroll
            for (int nt = 0; nt < 8; nt++)
                mma_f16(s[nt], qa[ks][0], qa[ks][1], qa[ks][2], qa[ks][3],
                        kf[nt >> 1][(nt & 1) * 2], kf[nt >> 1][(nt & 1) * 2 + 1]);
        }

        float mx0 = -1e30f, mx1 = -1e30f;
#pragma unroll
        for (int nt = 0; nt < 8; nt++) {
            int c0 = nt * 8 + 2 * tig;
            int mk0v = mk[c0];
            int mk1v = mk[c0 + 1];
            float v0 = s[nt][0] * 0.125f; if (mk0v == 0) v0 = -1e30f;
            float v1 = s[nt][1] * 0.125f; if (mk1v == 0) v1 = -1e30f;
            float v2 = s[nt][2] * 0.125f; if (mk0v == 0) v2 = -1e30f;
            float v3 = s[nt][3] * 0.125f; if (mk1v == 0) v3 = -1e30f;
            s[nt][0] = v0; s[nt][1] = v1; s[nt][2] = v2; s[nt][3] = v3;
            mx0 = fmaxf(mx0, fmaxf(v0, v1));
            mx1 = fmaxf(mx1, fmaxf(v2, v3));
        }
        mx0 = fmaxf(mx0, __shfl_xor_sync(0xffffffffu, mx0, 1));
        mx0 = fmaxf(mx0, __shfl_xor_sync(0xffffffffu, mx0, 2));
        mx1 = fmaxf(mx1, __shfl_xor_sync(0xffffffffu, mx1, 1));
        mx1 = fmaxf(mx1, __shfl_xor_sync(0xffffffffu, mx1, 2));

        float mn0 = fmaxf(m0, mx0);
        float mn1 = fmaxf(m1, mx1);
        float corr0 = __expf(m0 - mn0);
        float corr1 = __expf(m1 - mn1);
        m0 = mn0; m1 = mn1;

        float ps0 = 0.f, ps1 = 0.f;
#pragma unroll
        for (int nt = 0; nt < 8; nt++) {
            float p0 = __expf(s[nt][0] - mn0);
            float p1 = __expf(s[nt][1] - mn0);
            float p2 = __expf(s[nt][2] - mn1);
            float p3 = __expf(s[nt][3] - mn1);
            ps0 += p0 + p1;
            ps1 += p2 + p3;
            s[nt][0] = p0; s[nt][1] = p1; s[nt][2] = p2; s[nt][3] = p3;
        }
        ps0 += __shfl_xor_sync(0xffffffffu, ps0, 1);
        ps0 += __shfl_xor_sync(0xffffffffu, ps0, 2);
        ps1 += __shfl_xor_sync(0xffffffffu, ps1, 1);
        ps1 += __shfl_xor_sync(0xffffffffu, ps1, 2);
        l0 = l0 * corr0 + ps0;
        l1 = l1 * corr1 + ps1;

#pragma unroll
        for (int nt = 0; nt < 8; nt++) {
            o[nt][0] *= corr0; o[nt][1] *= corr0;
            o[nt][2] *= corr1; o[nt][3] *= corr1;
        }

#pragma unroll
        for (int ks = 0; ks < 4; ks++) {
            uint32_t pa0 = fh2(s[2 * ks][0],     s[2 * ks][1]);
            uint32_t pa1 = fh2(s[2 * ks][2],     s[2 * ks][3]);
            uint32_t pa2 = fh2(s[2 * ks + 1][0], s[2 * ks + 1][1]);
            uint32_t pa3 = fh2(s[2 * ks + 1][2], s[2 * ks + 1][3]);
#pragma unroll
            for (int dp = 0; dp < 4; dp++) {
                uint32_t vf[4];
                ldsm4t(vf[0], vf[1], vf[2], vf[3],
                       vbse + (uint32_t)((ks * 16 + v_ro) * APH + dp * 16 + v_co) * 2u);
                mma_f16(o[2 * dp],     pa0, pa1, pa2, pa3, vf[0], vf[1]);
                mma_f16(o[2 * dp + 1], pa0, pa1, pa2, pa3, vf[2], vf[3]);
            }
        }
    }

    float inv0 = 1.f / l0;
    float inv1 = 1.f / l1;
    int grow = b * SEQ + qb * AQT + warp * 16 + g;
#pragma unroll
    for (int nt = 0; nt < 8; nt++) {
        int col = h * DK + nt * 8 + 2 * tig;
        *(__half2*)(Og + (size_t)grow * DM + col) =
            __floats2half2_rn(o[nt][0] * inv0, o[nt][1] * inv0);
        *(__half2*)(Og + (size_t)(grow + 8) * DM + col) =
            __floats2half2_rn(o[nt][2] * inv1, o[nt][3] * inv1);
    }
}

// ---------------- fused residual + LayerNorm (float4 vectorized) ------------------
__global__ __launch_bounds__(256) void ln_residual(
    const float* __restrict__ X, const float* __restrict__ R,
    const float* __restrict__ gamma, const float* __restrict__ beta,
    float* __restrict__ out, __half* __restrict__ outh)
{
    const int row = blockIdx.x;
    const int tid = threadIdx.x;
    const float4* x4 = (const float4*)(X + (size_t)row * DM);
    const float4* r4 = (const float4*)(R + (size_t)row * DM);

    float4 xv = x4[tid];
    float4 rv = r4[tid];
    float4 v;
    v.x = xv.x + rv.x; v.y = xv.y + rv.y;
    v.z = xv.z + rv.z; v.w = xv.w + rv.w;
    float sum = v.x + v.y + v.z + v.w;
    float sumsq = v.x * v.x + v.y * v.y + v.z * v.z + v.w * v.w;

    __shared__ float2 wred[8];
    __shared__ float2 fin;
    float2 agg = make_float2(sum, sumsq);
#pragma unroll
    for (int off = 16; off > 0; off >>= 1) {
        agg.x += __shfl_xor_sync(0xffffffffu, agg.x, off);
        agg.y += __shfl_xor_sync(0xffffffffu, agg.y, off);
    }
    const int warp = tid >> 5, lane = tid & 31;
    if (lane == 0) wred[warp] = agg;
    __syncthreads();
    if (warp == 0) {
        float2 a = (lane < 8) ? wred[lane] : make_float2(0.f, 0.f);
#pragma unroll
        for (int off = 4; off > 0; off >>= 1) {
            a.x += __shfl_xor_sync(0xffffffffu, a.x, off);
            a.y += __shfl_xor_sync(0xffffffffu, a.y, off);
        }
        if (lane == 0) fin = a;
    }
    __syncthreads();

    float mu = fin.x * (1.f / DM);
    float var = fin.y * (1.f / DM) - mu * mu;
    float rstd = rsqrtf(var + LN_EPS);

    float4 gv = ((const float4*)gamma)[tid];
    float4 bv = ((const float4*)beta)[tid];
    float4 y;
    y.x = (v.x - mu) * rstd * gv.x + bv.x;
    y.y = (v.y - mu) * rstd * gv.y + bv.y;
    y.z = (v.z - mu) * rstd * gv.z + bv.z;
    y.w = (v.w - mu) * rstd * gv.w + bv.w;
    ((float4*)(out + (size_t)row * DM))[tid] = y;
    if (outh) {
        __half2* oh = (__half2*)(outh + (size_t)row * DM);
        oh[2 * tid + 0] = __floats2half2_rn(y.x, y.y);
        oh[2 * tid + 1] = __floats2half2_rn(y.z, y.w);
    }
}

// ---------------- launch ----------------------------------------------------------
extern "C" void kernel_launch(void* const* d_in, const int* in_sizes, int n_in,
                              void* d_out, int out_size)
{
    const float* x    = (const float*)d_in[0];
    const int*   mask = (const int*)  d_in[1];
    const float* w_q  = (const float*)d_in[2];
    const float* b_q  = (const float*)d_in[3];
    const float* w_k  = (const float*)d_in[4];
    const float* b_k  = (const float*)d_in[5];
    const float* w_v  = (const float*)d_in[6];
    const float* b_v  = (const float*)d_in[7];
    const float* w_o  = (const float*)d_in[8];
    const float* b_o  = (const float*)d_in[9];
    const float* w1   = (const float*)d_in[10];
    const float* b1   = (const float*)d_in[11];
    const float* w2   = (const float*)d_in[12];
    const float* b2   = (const float*)d_in[13];
    const float* g1   = (const float*)d_in[14];
    const float* be1  = (const float*)d_in[15];
    const float* g2   = (const float*)d_in[16];
    const float* be2  = (const float*)d_in[17];
    float* out = (float*)d_out;

    float *pattn, *ph, *pff2, *pbqkv;
    __half *pqkvh, *pxh, *pctxh, *phh, *pff1h, *pwqkvh, *pwtoh, *pwt1h, *pwt2h;
    cudaGetSymbolAddress((void**)&pattn,  g_attn);
    cudaGetSymbolAddress((void**)&ph,     g_h);
    cudaGetSymbolAddress((void**)&pff2,   g_ff2);
    cudaGetSymbolAddress((void**)&pbqkv,  g_bqkv);
    cudaGetSymbolAddress((void**)&pqkvh,  g_qkvh);
    cudaGetSymbolAddress((void**)&pxh,    g_xh);
    cudaGetSymbolAddress((void**)&pctxh,  g_ctxh);
    cudaGetSymbolAddress((void**)&phh,    g_hh);
    cudaGetSymbolAddress((void**)&pff1h,  g_ff1h);
    cudaGetSymbolAddress((void**)&pwqkvh, g_wqkvh);
    cudaGetSymbolAddress((void**)&pwtoh,  g_wtoh);
    cudaGetSymbolAddress((void**)&pwt1h,  g_wt1h);
    cudaGetSymbolAddress((void**)&pwt2h,  g_wt2h);

    cudaFuncSetAttribute(gemm_f16, cudaFuncAttributeMaxDynamicSharedMemorySize, GEMM_SMEM);
    cudaFuncSetAttribute(attn_mma, cudaFuncAttributeMaxDynamicSharedMemorySize, ATTN_SMEM);

    dim3 gQKV(3 * DM / 256, MROWS / 128);  // (12, 64)
    dim3 gD(DM / 256, MROWS / 128);        // (4, 64)
    dim3 gF1(DFF / 256, MROWS / 128);      // (16, 64)

    // ALL prep in one launch: 6 transposes + bias concat + x->half
    prep_all<<<PREP_BLOCKS, 256>>>(x, w_q, w_k, w_v, w_o, w1, w2, b_q, b_k, b_v,
                                   pwqkvh, pwtoh, pwt1h, pwt2h, pxh, pbqkv);

    // fused QKV projection (fp16 mma; half output feeds fp16 attention)
    gemm_f16<<<gQKV, 256, GEMM_SMEM>>>(pxh, pwqkvh, pbqkv, pqkvh, MROWS, 3 * DM, DM, 0, 2);

    // flash attention (fp16 mma), half output for O-projection
    attn_mma<<<dim3(SEQ / AQT, BATCH * NH), 256, ATTN_SMEM>>>(
        pqkvh, pqkvh + DM, pqkvh + 2 * DM, mask, pctxh, 3 * DM);

    // output projection (fp16)
    gemm_f16<<<gD, 256, GEMM_SMEM>>>(pctxh, pwtoh, b_o, pattn, MROWS, DM, DM, 0, 0);

    // LN1: h = LN(x + attn_out); hh = half copy
    ln_residual<<<MROWS, 256>>>(x, pattn, g1, be1, ph, phh);

    // FFN (fp16; ff1 stored half directly)
    gemm_f16<<<gF1, 256, GEMM_SMEM>>>(phh, pwt1h, b1, pff1h, MROWS, DFF, DM, 1, 2);
    gemm_f16<<<gD, 256, GEMM_SMEM>>>(pff1h, pwt2h, b2, pff2, MROWS, DM, DFF, 0, 0);

    // LN2: out = LN(h + ff)
    ln_residual<<<MROWS, 256>>>(ph, pff2, g2, be2, out, nullptr);
}

// round 15
// speedup vs baseline: 11.0174x; 1.0773x over previous
#include <cuda_runtime.h>
#include <cuda_fp16.h>
#include <math.h>
#include <stdint.h>

// Problem constants
#define BATCH 4
#define SEQ   2048
#define DM    1024
#define NH    16
#define DK    64
#define DFF   4096
#define MROWS (BATCH * SEQ)   // 8192
#define LN_EPS 1e-5f

// ---------------- scratch (device globals; no allocation allowed) ----------------
__device__ __half g_qkvh[(size_t)MROWS * 3 * DM];  // fused QKV (half) for attention
__device__ __half g_xh[MROWS * DM];
__device__ __half g_ctxh[MROWS * DM];
__device__ float  g_attn[MROWS * DM];
__device__ float  g_h[MROWS * DM];
__device__ __half g_hh[MROWS * DM];
__device__ __half g_ff1h[(size_t)MROWS * DFF];
__device__ float  g_ff2[MROWS * DM];
// transposed (+fp16) weights: [N,K] layout
__device__ __half g_wqkvh[(size_t)3 * DM * DM];
__device__ float  g_bqkv[3 * DM];
__device__ __half g_wtoh[DM * DM];
__device__ __half g_wt1h[(size_t)DFF * DM];
__device__ __half g_wt2h[(size_t)DM * DFF];

// ---------------- small helpers ---------------------------------------------------
__device__ __forceinline__ uint32_t smem_u32(const void* p) {
    uint32_t a;
    asm("{ .reg .u64 t; cvta.to.shared.u64 t, %1; cvt.u32.u64 %0, t; }" : "=r"(a) : "l"(p));
    return a;
}

__device__ __forceinline__ void cp16(uint32_t dst, const void* src) {
    asm volatile("cp.async.cg.shared.global [%0], [%1], 16;" :: "r"(dst), "l"(src) : "memory");
}

__device__ __forceinline__ void cp_commit() {
    asm volatile("cp.async.commit_group;" ::: "memory");
}

__device__ __forceinline__ void cp_wait(int pend) {
    if (pend == 0) asm volatile("cp.async.wait_group 0;" ::: "memory");
    else           asm volatile("cp.async.wait_group 1;" ::: "memory");
}

__device__ __forceinline__ void mma_f16(float* c, uint32_t a0, uint32_t a1,
                                        uint32_t a2, uint32_t a3,
                                        uint32_t b0, uint32_t b1) {
    asm volatile(
        "mma.sync.aligned.m16n8k16.row.col.f32.f16.f16.f32 "
        "{%0,%1,%2,%3}, {%4,%5,%6,%7}, {%8,%9}, {%0,%1,%2,%3};"
        : "+f"(c[0]), "+f"(c[1]), "+f"(c[2]), "+f"(c[3])
        : "r"(a0), "r"(a1), "r"(a2), "r"(a3), "r"(b0), "r"(b1));
}

__device__ __forceinline__ void ldsm4(uint32_t& r0, uint32_t& r1, uint32_t& r2,
                                      uint32_t& r3, uint32_t addr) {
    asm volatile("ldmatrix.sync.aligned.m8n8.x4.shared.b16 {%0,%1,%2,%3}, [%4];"
                 : "=r"(r0), "=r"(r1), "=r"(r2), "=r"(r3) : "r"(addr));
}

__device__ __forceinline__ void ldsm4t(uint32_t& r0, uint32_t& r1, uint32_t& r2,
                                       uint32_t& r3, uint32_t addr) {
    asm volatile("ldmatrix.sync.aligned.m8n8.x4.trans.shared.b16 {%0,%1,%2,%3}, [%4];"
                 : "=r"(r0), "=r"(r1), "=r"(r2), "=r"(r3) : "r"(addr));
}

__device__ __forceinline__ uint32_t fh2(float a, float b) {
    __half2 h = __floats2half2_rn(a, b);
    return *(uint32_t*)&h;
}

// ---------------- fp16 mma.sync GEMM — CTA 128x128, 4 warps, warp tile 64x64 -------
// C[M,N] = A[M,K] @ B[N,K]^T + bias, optional relu. mode: 0=float out, 2=half out.
// BK=64 halves, 3-stage cp.async ring, 110.6KB smem -> 2 CTAs/SM: two independent
// pipelines per SM (staggered barriers) while keeping ldsm:mma = 1:4 reuse.
#define HBK 64
#define HST 72
#define HROWS 256                        // 128 A rows + 128 B rows
#define HSTAGE (HROWS * HST)             // halves per stage
#define HNST 3
#define GEMM_SMEM (HNST * HSTAGE * 2)    // 110592 bytes

__device__ __forceinline__ void h_load_stage(__half* smem, const __half* Ablk,
                                             const __half* Bblk, int K, int s, int tid) {
    __half* As = smem + (s % HNST) * HSTAGE;
    __half* Bs = As + 128 * HST;
    const int k0 = s * HBK;
#pragma unroll
    for (int i = 0; i < 8; i++) {        // A: 128 rows x 8 chunks = 1024
        int c = tid + i * 128;
        int row = c >> 3, col = c & 7;
        cp16(smem_u32(As + row * HST + col * 8), Ablk + (size_t)row * K + k0 + col * 8);
    }
#pragma unroll
    for (int i = 0; i < 8; i++) {        // B: 128 rows x 8 chunks = 1024
        int c = tid + i * 128;
        int row = c >> 3, col = c & 7;
        cp16(smem_u32(Bs + row * HST + col * 8), Bblk + (size_t)row * K + k0 + col * 8);
    }
    cp_commit();
}

__global__ __launch_bounds__(128, 2) void gemm_f16(
    const __half* __restrict__ A, const __half* __restrict__ B,
    const float* __restrict__ bias, void* __restrict__ C,
    int M, int N, int K, int relu, int mode)
{
    extern __shared__ __half hsm[];

    const int tid = threadIdx.x;
    const int wid = tid >> 5;          // 0..3
    const int lane = tid & 31;
    const int g = lane >> 2;
    const int tig = lane & 3;
    const int lr = lane & 7;
    const int sub = lane >> 3;

    const int rowBase = (wid & 1) * 64;    // warpM 0..1
    const int colBase = (wid >> 1) * 64;   // warpN 0..1

    int a_row[4], b_row[4];
#pragma unroll
    for (int ma = 0; ma < 4; ma++)
        a_row[ma] = rowBase + ma * 16 + ((sub & 1) << 3) + lr;
    const int a_koff = (sub >> 1) << 3;
#pragma unroll
    for (int nbp = 0; nbp < 4; nbp++)
        b_row[nbp] = colBase + nbp * 16 + ((sub >> 1) << 3) + lr;
    const int b_koff = (sub & 1) << 3;

    const int bx = blockIdx.x, by = blockIdx.y;
    const __half* Ablk = A + (size_t)by * 128 * K;
    const __half* Bblk = B + (size_t)bx * 128 * K;
    const int nstages = K / HBK;

    float acc[4][8][4];
#pragma unroll
    for (int i = 0; i < 4; i++)
#pragma unroll
        for (int j = 0; j < 8; j++)
#pragma unroll
            for (int q = 0; q < 4; q++) acc[i][j][q] = 0.f;

    h_load_stage(hsm, Ablk, Bblk, K, 0, tid);
    h_load_stage(hsm, Ablk, Bblk, K, 1, tid);

    for (int s = 0; s < nstages; s++) {
        cp_wait((s + 1 < nstages) ? 1 : 0);
        __syncthreads();
        if (s + 2 < nstages) h_load_stage(hsm, Ablk, Bblk, K, s + 2, tid);

        const __half* As = hsm + (s % HNST) * HSTAGE;
        const uint32_t abase = smem_u32(As);
        const uint32_t bbase = smem_u32(As + 128 * HST);

#pragma unroll
        for (int ks = 0; ks < 4; ks++) {
            const int k0 = ks * 16;
            uint32_t a[4][4];
#pragma unroll
            for (int ma = 0; ma < 4; ma++)
                ldsm4(a[ma][0], a[ma][1], a[ma][2], a[ma][3],
                      abase + (uint32_t)(a_row[ma] * HST + k0 + a_koff) * 2u);
            uint32_t bb[4][4];
#pragma unroll
            for (int nbp = 0; nbp < 4; nbp++)
                ldsm4(bb[nbp][0], bb[nbp][1], bb[nbp][2], bb[nbp][3],
                      bbase + (uint32_t)(b_row[nbp] * HST + k0 + b_koff) * 2u);
#pragma unroll
            for (int ma = 0; ma < 4; ma++)
#pragma unroll
                for (int nb = 0; nb < 8; nb++)
                    mma_f16(acc[ma][nb], a[ma][0], a[ma][1], a[ma][2], a[ma][3],
                            bb[nb >> 1][(nb & 1) * 2], bb[nb >> 1][(nb & 1) * 2 + 1]);
        }
    }

#pragma unroll
    for (int ma = 0; ma < 4; ma++) {
        int r0 = by * 128 + rowBase + ma * 16 + g;
        int r1 = r0 + 8;
#pragma unroll
        for (int nb = 0; nb < 8; nb++) {
            int col = bx * 128 + colBase + nb * 8 + 2 * tig;
            float b0 = bias[col], b1 = bias[col + 1];
            float2 v0, v1;
            v0.x = acc[ma][nb][0] + b0;
            v0.y = acc[ma][nb][1] + b1;
            v1.x = acc[ma][nb][2] + b0;
            v1.y = acc[ma][nb][3] + b1;
            if (relu) {
                v0.x = fmaxf(v0.x, 0.f); v0.y = fmaxf(v0.y, 0.f);
                v1.x = fmaxf(v1.x, 0.f); v1.y = fmaxf(v1.y, 0.f);
            }
            if (mode == 2) {
                __half* Ch = (__half*)C;
                *(__half2*)(Ch + (size_t)r0 * N + col) = __floats2half2_rn(v0.x, v0.y);
                *(__half2*)(Ch + (size_t)r1 * N + col) = __floats2half2_rn(v1.x, v1.y);
            } else {
                float* Cf = (float*)C;
                *(float2*)(Cf + (size_t)r0 * N + col) = v0;
                *(float2*)(Cf + (size_t)r1 * N + col) = v1;
            }
        }
    }
}

// ---------------- merged prep kernel (unchanged) -----------------------------------
#define PREP_T_QKVO 4096
#define PREP_T_W1   4096
#define PREP_T_W2   4096
#define PREP_T_COPY 8192
#define PREP_T_BIAS 12
#define PREP_BLOCKS (PREP_T_QKVO + PREP_T_W1 + PREP_T_W2 + PREP_T_COPY + PREP_T_BIAS)

__device__ __forceinline__ void prep_transpose(const float* __restrict__ in,
                                               __half* __restrict__ out,
                                               int K, int N, int bx, int by,
                                               int tx, int ty) {
    __shared__ float t[32][33];
    int x = bx * 32 + tx;
#pragma unroll
    for (int j = 0; j < 32; j += 8)
        t[ty + j][tx] = in[(size_t)(by * 32 + ty + j) * N + x];
    __syncthreads();
    int xo = by * 32 + tx;
#pragma unroll
    for (int j = 0; j < 32; j += 8)
        out[(size_t)(bx * 32 + ty + j) * K + xo] = __float2half_rn(t[tx][ty + j]);
}

__global__ __launch_bounds__(256) void prep_all(
    const float* __restrict__ x,
    const float* __restrict__ w_q, const float* __restrict__ w_k,
    const float* __restrict__ w_v, const float* __restrict__ w_o,
    const float* __restrict__ w1, const float* __restrict__ w2,
    const float* __restrict__ b_q, const float* __restrict__ b_k,
    const float* __restrict__ b_v,
    __half* __restrict__ wqkvh, __half* __restrict__ wtoh,
    __half* __restrict__ wt1h, __half* __restrict__ wt2h,
    __half* __restrict__ xh, float* __restrict__ bqkv)
{
    const int blk = blockIdx.x;
    const int tid = threadIdx.x;
    const int tx = tid & 31;
    const int ty = tid >> 5;

    if (blk < PREP_T_QKVO) {
        int which = blk >> 10;
        int t = blk & 1023;
        int bx = t & 31, by = t >> 5;
        const float* in = (which == 0) ? w_q : (which == 1) ? w_k :
                          (which == 2) ? w_v : w_o;
        __half* out = (which == 0) ? wqkvh :
                      (which == 1) ? wqkvh + DM * DM :
                      (which == 2) ? wqkvh + 2 * DM * DM : wtoh;
        prep_transpose(in, out, DM, DM, bx, by, tx, ty);
    } else if (blk < PREP_T_QKVO + PREP_T_W1) {
        int t = blk - PREP_T_QKVO;
        int bx = t & 127, by = t >> 7;
        prep_transpose(w1, wt1h, DM, DFF, bx, by, tx, ty);
    } else if (blk < PREP_T_QKVO + PREP_T_W1 + PREP_T_W2) {
        int t = blk - PREP_T_QKVO - PREP_T_W1;
        int bx = t & 31, by = t >> 5;
        prep_transpose(w2, wt2h, DFF, DM, bx, by, tx, ty);
    } else if (blk < PREP_T_QKVO + PREP_T_W1 + PREP_T_W2 + PREP_T_COPY) {
        int i = (blk - PREP_T_QKVO - PREP_T_W1 - PREP_T_W2) * 256 + tid;
        float4 v = ((const float4*)x)[i];
        __half2* o = (__half2*)xh;
        o[2 * i + 0] = __floats2half2_rn(v.x, v.y);
        o[2 * i + 1] = __floats2half2_rn(v.z, v.w);
    } else {
        int i = (blk - PREP_T_QKVO - PREP_T_W1 - PREP_T_W2 - PREP_T_COPY) * 256 + tid;
        if (i < DM) bqkv[i] = b_q[i];
        else if (i < 2 * DM) bqkv[i] = b_k[i - DM];
        else if (i < 3 * DM) bqkv[i] = b_v[i - 2 * DM];
    }
}

// ---------------- Flash attention, fully fp16 mma.sync (unchanged) ----------------
#define AQT 128
#define AKT 64
#define NKB (SEQ / AKT)
#define APH 72
#define AH_K 9216
#define AH_V 18432
#define AB_M 55296
#define ATTN_SMEM (AB_M + 2 * 64 * 4)   // 55808 bytes

__device__ __forceinline__ void attn_load_kv(char* smb, const __half* Kb, const __half* Vb,
                                             const int* mb, int buf, int tid, int rstr) {
    __half* Ks = (__half*)smb + AH_K + buf * (AKT * APH);
    __half* Vs = (__half*)smb + AH_V + buf * (AKT * APH);
    int* mk = (int*)(smb + AB_M) + buf * 64;
#pragma unroll
    for (int i = 0; i < 2; i++) {
        int idx = tid + i * 256;
        int r = idx >> 3;
        int c = idx & 7;
        cp16(smem_u32(Ks + r * APH + c * 8), Kb + (size_t)r * rstr + c * 8);
        cp16(smem_u32(Vs + r * APH + c * 8), Vb + (size_t)r * rstr + c * 8);
    }
    if (tid < 16) cp16(smem_u32(mk + tid * 4), mb + tid * 4);
    cp_commit();
}

__global__ __launch_bounds__(256, 2) void attn_mma(
    const __half* __restrict__ Qg, const __half* __restrict__ Kg,
    const __half* __restrict__ Vg, const int* __restrict__ maskg,
    __half* __restrict__ Og, int rstr)
{
    extern __shared__ char asmb[];
    const int tid = threadIdx.x;
    const int warp = tid >> 5;
    const int lane = tid & 31;
    const int g = lane >> 2;
    const int tig = lane & 3;
    const int lr = lane & 7;
    const int sub = lane >> 3;

    const int bh = blockIdx.y;
    const int b = bh >> 4;
    const int h = bh & 15;
    const int qb = blockIdx.x;

    const __half* Qbase = Qg + (size_t)(b * SEQ + qb * AQT) * rstr + h * DK;
    const int* maskp = maskg + b * SEQ;

    {
        __half* Qs = (__half*)asmb;
#pragma unroll
        for (int i = 0; i < 4; i++) {
            int idx = tid + i * 256;
            int r = idx >> 3;
            int c = idx & 7;
            cp16(smem_u32(Qs + r * APH + c * 8), Qbase + (size_t)r * rstr + c * 8);
        }
        cp_commit();
    }
    attn_load_kv(asmb, Kg + (size_t)(b * SEQ) * rstr + h * DK,
                 Vg + (size_t)(b * SEQ) * rstr + h * DK, maskp, 0, tid, rstr);

    const int a_ro = warp * 16 + ((sub & 1) << 3) + lr;
    const int a_ko = (sub >> 1) << 3;
    const int b_ro = ((sub >> 1) << 3) + lr;
    const int b_ko = (sub & 1) << 3;
    const int v_ro = ((sub & 1) << 3) + lr;
    const int v_co = (sub >> 1) << 3;

    cp_wait(1);
    __syncthreads();
    uint32_t qa[4][4];
    {
        uint32_t qbse = smem_u32(asmb);
#pragma unroll
        for (int ks = 0; ks < 4; ks++)
            ldsm4(qa[ks][0], qa[ks][1], qa[ks][2], qa[ks][3],
                  qbse + (uint32_t)(a_ro * APH + ks * 16 + a_ko) * 2u);
    }

    float o[8][4];
#pragma unroll
    for (int nt = 0; nt < 8; nt++)
#pragma unroll
        for (int j = 0; j < 4; j++) o[nt][j] = 0.f;
    float m0 = -1e30f, m1 = -1e30f, l0 = 0.f, l1 = 0.f;

    for (int kb = 0; kb < NKB; kb++) {
        cp_wait(0);
        __syncthreads();
        if (kb + 1 < NKB) {
            const __half* Kb = Kg + (size_t)(b * SEQ + (kb + 1) * AKT) * rstr + h * DK;
            const __half* Vb = Vg + (size_t)(b * SEQ + (kb + 1) * AKT) * rstr + h * DK;
            attn_load_kv(asmb, Kb, Vb, maskp + (kb + 1) * AKT, (kb + 1) & 1, tid, rstr);
        }

        const uint32_t kbse = smem_u32((__half*)asmb + AH_K + (kb & 1) * (AKT * APH));
        const uint32_t vbse = smem_u32((__half*)asmb + AH_V + (kb & 1) * (AKT * APH));
        const int* mk = (const int*)(asmb + AB_M) + (kb & 1) * 64;

        float s[8][4];
#pragma unroll
        for (int nt = 0; nt < 8; nt++)
#pragma unroll
            for (int j = 0; j < 4; j++) s[nt][j] = 0.f;

#pragma unroll
        for (int ks = 0; ks < 4; ks++) {
            uint32_t kf[4][4];
#pragma unroll
            for (int ntp = 0; ntp < 4; ntp++)
                ldsm4(kf[ntp][0], kf[ntp][1], kf[ntp][2], kf[ntp][3],
                      kbse + (uint32_t)((ntp * 16 + b_ro) * APH + ks * 16 + b_ko) * 2u);
#pragma unroll
            for (int nt = 0; nt < 8; nt++)
                mma_f16(s[nt], qa[ks][0], qa[ks][1], qa[ks][2], qa[ks][3],
                        kf[nt >> 1][(nt & 1) * 2], kf[nt >> 1][(nt & 1) * 2 + 1]);
        }

        float mx0 = -1e30f, mx1 = -1e30f;
#pragma unroll
        for (int nt = 0; nt < 8; nt++) {
            int c0 = nt * 8 + 2 * tig;
            int mk0v = mk[c0];
            int mk1v = mk[c0 + 1];
            float v0 = s[nt][0] * 0.125f; if (mk0v == 0) v0 = -1e30f;
            float v1 = s[nt][1] * 0.125f; if (mk1v == 0) v1 = -1e30f;
            float v2 = s[nt][2] * 0.125f; if (mk0v == 0) v2 = -1e30f;
            float v3 = s[nt][3] * 0.125f; if (mk1v == 0) v3 = -1e30f;
            s[nt][0] = v0; s[nt][1] = v1; s[nt][2] = v2; s[nt][3] = v3;
            mx0 = fmaxf(mx0, fmaxf(v0, v1));
            mx1 = fmaxf(mx1, fmaxf(v2, v3));
        }
        mx0 = fmaxf(mx0, __shfl_xor_sync(0xffffffffu, mx0, 1));
        mx0 = fmaxf(mx0, __shfl_xor_sync(0xffffffffu, mx0, 2));
        mx1 = fmaxf(mx1, __shfl_xor_sync(0xffffffffu, mx1, 1));
        mx1 = fmaxf(mx1, __shfl_xor_sync(0xffffffffu, mx1, 2));

        float mn0 = fmaxf(m0, mx0);
        float mn1 = fmaxf(m1, mx1);
        float corr0 = __expf(m0 - mn0);
        float corr1 = __expf(m1 - mn1);
        m0 = mn0; m1 = mn1;

        float ps0 = 0.f, ps1 = 0.f;
#pragma unroll
        for (int nt = 0; nt < 8; nt++) {
            float p0 = __expf(s[nt][0] - mn0);
            float p1 = __expf(s[nt][1] - mn0);
            float p2 = __expf(s[nt][2] - mn1);
            float p3 = __expf(s[nt][3] - mn1);
            ps0 += p0 + p1;
            ps1 += p2 + p3;
            s[nt][0] = p0; s[nt][1] = p1; s[nt][2] = p2; s[nt][3] = p3;
        }
        ps0 += __shfl_xor_sync(0xffffffffu, ps0, 1);
        ps0 += __shfl_xor_sync(0xffffffffu, ps0, 2);
        ps1 += __shfl_xor_sync(0xffffffffu, ps1, 1);
        ps1 += __shfl_xor_sync(0xffffffffu, ps1, 2);
        l0 = l0 * corr0 + ps0;
        l1 = l1 * corr1 + ps1;

#pragma unroll
        for (int nt = 0; nt < 8; nt++) {
            o[nt][0] *= corr0; o[nt][1] *= corr0;
            o[nt][2] *= corr1; o[nt][3] *= corr1;
        }

#pragma unroll
        for (int ks = 0; ks < 4; ks++) {
            uint32_t pa0 = fh2(s[2 * ks][0],     s[2 * ks][1]);
            uint32_t pa1 = fh2(s[2 * ks][2],     s[2 * ks][3]);
            uint32_t pa2 = fh2(s[2 * ks + 1][0], s[2 * ks + 1][1]);
            uint32_t pa3 = fh2(s[2 * ks + 1][2], s[2 * ks + 1][3]);
#pragma unroll
            for (int dp = 0; dp < 4; dp++) {
                uint32_t vf[4];
                ldsm4t(vf[0], vf[1], vf[2], vf[3],
                       vbse + (uint32_t)((ks * 16 + v_ro) * APH + dp * 16 + v_co) * 2u);
                mma_f16(o[2 * dp],     pa0, pa1, pa2, pa3, vf[0], vf[1]);
                mma_f16(o[2 * dp + 1], pa0, pa1, pa2, pa3, vf[2], vf[3]);
            }
        }
    }

    float inv0 = 1.f / l0;
    float inv1 = 1.f / l1;
    int grow = b * SEQ + qb * AQT + warp * 16 + g;
#pragma unroll
    for (int nt = 0; nt < 8; nt++) {
        int col = h * DK + nt * 8 + 2 * tig;
        *(__half2*)(Og + (size_t)grow * DM + col) =
            __floats2half2_rn(o[nt][0] * inv0, o[nt][1] * inv0);
        *(__half2*)(Og + (size_t)(grow + 8) * DM + col) =
            __floats2half2_rn(o[nt][2] * inv1, o[nt][3] * inv1);
    }
}

// ---------------- fused residual + LayerNorm (float4 vectorized) ------------------
__global__ __launch_bounds__(256) void ln_residual(
    const float* __restrict__ X, const float* __restrict__ R,
    const float* __restrict__ gamma, const float* __restrict__ beta,
    float* __restrict__ out, __half* __restrict__ outh)
{
    const int row = blockIdx.x;
    const int tid = threadIdx.x;
    const float4* x4 = (const float4*)(X + (size_t)row * DM);
    const float4* r4 = (const float4*)(R + (size_t)row * DM);

    float4 xv = x4[tid];
    float4 rv = r4[tid];
    float4 v;
    v.x = xv.x + rv.x; v.y = xv.y + rv.y;
    v.z = xv.z + rv.z; v.w = xv.w + rv.w;
    float sum = v.x + v.y + v.z + v.w;
    float sumsq = v.x * v.x + v.y * v.y + v.z * v.z + v.w * v.w;

    __shared__ float2 wred[8];
    __shared__ float2 fin;
    float2 agg = make_float2(sum, sumsq);
#pragma unroll
    for (int off = 16; off > 0; off >>= 1) {
        agg.x += __shfl_xor_sync(0xffffffffu, agg.x, off);
        agg.y += __shfl_xor_sync(0xffffffffu, agg.y, off);
    }
    const int warp = tid >> 5, lane = tid & 31;
    if (lane == 0) wred[warp] = agg;
    __syncthreads();
    if (warp == 0) {
        float2 a = (lane < 8) ? wred[lane] : make_float2(0.f, 0.f);
#pragma unroll
        for (int off = 4; off > 0; off >>= 1) {
            a.x += __shfl_xor_sync(0xffffffffu, a.x, off);
            a.y += __shfl_xor_sync(0xffffffffu, a.y, off);
        }
        if (lane == 0) fin = a;
    }
    __syncthreads();

    float mu = fin.x * (1.f / DM);
    float var = fin.y * (1.f / DM) - mu * mu;
    float rstd = rsqrtf(var + LN_EPS);

    float4 gv = ((const float4*)gamma)[tid];
    float4 bv = ((const float4*)beta)[tid];
    float4 y;
    y.x = (v.x - mu) * rstd * gv.x + bv.x;
    y.y = (v.y - mu) * rstd * gv.y + bv.y;
    y.z = (v.z - mu) * rstd * gv.z + bv.z;
    y.w = (v.w - mu) * rstd * gv.w + bv.w;
    ((float4*)(out + (size_t)row * DM))[tid] = y;
    if (outh) {
        __half2* oh = (__half2*)(outh + (size_t)row * DM);
        oh[2 * tid + 0] = __floats2half2_rn(y.x, y.y);
        oh[2 * tid + 1] = __floats2half2_rn(y.z, y.w);
    }
}

// ---------------- launch ----------------------------------------------------------
extern "C" void kernel_launch(void* const* d_in, const int* in_sizes, int n_in,
                              void* d_out, int out_size)
{
    const float* x    = (const float*)d_in[0];
    const int*   mask = (const int*)  d_in[1];
    const float* w_q  = (const float*)d_in[2];
    const float* b_q  = (const float*)d_in[3];
    const float* w_k  = (const float*)d_in[4];
    const float* b_k  = (const float*)d_in[5];
    const float* w_v  = (const float*)d_in[6];
    const float* b_v  = (const float*)d_in[7];
    const float* w_o  = (const float*)d_in[8];
    const float* b_o  = (const float*)d_in[9];
    const float* w1   = (const float*)d_in[10];
    const float* b1   = (const float*)d_in[11];
    const float* w2   = (const float*)d_in[12];
    const float* b2   = (const float*)d_in[13];
    const float* g1   = (const float*)d_in[14];
    const float* be1  = (const float*)d_in[15];
    const float* g2   = (const float*)d_in[16];
    const float* be2  = (const float*)d_in[17];
    float* out = (float*)d_out;

    float *pattn, *ph, *pff2, *pbqkv;
    __half *pqkvh, *pxh, *pctxh, *phh, *pff1h, *pwqkvh, *pwtoh, *pwt1h, *pwt2h;
    cudaGetSymbolAddress((void**)&pattn,  g_attn);
    cudaGetSymbolAddress((void**)&ph,     g_h);
    cudaGetSymbolAddress((void**)&pff2,   g_ff2);
    cudaGetSymbolAddress((void**)&pbqkv,  g_bqkv);
    cudaGetSymbolAddress((void**)&pqkvh,  g_qkvh);
    cudaGetSymbolAddress((void**)&pxh,    g_xh);
    cudaGetSymbolAddress((void**)&pctxh,  g_ctxh);
    cudaGetSymbolAddress((void**)&phh,    g_hh);
    cudaGetSymbolAddress((void**)&pff1h,  g_ff1h);
    cudaGetSymbolAddress((void**)&pwqkvh, g_wqkvh);
    cudaGetSymbolAddress((void**)&pwtoh,  g_wtoh);
    cudaGetSymbolAddress((void**)&pwt1h,  g_wt1h);
    cudaGetSymbolAddress((void**)&pwt2h,  g_wt2h);

    cudaFuncSetAttribute(gemm_f16, cudaFuncAttributeMaxDynamicSharedMemorySize, GEMM_SMEM);
    cudaFuncSetAttribute(attn_mma, cudaFuncAttributeMaxDynamicSharedMemorySize, ATTN_SMEM);

    dim3 gQKV(3 * DM / 128, MROWS / 128);  // (24, 64)
    dim3 gD(DM / 128, MROWS / 128);        // (8, 64)
    dim3 gF1(DFF / 128, MROWS / 128);      // (32, 64)

    // ALL prep in one launch: 6 transposes + bias concat + x->half
    prep_all<<<PREP_BLOCKS, 256>>>(x, w_q, w_k, w_v, w_o, w1, w2, b_q, b_k, b_v,
                                   pwqkvh, pwtoh, pwt1h, pwt2h, pxh, pbqkv);

    // fused QKV projection (fp16 mma; half output feeds fp16 attention)
    gemm_f16<<<gQKV, 128, GEMM_SMEM>>>(pxh, pwqkvh, pbqkv, pqkvh, MROWS, 3 * DM, DM, 0, 2);

    // flash attention (fp16 mma), half output for O-projection
    attn_mma<<<dim3(SEQ / AQT, BATCH * NH), 256, ATTN_SMEM>>>(
        pqkvh, pqkvh + DM, pqkvh + 2 * DM, mask, pctxh, 3 * DM);

    // output projection (fp16)
    gemm_f16<<<gD, 128, GEMM_SMEM>>>(pctxh, pwtoh, b_o, pattn, MROWS, DM, DM, 0, 0);

    // LN1: h = LN(x + attn_out); hh = half copy
    ln_residual<<<MROWS, 256>>>(x, pattn, g1, be1, ph, phh);

    // FFN (fp16; ff1 stored half directly)
    gemm_f16<<<gF1, 128, GEMM_SMEM>>>(phh, pwt1h, b1, pff1h, MROWS, DFF, DM, 1, 2);
    gemm_f16<<<gD, 128, GEMM_SMEM>>>(pff1h, pwt2h, b2, pff2, MROWS, DM, DFF, 0, 0);

    // LN2: out = LN(h + ff)
    ln_residual<<<MROWS, 256>>>(ph, pff2, g2, be2, out, nullptr);
}